// round 2
// baseline (speedup 1.0000x reference)
#include <cuda_runtime.h>
#include <math.h>
#include <stdint.h>
#include <stddef.h>

// Problem constants
#define BB 16
#define SS 512
#define DD 768
#define HH 12
#define LL 4
#define FF 3072
#define HDD 64
#define NK 9
#define TT (BB*SS)          // 8192 tokens
#define D3 (3*DD)           // 2304

// ---------------- scratch (static device globals; no runtime allocation) ----------------
__device__ float g_x[(size_t)TT*DD];                 // 25 MB  activations
__device__ float g_qkv[(size_t)TT*D3];               // 75 MB
__device__ float g_att[(size_t)BB*HH*SS*SS];         // 201 MB attention probs
__device__ float g_ctx[(size_t)TT*DD];               // 25 MB
__device__ float g_ffn[(size_t)TT*FF];               // 100 MB
__device__ float g_tmp[(size_t)TT*DD];               // 25 MB
__device__ float g_logits[(size_t)TT*NK];
__device__ float g_logZ[BB];
__device__ float g_score[BB];

// ---------------- helpers ----------------
__device__ __forceinline__ float blk_reduce256(float v, float* sh) {
    int tid = threadIdx.x;
    sh[tid] = v; __syncthreads();
    #pragma unroll
    for (int s = 128; s > 0; s >>= 1) {
        if (tid < s) sh[tid] += sh[tid + s];
        __syncthreads();
    }
    float r = sh[0]; __syncthreads();
    return r;
}

// ---------------- embedding + LN ----------------
__global__ void embed_ln_kernel(const int* __restrict__ ids, const float* __restrict__ emb,
                                const float* __restrict__ pos, const float* __restrict__ g,
                                const float* __restrict__ bta, float* __restrict__ out) {
    __shared__ float sh[256];
    int t = blockIdx.x, s = t % SS;
    int id = ids[t];
    const float* e = emb + (size_t)id * DD;
    const float* p = pos + (size_t)s * DD;
    float v[3]; float ls = 0.f, lq = 0.f;
    #pragma unroll
    for (int i = 0; i < 3; i++) {
        int d = threadIdx.x + i * 256;
        float w = e[d] + p[d];
        v[i] = w; ls += w; lq += w * w;
    }
    float sum = blk_reduce256(ls, sh);
    float sq  = blk_reduce256(lq, sh);
    float mean = sum * (1.0f / DD);
    float var  = sq * (1.0f / DD) - mean * mean;
    float rstd = rsqrtf(var + 1e-12f);
    float* o = out + (size_t)t * DD;
    #pragma unroll
    for (int i = 0; i < 3; i++) {
        int d = threadIdx.x + i * 256;
        o[d] = (v[i] - mean) * rstd * g[d] + bta[d];
    }
}

// out = LN(a + r) * g + b   (per token; in-place on a is safe: block owns the row)
__global__ void ln_residual_kernel(const float* __restrict__ a, const float* __restrict__ r,
                                   const float* __restrict__ g, const float* __restrict__ bta,
                                   float* __restrict__ out) {
    __shared__ float sh[256];
    int t = blockIdx.x;
    const float* ap = a + (size_t)t * DD;
    const float* rp = r + (size_t)t * DD;
    float v[3]; float ls = 0.f, lq = 0.f;
    #pragma unroll
    for (int i = 0; i < 3; i++) {
        int d = threadIdx.x + i * 256;
        float w = ap[d] + rp[d];
        v[i] = w; ls += w; lq += w * w;
    }
    float sum = blk_reduce256(ls, sh);
    float sq  = blk_reduce256(lq, sh);
    float mean = sum * (1.0f / DD);
    float var  = sq * (1.0f / DD) - mean * mean;
    float rstd = rsqrtf(var + 1e-12f);
    float* o = out + (size_t)t * DD;
    #pragma unroll
    for (int i = 0; i < 3; i++) {
        int d = threadIdx.x + i * 256;
        o[d] = (v[i] - mean) * rstd * g[d] + bta[d];
    }
}

// ---------------- SGEMM: C[M,N] = A[M,K] @ B[K,N] + bias[N], optional tanh-GELU ----------------
// Requires M%128==0, N%128==0, K%8==0. 256 threads, 128x128 tile, 8x8 per thread.
__global__ __launch_bounds__(256)
void sgemm_kernel(const float* __restrict__ A, const float* __restrict__ Bm,
                  const float* __restrict__ bias, float* __restrict__ C,
                  int M, int N, int Kd, int act) {
    __shared__ float As[8][128];
    __shared__ float Bs[8][128];
    const int tid = threadIdx.x;
    const int tx = tid & 15, ty = tid >> 4;
    const int rowBase = blockIdx.y * 128;
    const int colBase = blockIdx.x * 128;

    float acc[2][2][4][4];
    #pragma unroll
    for (int m = 0; m < 2; m++)
        #pragma unroll
        for (int n = 0; n < 2; n++)
            #pragma unroll
            for (int i = 0; i < 4; i++)
                #pragma unroll
                for (int j = 0; j < 4; j++) acc[m][n][i][j] = 0.f;

    const int aRow = tid >> 1;            // 0..127
    const int aCol = (tid & 1) * 4;       // 0 or 4
    const int bRow = tid >> 5;            // 0..7
    const int bCol = (tid & 31) * 4;      // 0..124

    const float* Ap = A + (size_t)(rowBase + aRow) * Kd + aCol;
    const float* Bp = Bm + (size_t)bRow * N + colBase + bCol;

    for (int k0 = 0; k0 < Kd; k0 += 8) {
        float4 a4 = *(const float4*)(Ap + k0);
        As[aCol + 0][aRow] = a4.x;
        As[aCol + 1][aRow] = a4.y;
        As[aCol + 2][aRow] = a4.z;
        As[aCol + 3][aRow] = a4.w;
        *(float4*)&Bs[bRow][bCol] = *(const float4*)(Bp + (size_t)k0 * N);
        __syncthreads();
        #pragma unroll
        for (int kk = 0; kk < 8; kk++) {
            float4 a0 = *(float4*)&As[kk][ty * 4];
            float4 a1 = *(float4*)&As[kk][ty * 4 + 64];
            float4 b0 = *(float4*)&Bs[kk][tx * 4];
            float4 b1 = *(float4*)&Bs[kk][tx * 4 + 64];
            float ar[2][4] = {{a0.x, a0.y, a0.z, a0.w}, {a1.x, a1.y, a1.z, a1.w}};
            float br[2][4] = {{b0.x, b0.y, b0.z, b0.w}, {b1.x, b1.y, b1.z, b1.w}};
            #pragma unroll
            for (int m = 0; m < 2; m++)
                #pragma unroll
                for (int i = 0; i < 4; i++)
                    #pragma unroll
                    for (int n = 0; n < 2; n++)
                        #pragma unroll
                        for (int j = 0; j < 4; j++)
                            acc[m][n][i][j] += ar[m][i] * br[n][j];
        }
        __syncthreads();
    }

    #pragma unroll
    for (int m = 0; m < 2; m++) {
        #pragma unroll
        for (int i = 0; i < 4; i++) {
            int row = rowBase + m * 64 + ty * 4 + i;
            #pragma unroll
            for (int n = 0; n < 2; n++) {
                #pragma unroll
                for (int j = 0; j < 4; j++) {
                    int col = colBase + n * 64 + tx * 4 + j;
                    float v = acc[m][n][i][j] + bias[col];
                    if (act) {
                        float u = v;
                        float c = 0.7978845608028654f * (u + 0.044715f * u * u * u);
                        v = 0.5f * u * (1.0f + tanhf(c));
                    }
                    C[(size_t)row * N + col] = v;
                }
            }
        }
    }
}

// ---------------- attention scores: att = Q@K^T * 0.125 + mask_bias ----------------
// grid: (S/64, B*H), 256 threads. Each block: 64 q-rows x all 512 k-cols.
__global__ __launch_bounds__(256)
void attn_scores_kernel(const float* __restrict__ qkv, const int* __restrict__ amask,
                        float* __restrict__ att) {
    int bh = blockIdx.y;
    int b = bh / HH, h = bh % HH;
    int q0 = blockIdx.x * 64;
    __shared__ float Qs[64][65];
    __shared__ float Ks[64][65];
    int tid = threadIdx.x;
    int tx = tid & 15, ty = tid >> 4;

    const float* Qbase = qkv + (size_t)(b * SS + q0) * D3 + h * HDD;
    const float* Kbase = qkv + (size_t)(b * SS) * D3 + DD + h * HDD;
    float* out = att + ((size_t)bh * SS + q0) * SS;

    {   // load Q tile 64x64
        int r = tid >> 4, c = (tid & 15) * 4;
        #pragma unroll
        for (int rr = 0; rr < 4; rr++) {
            int row = r + rr * 16;
            float4 v = *(const float4*)(Qbase + (size_t)row * D3 + c);
            Qs[row][c] = v.x; Qs[row][c+1] = v.y; Qs[row][c+2] = v.z; Qs[row][c+3] = v.w;
        }
    }

    for (int kt = 0; kt < 8; kt++) {
        __syncthreads();
        {   // load K tile 64x64 (rows kt*64..)
            int r = tid >> 4, c = (tid & 15) * 4;
            #pragma unroll
            for (int rr = 0; rr < 4; rr++) {
                int row = r + rr * 16;
                float4 v = *(const float4*)(Kbase + (size_t)(kt * 64 + row) * D3 + c);
                Ks[row][c] = v.x; Ks[row][c+1] = v.y; Ks[row][c+2] = v.z; Ks[row][c+3] = v.w;
            }
        }
        __syncthreads();
        float acc[4][4];
        #pragma unroll
        for (int i = 0; i < 4; i++)
            #pragma unroll
            for (int j = 0; j < 4; j++) acc[i][j] = 0.f;
        #pragma unroll 8
        for (int kk = 0; kk < 64; kk++) {
            float ar[4], br[4];
            #pragma unroll
            for (int i = 0; i < 4; i++) ar[i] = Qs[ty + 16 * i][kk];
            #pragma unroll
            for (int j = 0; j < 4; j++) br[j] = Ks[tx + 16 * j][kk];
            #pragma unroll
            for (int i = 0; i < 4; i++)
                #pragma unroll
                for (int j = 0; j < 4; j++) acc[i][j] += ar[i] * br[j];
        }
        #pragma unroll
        for (int j = 0; j < 4; j++) {
            int kcol = kt * 64 + tx + 16 * j;
            float biasv = (1.0f - (float)amask[b * SS + kcol]) * -1e9f;
            #pragma unroll
            for (int i = 0; i < 4; i++) {
                int qrow = ty + 16 * i;
                out[(size_t)qrow * SS + kcol] = acc[i][j] * 0.125f + biasv;
            }
        }
    }
}

// ---------------- softmax over last dim (512) in-place; one block per row ----------------
__global__ __launch_bounds__(128)
void softmax_kernel(float* __restrict__ att) {
    __shared__ float sh[128];
    size_t row = blockIdx.x;
    float* p = att + row * SS;
    int tid = threadIdx.x;
    float4 v = ((float4*)p)[tid];
    float mx = fmaxf(fmaxf(v.x, v.y), fmaxf(v.z, v.w));
    sh[tid] = mx; __syncthreads();
    #pragma unroll
    for (int s = 64; s > 0; s >>= 1) { if (tid < s) sh[tid] = fmaxf(sh[tid], sh[tid + s]); __syncthreads(); }
    mx = sh[0]; __syncthreads();
    v.x = expf(v.x - mx); v.y = expf(v.y - mx); v.z = expf(v.z - mx); v.w = expf(v.w - mx);
    float lsum = v.x + v.y + v.z + v.w;
    sh[tid] = lsum; __syncthreads();
    #pragma unroll
    for (int s = 64; s > 0; s >>= 1) { if (tid < s) sh[tid] += sh[tid + s]; __syncthreads(); }
    float inv = 1.0f / sh[0];
    v.x *= inv; v.y *= inv; v.z *= inv; v.w *= inv;
    ((float4*)p)[tid] = v;
}

// ---------------- ctx = att @ V, scattered into (T, D) at head offset ----------------
__global__ __launch_bounds__(256)
void attn_ctx_kernel(const float* __restrict__ att, const float* __restrict__ qkv,
                     float* __restrict__ ctx) {
    int bh = blockIdx.y;
    int b = bh / HH, h = bh % HH;
    int q0 = blockIdx.x * 64;
    __shared__ float As[64][65];
    __shared__ float Vs[64][65];
    int tid = threadIdx.x;
    int tx = tid & 15, ty = tid >> 4;

    const float* arow = att + ((size_t)bh * SS + q0) * SS;
    const float* Vbase = qkv + (size_t)(b * SS) * D3 + 2 * DD + h * HDD;

    float acc[4][4];
    #pragma unroll
    for (int i = 0; i < 4; i++)
        #pragma unroll
        for (int j = 0; j < 4; j++) acc[i][j] = 0.f;

    for (int kt = 0; kt < 8; kt++) {
        __syncthreads();
        int r = tid >> 4, c = (tid & 15) * 4;
        #pragma unroll
        for (int rr = 0; rr < 4; rr++) {
            int row = r + rr * 16;
            float4 v = *(const float4*)(arow + (size_t)row * SS + kt * 64 + c);
            As[row][c] = v.x; As[row][c+1] = v.y; As[row][c+2] = v.z; As[row][c+3] = v.w;
            float4 w = *(const float4*)(Vbase + (size_t)(kt * 64 + row) * D3 + c);
            Vs[row][c] = w.x; Vs[row][c+1] = w.y; Vs[row][c+2] = w.z; Vs[row][c+3] = w.w;
        }
        __syncthreads();
        #pragma unroll 8
        for (int kk = 0; kk < 64; kk++) {
            float ar[4], br[4];
            #pragma unroll
            for (int i = 0; i < 4; i++) ar[i] = As[ty + 16 * i][kk];
            #pragma unroll
            for (int j = 0; j < 4; j++) br[j] = Vs[kk][tx + 16 * j];
            #pragma unroll
            for (int i = 0; i < 4; i++)
                #pragma unroll
                for (int j = 0; j < 4; j++) acc[i][j] += ar[i] * br[j];
        }
    }
    #pragma unroll
    for (int i = 0; i < 4; i++) {
        int qrow = q0 + ty + 16 * i;
        #pragma unroll
        for (int j = 0; j < 4; j++) {
            int dcol = tx + 16 * j;
            ctx[(size_t)(b * SS + qrow) * DD + h * HDD + dcol] = acc[i][j];
        }
    }
}

// ---------------- classifier: logits[t, j] = x[t] . Wcls[:, j] + bcls[j] ----------------
// 288 threads = 9 warps per token-block; warp j handles class j.
__global__ __launch_bounds__(288)
void cls_kernel(const float* __restrict__ x, const float* __restrict__ W,
                const float* __restrict__ bias, float* __restrict__ logits) {
    int t = blockIdx.x;
    int w = threadIdx.x >> 5;
    int lane = threadIdx.x & 31;
    const float* xp = x + (size_t)t * DD;
    float s = 0.f;
    for (int d = lane; d < DD; d += 32) s += xp[d] * W[(size_t)d * NK + w];
    #pragma unroll
    for (int o = 16; o > 0; o >>= 1) s += __shfl_down_sync(0xffffffffu, s, o);
    if (lane == 0) logits[(size_t)t * NK + w] = s + bias[w];
}

// ---------------- CRF gold-path score; one block per batch ----------------
__global__ __launch_bounds__(512)
void crf_score_kernel(const int* __restrict__ labels, const int* __restrict__ amask,
                      const float* __restrict__ logits, const float* __restrict__ start_t,
                      const float* __restrict__ end_t, const float* __restrict__ trans,
                      float* __restrict__ score) {
    __shared__ float sf[512];
    __shared__ int si[512];
    int b = blockIdx.x;
    int t = threadIdx.x;
    const int* lab = labels + b * SS;
    const int* m = amask + b * SS;
    const float* lg = logits + (size_t)b * SS * NK;
    float em = lg[t * NK + lab[t]];
    float contrib = (t == 0) ? em : (float)m[t] * (trans[lab[t - 1] * NK + lab[t]] + em);
    sf[t] = contrib; si[t] = m[t];
    __syncthreads();
    #pragma unroll
    for (int s = 256; s > 0; s >>= 1) {
        if (t < s) { sf[t] += sf[t + s]; si[t] += si[t + s]; }
        __syncthreads();
    }
    if (t == 0) {
        int last = si[0] - 1;
        score[b] = sf[0] + start_t[lab[0]] + end_t[lab[last]];
    }
}

// ---------------- CRF forward (logZ); one block (1 warp) per batch ----------------
__global__ __launch_bounds__(32)
void crf_forward_kernel(const float* __restrict__ logits, const int* __restrict__ amask,
                        const float* __restrict__ start_t, const float* __restrict__ end_t,
                        const float* __restrict__ trans, float* __restrict__ logZ) {
    __shared__ float lg[SS * NK];
    __shared__ float tr[NK * NK];
    __shared__ float alpha[2][NK];
    int b = blockIdx.x;
    int tid = threadIdx.x;
    const float* src = logits + (size_t)b * SS * NK;
    for (int i = tid; i < SS * NK; i += 32) lg[i] = src[i];
    for (int i = tid; i < NK * NK; i += 32) tr[i] = trans[i];
    if (tid < NK) alpha[0][tid] = start_t[tid] + lg[tid];
    __syncwarp();
    int cur = 0;
    for (int t = 1; t < SS; t++) {
        if (tid < NK) {
            int j = tid;
            float mx = -INFINITY;
            #pragma unroll
            for (int i = 0; i < NK; i++) mx = fmaxf(mx, alpha[cur][i] + tr[i * NK + j]);
            float s = 0.f;
            #pragma unroll
            for (int i = 0; i < NK; i++) s += expf(alpha[cur][i] + tr[i * NK + j] - mx);
            float cand = mx + logf(s) + lg[t * NK + j];
            alpha[cur ^ 1][j] = (amask[b * SS + t] > 0) ? cand : alpha[cur][j];
        }
        __syncwarp();
        cur ^= 1;
    }
    if (tid == 0) {
        float mx = -INFINITY;
        #pragma unroll
        for (int i = 0; i < NK; i++) mx = fmaxf(mx, alpha[cur][i] + end_t[i]);
        float s = 0.f;
        #pragma unroll
        for (int i = 0; i < NK; i++) s += expf(alpha[cur][i] + end_t[i] - mx);
        logZ[b] = mx + logf(s);
    }
}

// ---------------- final reduction: out = sum_b (logZ[b] - score[b]) ----------------
__global__ __launch_bounds__(32)
void final_kernel(const float* __restrict__ logZ, const float* __restrict__ score,
                  float* __restrict__ out) {
    int tid = threadIdx.x;
    float v = (tid < BB) ? (logZ[tid] - score[tid]) : 0.f;
    #pragma unroll
    for (int o = 16; o > 0; o >>= 1) v += __shfl_down_sync(0xffffffffu, v, o);
    if (tid == 0) out[0] = v;
}

// ---------------- launch ----------------
extern "C" void kernel_launch(void* const* d_in, const int* in_sizes, int n_in,
                              void* d_out, int out_size) {
    const int*   ids     = (const int*)d_in[0];
    const int*   am      = (const int*)d_in[1];
    const int*   labels  = (const int*)d_in[2];
    const float* emb     = (const float*)d_in[3];
    const float* pos     = (const float*)d_in[4];
    const float* lng     = (const float*)d_in[5];
    const float* lnb     = (const float*)d_in[6];
    const float* Wqkv    = (const float*)d_in[7];
    const float* bqkv    = (const float*)d_in[8];
    const float* Wo      = (const float*)d_in[9];
    const float* bo      = (const float*)d_in[10];
    const float* ln1g    = (const float*)d_in[11];
    const float* ln1b    = (const float*)d_in[12];
    const float* W1      = (const float*)d_in[13];
    const float* b1      = (const float*)d_in[14];
    const float* W2      = (const float*)d_in[15];
    const float* b2      = (const float*)d_in[16];
    const float* ln2g    = (const float*)d_in[17];
    const float* ln2b    = (const float*)d_in[18];
    const float* Wcls    = (const float*)d_in[19];
    const float* bcls    = (const float*)d_in[20];
    const float* start_t = (const float*)d_in[21];
    const float* end_t   = (const float*)d_in[22];
    const float* trans   = (const float*)d_in[23];

    float *xp, *qkvp, *attp, *ctxp, *ffnp, *tmpp, *logitsp, *logZp, *scorep;
    cudaGetSymbolAddress((void**)&xp, g_x);
    cudaGetSymbolAddress((void**)&qkvp, g_qkv);
    cudaGetSymbolAddress((void**)&attp, g_att);
    cudaGetSymbolAddress((void**)&ctxp, g_ctx);
    cudaGetSymbolAddress((void**)&ffnp, g_ffn);
    cudaGetSymbolAddress((void**)&tmpp, g_tmp);
    cudaGetSymbolAddress((void**)&logitsp, g_logits);
    cudaGetSymbolAddress((void**)&logZp, g_logZ);
    cudaGetSymbolAddress((void**)&scorep, g_score);

    embed_ln_kernel<<<TT, 256>>>(ids, emb, pos, lng, lnb, xp);

    for (int l = 0; l < LL; l++) {
        sgemm_kernel<<<dim3(D3 / 128, TT / 128), 256>>>(
            xp, Wqkv + (size_t)l * DD * D3, bqkv + (size_t)l * D3, qkvp, TT, D3, DD, 0);
        attn_scores_kernel<<<dim3(SS / 64, BB * HH), 256>>>(qkvp, am, attp);
        softmax_kernel<<<BB * HH * SS, 128>>>(attp);
        attn_ctx_kernel<<<dim3(SS / 64, BB * HH), 256>>>(attp, qkvp, ctxp);
        sgemm_kernel<<<dim3(DD / 128, TT / 128), 256>>>(
            ctxp, Wo + (size_t)l * DD * DD, bo + (size_t)l * DD, tmpp, TT, DD, DD, 0);
        ln_residual_kernel<<<TT, 256>>>(xp, tmpp, ln1g + (size_t)l * DD, ln1b + (size_t)l * DD, xp);
        sgemm_kernel<<<dim3(FF / 128, TT / 128), 256>>>(
            xp, W1 + (size_t)l * DD * FF, b1 + (size_t)l * FF, ffnp, TT, FF, DD, 1);
        sgemm_kernel<<<dim3(DD / 128, TT / 128), 256>>>(
            ffnp, W2 + (size_t)l * FF * DD, b2 + (size_t)l * DD, tmpp, TT, DD, FF, 0);
        ln_residual_kernel<<<TT, 256>>>(xp, tmpp, ln2g + (size_t)l * DD, ln2b + (size_t)l * DD, xp);
    }

    cls_kernel<<<TT, 288>>>(xp, Wcls, bcls, logitsp);
    crf_score_kernel<<<BB, 512>>>(labels, am, logitsp, start_t, end_t, trans, scorep);
    crf_forward_kernel<<<BB, 32>>>(logitsp, am, start_t, end_t, trans, logZp);
    final_kernel<<<1, 32>>>(logZp, scorep, (float*)d_out);
}

// round 3
// speedup vs baseline: 2.0147x; 2.0147x over previous
#include <cuda_runtime.h>
#include <math.h>
#include <stdint.h>
#include <stddef.h>

// Problem constants
#define BB 16
#define SS 512
#define DD 768
#define HH 12
#define LL 4
#define FF 3072
#define HDD 64
#define NK 9
#define TT (BB*SS)          // 8192 tokens
#define D3 (3*DD)           // 2304

// ---------------- scratch (static device globals; no runtime allocation) ----------------
__device__ float g_x[(size_t)TT*DD];
__device__ float g_qkv[(size_t)TT*D3];
__device__ float g_att[(size_t)BB*HH*SS*SS];
__device__ float g_ctx[(size_t)TT*DD];
__device__ float g_ffn[(size_t)TT*FF];
__device__ float g_tmp[(size_t)TT*DD];
__device__ float g_logits[(size_t)TT*NK];
__device__ float g_logZ[BB];
__device__ float g_score[BB];

// ---------------- helpers ----------------
__device__ __forceinline__ float blk_reduce256(float v, float* sh) {
    int tid = threadIdx.x;
    sh[tid] = v; __syncthreads();
    #pragma unroll
    for (int s = 128; s > 0; s >>= 1) {
        if (tid < s) sh[tid] += sh[tid + s];
        __syncthreads();
    }
    float r = sh[0]; __syncthreads();
    return r;
}

__device__ __forceinline__ uint32_t f2tf32(float f) {
    uint32_t u;
    asm("cvt.rna.tf32.f32 %0, %1;" : "=r"(u) : "f"(f));
    return u;
}

// ---------------- embedding + LN ----------------
__global__ void embed_ln_kernel(const int* __restrict__ ids, const float* __restrict__ emb,
                                const float* __restrict__ pos, const float* __restrict__ g,
                                const float* __restrict__ bta, float* __restrict__ out) {
    __shared__ float sh[256];
    int t = blockIdx.x, s = t % SS;
    int id = ids[t];
    const float* e = emb + (size_t)id * DD;
    const float* p = pos + (size_t)s * DD;
    float v[3]; float ls = 0.f, lq = 0.f;
    #pragma unroll
    for (int i = 0; i < 3; i++) {
        int d = threadIdx.x + i * 256;
        float w = e[d] + p[d];
        v[i] = w; ls += w; lq += w * w;
    }
    float sum = blk_reduce256(ls, sh);
    float sq  = blk_reduce256(lq, sh);
    float mean = sum * (1.0f / DD);
    float var  = sq * (1.0f / DD) - mean * mean;
    float rstd = rsqrtf(var + 1e-12f);
    float* o = out + (size_t)t * DD;
    #pragma unroll
    for (int i = 0; i < 3; i++) {
        int d = threadIdx.x + i * 256;
        o[d] = (v[i] - mean) * rstd * g[d] + bta[d];
    }
}

__global__ void ln_residual_kernel(const float* __restrict__ a, const float* __restrict__ r,
                                   const float* __restrict__ g, const float* __restrict__ bta,
                                   float* __restrict__ out) {
    __shared__ float sh[256];
    int t = blockIdx.x;
    const float* ap = a + (size_t)t * DD;
    const float* rp = r + (size_t)t * DD;
    float v[3]; float ls = 0.f, lq = 0.f;
    #pragma unroll
    for (int i = 0; i < 3; i++) {
        int d = threadIdx.x + i * 256;
        float w = ap[d] + rp[d];
        v[i] = w; ls += w; lq += w * w;
    }
    float sum = blk_reduce256(ls, sh);
    float sq  = blk_reduce256(lq, sh);
    float mean = sum * (1.0f / DD);
    float var  = sq * (1.0f / DD) - mean * mean;
    float rstd = rsqrtf(var + 1e-12f);
    float* o = out + (size_t)t * DD;
    #pragma unroll
    for (int i = 0; i < 3; i++) {
        int d = threadIdx.x + i * 256;
        o[d] = (v[i] - mean) * rstd * g[d] + bta[d];
    }
}

// ---------------- TF32 tensor-core GEMM ----------------
// C[M,N] = A[M,K] @ B[K,N] + bias[N], optional tanh-GELU.
// 128x128 CTA tile, K-tile 32, 8 warps each 64x32 via m16n8k8 tf32 mma.
// Requires M%128==0, N%128==0, K%32==0.
__global__ __launch_bounds__(256, 2)
void mma_gemm_kernel(const float* __restrict__ A, const float* __restrict__ Bm,
                     const float* __restrict__ bias, float* __restrict__ C,
                     int M, int N, int Kd, int act) {
    __shared__ float As[128][36];   // [m][k], pad 4 -> conflict-free frag loads
    __shared__ float Bs[32][136];   // [k][n], pad 8 -> conflict-free frag loads

    const int tid  = threadIdx.x;
    const int warp = tid >> 5, lane = tid & 31;
    const int warpM = warp >> 2, warpN = warp & 3;   // 2 x 4 warps
    const int lr = lane >> 2;   // 0..7
    const int lc = lane & 3;    // 0..3
    const int rowBase = blockIdx.y * 128;
    const int colBase = blockIdx.x * 128;

    float acc[4][4][4];
    #pragma unroll
    for (int im = 0; im < 4; im++)
        #pragma unroll
        for (int in = 0; in < 4; in++)
            #pragma unroll
            for (int r = 0; r < 4; r++) acc[im][in][r] = 0.f;

    for (int k0 = 0; k0 < Kd; k0 += 32) {
        // A tile: 128 x 32, converted to tf32 bit patterns
        #pragma unroll
        for (int i = 0; i < 4; i++) {
            int idx = i * 256 + tid;
            int r = idx >> 3;
            int c = (idx & 7) * 4;
            float4 v = *(const float4*)(A + (size_t)(rowBase + r) * Kd + k0 + c);
            uint32_t* dst = (uint32_t*)&As[r][c];
            dst[0] = f2tf32(v.x); dst[1] = f2tf32(v.y);
            dst[2] = f2tf32(v.z); dst[3] = f2tf32(v.w);
        }
        // B tile: 32 x 128
        #pragma unroll
        for (int i = 0; i < 4; i++) {
            int idx = i * 256 + tid;
            int kk = idx >> 5;
            int c = (idx & 31) * 4;
            float4 v = *(const float4*)(Bm + (size_t)(k0 + kk) * N + colBase + c);
            uint32_t* dst = (uint32_t*)&Bs[kk][c];
            dst[0] = f2tf32(v.x); dst[1] = f2tf32(v.y);
            dst[2] = f2tf32(v.z); dst[3] = f2tf32(v.w);
        }
        __syncthreads();

        #pragma unroll
        for (int ks = 0; ks < 4; ks++) {
            const int kb = ks * 8;
            uint32_t afr[4][4];
            #pragma unroll
            for (int im = 0; im < 4; im++) {
                int m = warpM * 64 + im * 16 + lr;
                afr[im][0] = __float_as_uint(As[m    ][kb + lc    ]);
                afr[im][1] = __float_as_uint(As[m + 8][kb + lc    ]);
                afr[im][2] = __float_as_uint(As[m    ][kb + lc + 4]);
                afr[im][3] = __float_as_uint(As[m + 8][kb + lc + 4]);
            }
            uint32_t bfr[4][2];
            #pragma unroll
            for (int in = 0; in < 4; in++) {
                int n = warpN * 32 + in * 8 + lr;
                bfr[in][0] = __float_as_uint(Bs[kb + lc    ][n]);
                bfr[in][1] = __float_as_uint(Bs[kb + lc + 4][n]);
            }
            #pragma unroll
            for (int im = 0; im < 4; im++)
                #pragma unroll
                for (int in = 0; in < 4; in++) {
                    asm volatile(
                        "mma.sync.aligned.m16n8k8.row.col.f32.tf32.tf32.f32 "
                        "{%0,%1,%2,%3}, {%4,%5,%6,%7}, {%8,%9}, {%0,%1,%2,%3};"
                        : "+f"(acc[im][in][0]), "+f"(acc[im][in][1]),
                          "+f"(acc[im][in][2]), "+f"(acc[im][in][3])
                        : "r"(afr[im][0]), "r"(afr[im][1]), "r"(afr[im][2]), "r"(afr[im][3]),
                          "r"(bfr[in][0]), "r"(bfr[in][1]));
                }
        }
        __syncthreads();
    }

    // epilogue: bias (+ optional tanh-GELU)
    #pragma unroll
    for (int im = 0; im < 4; im++) {
        int row0 = rowBase + warpM * 64 + im * 16 + lr;
        #pragma unroll
        for (int in = 0; in < 4; in++) {
            int col0 = colBase + warpN * 32 + in * 8 + lc * 2;
            float b0 = bias[col0], b1 = bias[col0 + 1];
            float v0 = acc[im][in][0] + b0;
            float v1 = acc[im][in][1] + b1;
            float v2 = acc[im][in][2] + b0;
            float v3 = acc[im][in][3] + b1;
            if (act) {
                float u, cc;
                u = v0; cc = 0.7978845608028654f * (u + 0.044715f * u * u * u); v0 = 0.5f * u * (1.0f + tanhf(cc));
                u = v1; cc = 0.7978845608028654f * (u + 0.044715f * u * u * u); v1 = 0.5f * u * (1.0f + tanhf(cc));
                u = v2; cc = 0.7978845608028654f * (u + 0.044715f * u * u * u); v2 = 0.5f * u * (1.0f + tanhf(cc));
                u = v3; cc = 0.7978845608028654f * (u + 0.044715f * u * u * u); v3 = 0.5f * u * (1.0f + tanhf(cc));
            }
            C[(size_t)row0 * N + col0]           = v0;
            C[(size_t)row0 * N + col0 + 1]       = v1;
            C[(size_t)(row0 + 8) * N + col0]     = v2;
            C[(size_t)(row0 + 8) * N + col0 + 1] = v3;
        }
    }
}

// ---------------- attention scores: att = Q@K^T * 0.125 + mask_bias ----------------
__global__ __launch_bounds__(256)
void attn_scores_kernel(const float* __restrict__ qkv, const int* __restrict__ amask,
                        float* __restrict__ att) {
    int bh = blockIdx.y;
    int b = bh / HH, h = bh % HH;
    int q0 = blockIdx.x * 64;
    __shared__ float Qs[64][65];
    __shared__ float Ks[64][65];
    int tid = threadIdx.x;
    int tx = tid & 15, ty = tid >> 4;

    const float* Qbase = qkv + (size_t)(b * SS + q0) * D3 + h * HDD;
    const float* Kbase = qkv + (size_t)(b * SS) * D3 + DD + h * HDD;
    float* out = att + ((size_t)bh * SS + q0) * SS;

    {
        int r = tid >> 4, c = (tid & 15) * 4;
        #pragma unroll
        for (int rr = 0; rr < 4; rr++) {
            int row = r + rr * 16;
            float4 v = *(const float4*)(Qbase + (size_t)row * D3 + c);
            Qs[row][c] = v.x; Qs[row][c+1] = v.y; Qs[row][c+2] = v.z; Qs[row][c+3] = v.w;
        }
    }

    for (int kt = 0; kt < 8; kt++) {
        __syncthreads();
        {
            int r = tid >> 4, c = (tid & 15) * 4;
            #pragma unroll
            for (int rr = 0; rr < 4; rr++) {
                int row = r + rr * 16;
                float4 v = *(const float4*)(Kbase + (size_t)(kt * 64 + row) * D3 + c);
                Ks[row][c] = v.x; Ks[row][c+1] = v.y; Ks[row][c+2] = v.z; Ks[row][c+3] = v.w;
            }
        }
        __syncthreads();
        float acc[4][4];
        #pragma unroll
        for (int i = 0; i < 4; i++)
            #pragma unroll
            for (int j = 0; j < 4; j++) acc[i][j] = 0.f;
        #pragma unroll 8
        for (int kk = 0; kk < 64; kk++) {
            float ar[4], br[4];
            #pragma unroll
            for (int i = 0; i < 4; i++) ar[i] = Qs[ty + 16 * i][kk];
            #pragma unroll
            for (int j = 0; j < 4; j++) br[j] = Ks[tx + 16 * j][kk];
            #pragma unroll
            for (int i = 0; i < 4; i++)
                #pragma unroll
                for (int j = 0; j < 4; j++) acc[i][j] += ar[i] * br[j];
        }
        #pragma unroll
        for (int j = 0; j < 4; j++) {
            int kcol = kt * 64 + tx + 16 * j;
            float biasv = (1.0f - (float)amask[b * SS + kcol]) * -1e9f;
            #pragma unroll
            for (int i = 0; i < 4; i++) {
                int qrow = ty + 16 * i;
                out[(size_t)qrow * SS + kcol] = acc[i][j] * 0.125f + biasv;
            }
        }
    }
}

// ---------------- softmax over last dim (512) in-place ----------------
__global__ __launch_bounds__(128)
void softmax_kernel(float* __restrict__ att) {
    __shared__ float sh[128];
    size_t row = blockIdx.x;
    float* p = att + row * SS;
    int tid = threadIdx.x;
    float4 v = ((float4*)p)[tid];
    float mx = fmaxf(fmaxf(v.x, v.y), fmaxf(v.z, v.w));
    sh[tid] = mx; __syncthreads();
    #pragma unroll
    for (int s = 64; s > 0; s >>= 1) { if (tid < s) sh[tid] = fmaxf(sh[tid], sh[tid + s]); __syncthreads(); }
    mx = sh[0]; __syncthreads();
    v.x = expf(v.x - mx); v.y = expf(v.y - mx); v.z = expf(v.z - mx); v.w = expf(v.w - mx);
    float lsum = v.x + v.y + v.z + v.w;
    sh[tid] = lsum; __syncthreads();
    #pragma unroll
    for (int s = 64; s > 0; s >>= 1) { if (tid < s) sh[tid] += sh[tid + s]; __syncthreads(); }
    float inv = 1.0f / sh[0];
    v.x *= inv; v.y *= inv; v.z *= inv; v.w *= inv;
    ((float4*)p)[tid] = v;
}

// ---------------- ctx = att @ V ----------------
__global__ __launch_bounds__(256)
void attn_ctx_kernel(const float* __restrict__ att, const float* __restrict__ qkv,
                     float* __restrict__ ctx) {
    int bh = blockIdx.y;
    int b = bh / HH, h = bh % HH;
    int q0 = blockIdx.x * 64;
    __shared__ float As[64][65];
    __shared__ float Vs[64][65];
    int tid = threadIdx.x;
    int tx = tid & 15, ty = tid >> 4;

    const float* arow = att + ((size_t)bh * SS + q0) * SS;
    const float* Vbase = qkv + (size_t)(b * SS) * D3 + 2 * DD + h * HDD;

    float acc[4][4];
    #pragma unroll
    for (int i = 0; i < 4; i++)
        #pragma unroll
        for (int j = 0; j < 4; j++) acc[i][j] = 0.f;

    for (int kt = 0; kt < 8; kt++) {
        __syncthreads();
        int r = tid >> 4, c = (tid & 15) * 4;
        #pragma unroll
        for (int rr = 0; rr < 4; rr++) {
            int row = r + rr * 16;
            float4 v = *(const float4*)(arow + (size_t)row * SS + kt * 64 + c);
            As[row][c] = v.x; As[row][c+1] = v.y; As[row][c+2] = v.z; As[row][c+3] = v.w;
            float4 w = *(const float4*)(Vbase + (size_t)(kt * 64 + row) * D3 + c);
            Vs[row][c] = w.x; Vs[row][c+1] = w.y; Vs[row][c+2] = w.z; Vs[row][c+3] = w.w;
        }
        __syncthreads();
        #pragma unroll 8
        for (int kk = 0; kk < 64; kk++) {
            float ar[4], br[4];
            #pragma unroll
            for (int i = 0; i < 4; i++) ar[i] = As[ty + 16 * i][kk];
            #pragma unroll
            for (int j = 0; j < 4; j++) br[j] = Vs[kk][tx + 16 * j];
            #pragma unroll
            for (int i = 0; i < 4; i++)
                #pragma unroll
                for (int j = 0; j < 4; j++) acc[i][j] += ar[i] * br[j];
        }
    }
    #pragma unroll
    for (int i = 0; i < 4; i++) {
        int qrow = q0 + ty + 16 * i;
        #pragma unroll
        for (int j = 0; j < 4; j++) {
            int dcol = tx + 16 * j;
            ctx[(size_t)(b * SS + qrow) * DD + h * HDD + dcol] = acc[i][j];
        }
    }
}

// ---------------- classifier ----------------
__global__ __launch_bounds__(288)
void cls_kernel(const float* __restrict__ x, const float* __restrict__ W,
                const float* __restrict__ bias, float* __restrict__ logits) {
    int t = blockIdx.x;
    int w = threadIdx.x >> 5;
    int lane = threadIdx.x & 31;
    const float* xp = x + (size_t)t * DD;
    float s = 0.f;
    for (int d = lane; d < DD; d += 32) s += xp[d] * W[(size_t)d * NK + w];
    #pragma unroll
    for (int o = 16; o > 0; o >>= 1) s += __shfl_down_sync(0xffffffffu, s, o);
    if (lane == 0) logits[(size_t)t * NK + w] = s + bias[w];
}

// ---------------- CRF gold-path score ----------------
__global__ __launch_bounds__(512)
void crf_score_kernel(const int* __restrict__ labels, const int* __restrict__ amask,
                      const float* __restrict__ logits, const float* __restrict__ start_t,
                      const float* __restrict__ end_t, const float* __restrict__ trans,
                      float* __restrict__ score) {
    __shared__ float sf[512];
    __shared__ int si[512];
    int b = blockIdx.x;
    int t = threadIdx.x;
    const int* lab = labels + b * SS;
    const int* m = amask + b * SS;
    const float* lg = logits + (size_t)b * SS * NK;
    float em = lg[t * NK + lab[t]];
    float contrib = (t == 0) ? em : (float)m[t] * (trans[lab[t - 1] * NK + lab[t]] + em);
    sf[t] = contrib; si[t] = m[t];
    __syncthreads();
    #pragma unroll
    for (int s = 256; s > 0; s >>= 1) {
        if (t < s) { sf[t] += sf[t + s]; si[t] += si[t + s]; }
        __syncthreads();
    }
    if (t == 0) {
        int last = si[0] - 1;
        score[b] = sf[0] + start_t[lab[0]] + end_t[lab[last]];
    }
}

// ---------------- CRF forward (logZ) ----------------
__global__ __launch_bounds__(32)
void crf_forward_kernel(const float* __restrict__ logits, const int* __restrict__ amask,
                        const float* __restrict__ start_t, const float* __restrict__ end_t,
                        const float* __restrict__ trans, float* __restrict__ logZ) {
    __shared__ float lg[SS * NK];
    __shared__ float tr[NK * NK];
    __shared__ float alpha[2][NK];
    int b = blockIdx.x;
    int tid = threadIdx.x;
    const float* src = logits + (size_t)b * SS * NK;
    for (int i = tid; i < SS * NK; i += 32) lg[i] = src[i];
    for (int i = tid; i < NK * NK; i += 32) tr[i] = trans[i];
    if (tid < NK) alpha[0][tid] = start_t[tid] + lg[tid];
    __syncwarp();
    int cur = 0;
    for (int t = 1; t < SS; t++) {
        if (tid < NK) {
            int j = tid;
            float mx = -INFINITY;
            #pragma unroll
            for (int i = 0; i < NK; i++) mx = fmaxf(mx, alpha[cur][i] + tr[i * NK + j]);
            float s = 0.f;
            #pragma unroll
            for (int i = 0; i < NK; i++) s += expf(alpha[cur][i] + tr[i * NK + j] - mx);
            float cand = mx + logf(s) + lg[t * NK + j];
            alpha[cur ^ 1][j] = (amask[b * SS + t] > 0) ? cand : alpha[cur][j];
        }
        __syncwarp();
        cur ^= 1;
    }
    if (tid == 0) {
        float mx = -INFINITY;
        #pragma unroll
        for (int i = 0; i < NK; i++) mx = fmaxf(mx, alpha[cur][i] + end_t[i]);
        float s = 0.f;
        #pragma unroll
        for (int i = 0; i < NK; i++) s += expf(alpha[cur][i] + end_t[i] - mx);
        logZ[b] = mx + logf(s);
    }
}

// ---------------- final reduction ----------------
__global__ __launch_bounds__(32)
void final_kernel(const float* __restrict__ logZ, const float* __restrict__ score,
                  float* __restrict__ out) {
    int tid = threadIdx.x;
    float v = (tid < BB) ? (logZ[tid] - score[tid]) : 0.f;
    #pragma unroll
    for (int o = 16; o > 0; o >>= 1) v += __shfl_down_sync(0xffffffffu, v, o);
    if (tid == 0) out[0] = v;
}

// ---------------- launch ----------------
extern "C" void kernel_launch(void* const* d_in, const int* in_sizes, int n_in,
                              void* d_out, int out_size) {
    const int*   ids     = (const int*)d_in[0];
    const int*   am      = (const int*)d_in[1];
    const int*   labels  = (const int*)d_in[2];
    const float* emb     = (const float*)d_in[3];
    const float* pos     = (const float*)d_in[4];
    const float* lng     = (const float*)d_in[5];
    const float* lnb     = (const float*)d_in[6];
    const float* Wqkv    = (const float*)d_in[7];
    const float* bqkv    = (const float*)d_in[8];
    const float* Wo      = (const float*)d_in[9];
    const float* bo      = (const float*)d_in[10];
    const float* ln1g    = (const float*)d_in[11];
    const float* ln1b    = (const float*)d_in[12];
    const float* W1      = (const float*)d_in[13];
    const float* b1      = (const float*)d_in[14];
    const float* W2      = (const float*)d_in[15];
    const float* b2      = (const float*)d_in[16];
    const float* ln2g    = (const float*)d_in[17];
    const float* ln2b    = (const float*)d_in[18];
    const float* Wcls    = (const float*)d_in[19];
    const float* bcls    = (const float*)d_in[20];
    const float* start_t = (const float*)d_in[21];
    const float* end_t   = (const float*)d_in[22];
    const float* trans   = (const float*)d_in[23];

    float *xp, *qkvp, *attp, *ctxp, *ffnp, *tmpp, *logitsp, *logZp, *scorep;
    cudaGetSymbolAddress((void**)&xp, g_x);
    cudaGetSymbolAddress((void**)&qkvp, g_qkv);
    cudaGetSymbolAddress((void**)&attp, g_att);
    cudaGetSymbolAddress((void**)&ctxp, g_ctx);
    cudaGetSymbolAddress((void**)&ffnp, g_ffn);
    cudaGetSymbolAddress((void**)&tmpp, g_tmp);
    cudaGetSymbolAddress((void**)&logitsp, g_logits);
    cudaGetSymbolAddress((void**)&logZp, g_logZ);
    cudaGetSymbolAddress((void**)&scorep, g_score);

    embed_ln_kernel<<<TT, 256>>>(ids, emb, pos, lng, lnb, xp);

    for (int l = 0; l < LL; l++) {
        mma_gemm_kernel<<<dim3(D3 / 128, TT / 128), 256>>>(
            xp, Wqkv + (size_t)l * DD * D3, bqkv + (size_t)l * D3, qkvp, TT, D3, DD, 0);
        attn_scores_kernel<<<dim3(SS / 64, BB * HH), 256>>>(qkvp, am, attp);
        softmax_kernel<<<BB * HH * SS, 128>>>(attp);
        attn_ctx_kernel<<<dim3(SS / 64, BB * HH), 256>>>(attp, qkvp, ctxp);
        mma_gemm_kernel<<<dim3(DD / 128, TT / 128), 256>>>(
            ctxp, Wo + (size_t)l * DD * DD, bo + (size_t)l * DD, tmpp, TT, DD, DD, 0);
        ln_residual_kernel<<<TT, 256>>>(xp, tmpp, ln1g + (size_t)l * DD, ln1b + (size_t)l * DD, xp);
        mma_gemm_kernel<<<dim3(FF / 128, TT / 128), 256>>>(
            xp, W1 + (size_t)l * DD * FF, b1 + (size_t)l * FF, ffnp, TT, FF, DD, 1);
        mma_gemm_kernel<<<dim3(DD / 128, TT / 128), 256>>>(
            ffnp, W2 + (size_t)l * FF * DD, b2 + (size_t)l * DD, tmpp, TT, DD, FF, 0);
        ln_residual_kernel<<<TT, 256>>>(xp, tmpp, ln2g + (size_t)l * DD, ln2b + (size_t)l * DD, xp);
    }

    cls_kernel<<<TT, 288>>>(xp, Wcls, bcls, logitsp);
    crf_score_kernel<<<BB, 512>>>(labels, am, logitsp, start_t, end_t, trans, scorep);
    crf_forward_kernel<<<BB, 32>>>(logitsp, am, start_t, end_t, trans, logZp);
    final_kernel<<<1, 32>>>(logZp, scorep, (float*)d_out);
}

// round 6
// speedup vs baseline: 2.4589x; 1.2205x over previous
#include <cuda_runtime.h>
#include <math.h>
#include <stdint.h>
#include <stddef.h>

// Problem constants
#define BB 16
#define SS 512
#define DD 768
#define HH 12
#define LL 4
#define FF 3072
#define HDD 64
#define NK 9
#define TT (BB*SS)          // 8192 tokens
#define D3 (3*DD)           // 2304

// ---------------- scratch (static device globals) ----------------
__device__ float g_x[(size_t)TT*DD];
__device__ float g_qkv[(size_t)TT*D3];
__device__ float g_att[(size_t)BB*HH*SS*SS];
__device__ float g_ctx[(size_t)TT*DD];
__device__ float g_ffn[(size_t)TT*FF];
__device__ float g_tmp[(size_t)TT*DD];
__device__ float g_logits[(size_t)TT*NK];
__device__ float g_logZ[BB];
__device__ float g_score[BB];

// ---------------- helpers ----------------
__device__ __forceinline__ float blk_reduce256(float v, float* sh) {
    int tid = threadIdx.x;
    sh[tid] = v; __syncthreads();
    #pragma unroll
    for (int s = 128; s > 0; s >>= 1) {
        if (tid < s) sh[tid] += sh[tid + s];
        __syncthreads();
    }
    float r = sh[0]; __syncthreads();
    return r;
}

__device__ __forceinline__ void cp_async16(void* smem, const void* gmem) {
    uint32_t s = (uint32_t)__cvta_generic_to_shared(smem);
    asm volatile("cp.async.cg.shared.global [%0], [%1], 16;\n" :: "r"(s), "l"(gmem));
}
#define CP_COMMIT() asm volatile("cp.async.commit_group;\n")
#define CP_WAIT(n)  asm volatile("cp.async.wait_group %0;\n" :: "n"(n))

#define MMA_TF32(acc, a0,a1,a2,a3, b0,b1) \
    asm volatile( \
        "mma.sync.aligned.m16n8k8.row.col.f32.tf32.tf32.f32 " \
        "{%0,%1,%2,%3}, {%4,%5,%6,%7}, {%8,%9}, {%0,%1,%2,%3};" \
        : "+f"(acc[0]), "+f"(acc[1]), "+f"(acc[2]), "+f"(acc[3]) \
        : "r"(a0), "r"(a1), "r"(a2), "r"(a3), "r"(b0), "r"(b1))

// ---------------- embedding + LN ----------------
__global__ void embed_ln_kernel(const int* __restrict__ ids, const float* __restrict__ emb,
                                const float* __restrict__ pos, const float* __restrict__ g,
                                const float* __restrict__ bta, float* __restrict__ out) {
    __shared__ float sh[256];
    int t = blockIdx.x, s = t % SS;
    int id = ids[t];
    const float* e = emb + (size_t)id * DD;
    const float* p = pos + (size_t)s * DD;
    float v[3]; float ls = 0.f, lq = 0.f;
    #pragma unroll
    for (int i = 0; i < 3; i++) {
        int d = threadIdx.x + i * 256;
        float w = e[d] + p[d];
        v[i] = w; ls += w; lq += w * w;
    }
    float sum = blk_reduce256(ls, sh);
    float sq  = blk_reduce256(lq, sh);
    float mean = sum * (1.0f / DD);
    float var  = sq * (1.0f / DD) - mean * mean;
    float rstd = rsqrtf(var + 1e-12f);
    float* o = out + (size_t)t * DD;
    #pragma unroll
    for (int i = 0; i < 3; i++) {
        int d = threadIdx.x + i * 256;
        o[d] = (v[i] - mean) * rstd * g[d] + bta[d];
    }
}

__global__ void ln_residual_kernel(const float* __restrict__ a, const float* __restrict__ r,
                                   const float* __restrict__ g, const float* __restrict__ bta,
                                   float* __restrict__ out) {
    __shared__ float sh[256];
    int t = blockIdx.x;
    const float* ap = a + (size_t)t * DD;
    const float* rp = r + (size_t)t * DD;
    float v[3]; float ls = 0.f, lq = 0.f;
    #pragma unroll
    for (int i = 0; i < 3; i++) {
        int d = threadIdx.x + i * 256;
        float w = ap[d] + rp[d];
        v[i] = w; ls += w; lq += w * w;
    }
    float sum = blk_reduce256(ls, sh);
    float sq  = blk_reduce256(lq, sh);
    float mean = sum * (1.0f / DD);
    float var  = sq * (1.0f / DD) - mean * mean;
    float rstd = rsqrtf(var + 1e-12f);
    float* o = out + (size_t)t * DD;
    #pragma unroll
    for (int i = 0; i < 3; i++) {
        int d = threadIdx.x + i * 256;
        o[d] = (v[i] - mean) * rstd * g[d] + bta[d];
    }
}

// ---------------- TF32 tensor-core GEMM with cp.async double buffering ----------------
// Dynamic smem layout (floats):
//   As[buf] : 128 x 36   at  buf*4608          (stride 36 = 4 mod 32)
//   Bs[buf] : 32 x 136   at  9216 + buf*4352   (stride 136 = 8 mod 32)
// total = (4608*2 + 4352*2) * 4B = 71680 bytes
#define GEMM_SMEM_BYTES ((2*128*36 + 2*32*136) * 4)
__global__ __launch_bounds__(256, 2)
void mma_gemm_kernel(const float* __restrict__ A, const float* __restrict__ Bm,
                     const float* __restrict__ bias, float* __restrict__ C,
                     int M, int N, int Kd, int act) {
    extern __shared__ float dyn[];
    float* AsBuf[2] = { dyn,        dyn + 4608 };
    float* BsBuf[2] = { dyn + 9216, dyn + 9216 + 4352 };

    const int tid  = threadIdx.x;
    const int warp = tid >> 5, lane = tid & 31;
    const int warpM = warp >> 2, warpN = warp & 3;
    const int lr = lane >> 2;
    const int lc = lane & 3;
    const int rowBase = blockIdx.y * 128;
    const int colBase = blockIdx.x * 128;

    float acc[4][4][4];
    #pragma unroll
    for (int im = 0; im < 4; im++)
        #pragma unroll
        for (int in = 0; in < 4; in++)
            #pragma unroll
            for (int r = 0; r < 4; r++) acc[im][in][r] = 0.f;

    auto load_stage = [&](int k0, int buf) {
        float* as = AsBuf[buf];
        float* bs = BsBuf[buf];
        #pragma unroll
        for (int i = 0; i < 4; i++) {
            int idx = i * 256 + tid;
            int r = idx >> 3;
            int c = (idx & 7) * 4;
            cp_async16(as + r * 36 + c, A + (size_t)(rowBase + r) * Kd + k0 + c);
        }
        #pragma unroll
        for (int i = 0; i < 4; i++) {
            int idx = i * 256 + tid;
            int kk = idx >> 5;
            int c = (idx & 31) * 4;
            cp_async16(bs + kk * 136 + c, Bm + (size_t)(k0 + kk) * N + colBase + c);
        }
        CP_COMMIT();
    };

    load_stage(0, 0);
    int buf = 0;
    for (int k0 = 0; k0 < Kd; k0 += 32) {
        bool has_next = (k0 + 32 < Kd);
        if (has_next) load_stage(k0 + 32, buf ^ 1);
        if (has_next) { CP_WAIT(1); } else { CP_WAIT(0); }
        __syncthreads();

        const float* as = AsBuf[buf];
        const float* bs = BsBuf[buf];
        #pragma unroll
        for (int ks = 0; ks < 4; ks++) {
            const int kb = ks * 8;
            uint32_t afr[4][4];
            #pragma unroll
            for (int im = 0; im < 4; im++) {
                int m = warpM * 64 + im * 16 + lr;
                afr[im][0] = __float_as_uint(as[(m    ) * 36 + kb + lc    ]);
                afr[im][1] = __float_as_uint(as[(m + 8) * 36 + kb + lc    ]);
                afr[im][2] = __float_as_uint(as[(m    ) * 36 + kb + lc + 4]);
                afr[im][3] = __float_as_uint(as[(m + 8) * 36 + kb + lc + 4]);
            }
            uint32_t bfr[4][2];
            #pragma unroll
            for (int in = 0; in < 4; in++) {
                int n = warpN * 32 + in * 8 + lr;
                bfr[in][0] = __float_as_uint(bs[(kb + lc    ) * 136 + n]);
                bfr[in][1] = __float_as_uint(bs[(kb + lc + 4) * 136 + n]);
            }
            #pragma unroll
            for (int im = 0; im < 4; im++)
                #pragma unroll
                for (int in = 0; in < 4; in++)
                    MMA_TF32(acc[im][in], afr[im][0], afr[im][1], afr[im][2], afr[im][3],
                             bfr[in][0], bfr[in][1]);
        }
        __syncthreads();
        buf ^= 1;
    }

    #pragma unroll
    for (int im = 0; im < 4; im++) {
        int row0 = rowBase + warpM * 64 + im * 16 + lr;
        #pragma unroll
        for (int in = 0; in < 4; in++) {
            int col0 = colBase + warpN * 32 + in * 8 + lc * 2;
            float b0 = bias[col0], b1 = bias[col0 + 1];
            float v0 = acc[im][in][0] + b0;
            float v1 = acc[im][in][1] + b1;
            float v2 = acc[im][in][2] + b0;
            float v3 = acc[im][in][3] + b1;
            if (act) {
                float u, cc;
                u = v0; cc = 0.7978845608028654f * (u + 0.044715f * u * u * u); v0 = 0.5f * u * (1.0f + tanhf(cc));
                u = v1; cc = 0.7978845608028654f * (u + 0.044715f * u * u * u); v1 = 0.5f * u * (1.0f + tanhf(cc));
                u = v2; cc = 0.7978845608028654f * (u + 0.044715f * u * u * u); v2 = 0.5f * u * (1.0f + tanhf(cc));
                u = v3; cc = 0.7978845608028654f * (u + 0.044715f * u * u * u); v3 = 0.5f * u * (1.0f + tanhf(cc));
            }
            C[(size_t)row0 * N + col0]           = v0;
            C[(size_t)row0 * N + col0 + 1]       = v1;
            C[(size_t)(row0 + 8) * N + col0]     = v2;
            C[(size_t)(row0 + 8) * N + col0 + 1] = v3;
        }
    }
}

// ---------------- attention scores via mma: att[q][k] = (Q@K^T)*0.125 + bias ----------------
// Computed transposed: S^T[k][q] = K @ Q^T so K needs no smem transpose.
// Dynamic smem: Qt 64x72 @0, Ks 64x68 @4608, Ss 64x68 @8960  -> 13312 floats = 53248 B
#define ATTN_SMEM_BYTES ((64*72 + 64*68 + 64*68) * 4)
__global__ __launch_bounds__(256)
void attn_scores_mma_kernel(const float* __restrict__ qkv, const int* __restrict__ amask,
                            float* __restrict__ att) {
    extern __shared__ float dyn[];
    float* Qt = dyn;            // [d][q] stride 72 (=8 mod 32)
    float* Ks = dyn + 4608;     // [seq][d] stride 68 (=4 mod 32)
    float* Ss = dyn + 8960;     // [q][k] stride 68

    int bh = blockIdx.y;
    int b = bh / HH, h = bh % HH;
    int q0 = blockIdx.x * 64;
    const int tid = threadIdx.x;
    const int warp = tid >> 5, lane = tid & 31;
    const int lr = lane >> 2, lc = lane & 3;
    const int m0 = (warp >> 1) * 16;   // kseq tile base within 64
    const int n0 = (warp & 1) * 32;    // q base within 64

    const float* Qbase = qkv + (size_t)(b * SS + q0) * D3 + h * HDD;
    const float* Kbase = qkv + (size_t)(b * SS) * D3 + DD + h * HDD;
    float* outb = att + ((size_t)bh * SS + q0) * SS;

    // load Q tile transposed into Qt[d][q]
    {
        int r = tid >> 4, c = (tid & 15) * 4;
        #pragma unroll
        for (int rr = 0; rr < 4; rr++) {
            int row = r + rr * 16;
            float4 v = *(const float4*)(Qbase + (size_t)row * D3 + c);
            Qt[(c + 0) * 72 + row] = v.x; Qt[(c + 1) * 72 + row] = v.y;
            Qt[(c + 2) * 72 + row] = v.z; Qt[(c + 3) * 72 + row] = v.w;
        }
    }

    for (int kt = 0; kt < 8; kt++) {
        __syncthreads();
        {   // load K tile [64 seq][64 d]
            int r = tid >> 4, c = (tid & 15) * 4;
            #pragma unroll
            for (int rr = 0; rr < 4; rr++) {
                int row = r + rr * 16;
                *(float4*)&Ks[row * 68 + c] = *(const float4*)(Kbase + (size_t)(kt * 64 + row) * D3 + c);
            }
        }
        __syncthreads();

        float acc[4][4];
        #pragma unroll
        for (int in = 0; in < 4; in++)
            #pragma unroll
            for (int r = 0; r < 4; r++) acc[in][r] = 0.f;

        #pragma unroll
        for (int ks = 0; ks < 8; ks++) {
            const int kb = ks * 8;
            uint32_t a0 = __float_as_uint(Ks[(m0 + lr    ) * 68 + kb + lc    ]);
            uint32_t a1 = __float_as_uint(Ks[(m0 + lr + 8) * 68 + kb + lc    ]);
            uint32_t a2 = __float_as_uint(Ks[(m0 + lr    ) * 68 + kb + lc + 4]);
            uint32_t a3 = __float_as_uint(Ks[(m0 + lr + 8) * 68 + kb + lc + 4]);
            #pragma unroll
            for (int in = 0; in < 4; in++) {
                int n = n0 + in * 8 + lr;
                uint32_t b0 = __float_as_uint(Qt[(kb + lc    ) * 72 + n]);
                uint32_t b1 = __float_as_uint(Qt[(kb + lc + 4) * 72 + n]);
                MMA_TF32(acc[in], a0, a1, a2, a3, b0, b1);
            }
        }

        // write accum (m=kseq, n=q) transposed into Ss[q][k]
        #pragma unroll
        for (int in = 0; in < 4; in++) {
            int q = n0 + in * 8 + 2 * lc;
            int k = m0 + lr;
            Ss[(q    ) * 68 + k    ] = acc[in][0];
            Ss[(q + 1) * 68 + k    ] = acc[in][1];
            Ss[(q    ) * 68 + k + 8] = acc[in][2];
            Ss[(q + 1) * 68 + k + 8] = acc[in][3];
        }
        __syncthreads();

        // coalesced masked output: 64 rows x 64 cols
        {
            int q = tid >> 2, c4 = (tid & 3) * 16;
            #pragma unroll
            for (int j = 0; j < 4; j++) {
                int col = c4 + j * 4;
                int kglob = kt * 64 + col;
                float4 v = *(float4*)&Ss[q * 68 + col];
                v.x = v.x * 0.125f + (1.0f - (float)amask[b * SS + kglob    ]) * -1e9f;
                v.y = v.y * 0.125f + (1.0f - (float)amask[b * SS + kglob + 1]) * -1e9f;
                v.z = v.z * 0.125f + (1.0f - (float)amask[b * SS + kglob + 2]) * -1e9f;
                v.w = v.w * 0.125f + (1.0f - (float)amask[b * SS + kglob + 3]) * -1e9f;
                *(float4*)(outb + (size_t)q * SS + kglob) = v;
            }
        }
    }
}

// ---------------- softmax: one warp per row, 8 rows per block ----------------
__global__ __launch_bounds__(256)
void softmax_kernel(float* __restrict__ att) {
    size_t row = (size_t)blockIdx.x * 8 + (threadIdx.x >> 5);
    int lane = threadIdx.x & 31;
    float* p = att + row * SS;
    float4 v[4];
    #pragma unroll
    for (int i = 0; i < 4; i++) v[i] = ((float4*)p)[i * 32 + lane];
    float mx = -INFINITY;
    #pragma unroll
    for (int i = 0; i < 4; i++)
        mx = fmaxf(mx, fmaxf(fmaxf(v[i].x, v[i].y), fmaxf(v[i].z, v[i].w)));
    #pragma unroll
    for (int o = 16; o > 0; o >>= 1) mx = fmaxf(mx, __shfl_xor_sync(0xffffffffu, mx, o));
    float sum = 0.f;
    #pragma unroll
    for (int i = 0; i < 4; i++) {
        v[i].x = expf(v[i].x - mx); v[i].y = expf(v[i].y - mx);
        v[i].z = expf(v[i].z - mx); v[i].w = expf(v[i].w - mx);
        sum += v[i].x + v[i].y + v[i].z + v[i].w;
    }
    #pragma unroll
    for (int o = 16; o > 0; o >>= 1) sum += __shfl_xor_sync(0xffffffffu, sum, o);
    float inv = 1.0f / sum;
    #pragma unroll
    for (int i = 0; i < 4; i++) {
        v[i].x *= inv; v[i].y *= inv; v[i].z *= inv; v[i].w *= inv;
        ((float4*)p)[i * 32 + lane] = v[i];
    }
}

// ---------------- ctx = att @ V via mma ----------------
// Dynamic smem: Ps 64x68 @0, Vs 64x72 @4352, Cs 64x68 @8960 -> 53248 B
__global__ __launch_bounds__(256)
void attn_ctx_mma_kernel(const float* __restrict__ att, const float* __restrict__ qkv,
                         float* __restrict__ ctx) {
    extern __shared__ float dyn[];
    float* Ps = dyn;            // [q][seq] stride 68  A frags
    float* Vs = dyn + 4352;     // [seq][d] stride 72  B frags
    float* Cs = dyn + 8960;     // [q][d]   stride 68  output bounce

    int bh = blockIdx.y;
    int b = bh / HH, h = bh % HH;
    int q0 = blockIdx.x * 64;
    const int tid = threadIdx.x;
    const int warp = tid >> 5, lane = tid & 31;
    const int lr = lane >> 2, lc = lane & 3;
    const int m0 = (warp >> 1) * 16;   // q tile base
    const int n0 = (warp & 1) * 32;    // d base

    const float* arow = att + ((size_t)bh * SS + q0) * SS;
    const float* Vbase = qkv + (size_t)(b * SS) * D3 + 2 * DD + h * HDD;

    float acc[4][4];
    #pragma unroll
    for (int in = 0; in < 4; in++)
        #pragma unroll
        for (int r = 0; r < 4; r++) acc[in][r] = 0.f;

    for (int kt = 0; kt < 8; kt++) {
        __syncthreads();
        {
            int r = tid >> 4, c = (tid & 15) * 4;
            #pragma unroll
            for (int rr = 0; rr < 4; rr++) {
                int row = r + rr * 16;
                *(float4*)&Ps[row * 68 + c] = *(const float4*)(arow + (size_t)row * SS + kt * 64 + c);
                *(float4*)&Vs[row * 72 + c] = *(const float4*)(Vbase + (size_t)(kt * 64 + row) * D3 + c);
            }
        }
        __syncthreads();

        #pragma unroll
        for (int ks = 0; ks < 8; ks++) {
            const int kb = ks * 8;
            uint32_t a0 = __float_as_uint(Ps[(m0 + lr    ) * 68 + kb + lc    ]);
            uint32_t a1 = __float_as_uint(Ps[(m0 + lr + 8) * 68 + kb + lc    ]);
            uint32_t a2 = __float_as_uint(Ps[(m0 + lr    ) * 68 + kb + lc + 4]);
            uint32_t a3 = __float_as_uint(Ps[(m0 + lr + 8) * 68 + kb + lc + 4]);
            #pragma unroll
            for (int in = 0; in < 4; in++) {
                int n = n0 + in * 8 + lr;
                uint32_t b0 = __float_as_uint(Vs[(kb + lc    ) * 72 + n]);
                uint32_t b1 = __float_as_uint(Vs[(kb + lc + 4) * 72 + n]);
                MMA_TF32(acc[in], a0, a1, a2, a3, b0, b1);
            }
        }
    }

    // accum (m=q, n=d) -> Cs then coalesced gmem write
    #pragma unroll
    for (int in = 0; in < 4; in++) {
        int d = n0 + in * 8 + 2 * lc;
        int q = m0 + lr;
        Cs[(q    ) * 68 + d    ] = acc[in][0];
        Cs[(q    ) * 68 + d + 1] = acc[in][1];
        Cs[(q + 8) * 68 + d    ] = acc[in][2];
        Cs[(q + 8) * 68 + d + 1] = acc[in][3];
    }
    __syncthreads();
    {
        int q = tid >> 2, c4 = (tid & 3) * 16;
        #pragma unroll
        for (int j = 0; j < 4; j++) {
            int col = c4 + j * 4;
            float4 v = *(float4*)&Cs[q * 68 + col];
            *(float4*)(ctx + (size_t)(b * SS + q0 + q) * DD + h * HDD + col) = v;
        }
    }
}

// ---------------- classifier ----------------
__global__ __launch_bounds__(288)
void cls_kernel(const float* __restrict__ x, const float* __restrict__ W,
                const float* __restrict__ bias, float* __restrict__ logits) {
    int t = blockIdx.x;
    int w = threadIdx.x >> 5;
    int lane = threadIdx.x & 31;
    const float* xp = x + (size_t)t * DD;
    float s = 0.f;
    for (int d = lane; d < DD; d += 32) s += xp[d] * W[(size_t)d * NK + w];
    #pragma unroll
    for (int o = 16; o > 0; o >>= 1) s += __shfl_down_sync(0xffffffffu, s, o);
    if (lane == 0) logits[(size_t)t * NK + w] = s + bias[w];
}

// ---------------- CRF gold-path score ----------------
__global__ __launch_bounds__(512)
void crf_score_kernel(const int* __restrict__ labels, const int* __restrict__ amask,
                      const float* __restrict__ logits, const float* __restrict__ start_t,
                      const float* __restrict__ end_t, const float* __restrict__ trans,
                      float* __restrict__ score) {
    __shared__ float sf[512];
    __shared__ int si[512];
    int b = blockIdx.x;
    int t = threadIdx.x;
    const int* lab = labels + b * SS;
    const int* m = amask + b * SS;
    const float* lg = logits + (size_t)b * SS * NK;
    float em = lg[t * NK + lab[t]];
    float contrib = (t == 0) ? em : (float)m[t] * (trans[lab[t - 1] * NK + lab[t]] + em);
    sf[t] = contrib; si[t] = m[t];
    __syncthreads();
    #pragma unroll
    for (int s = 256; s > 0; s >>= 1) {
        if (t < s) { sf[t] += sf[t + s]; si[t] += si[t + s]; }
        __syncthreads();
    }
    if (t == 0) {
        int last = si[0] - 1;
        score[b] = sf[0] + start_t[lab[0]] + end_t[lab[last]];
    }
}

// ---------------- CRF forward (logZ) ----------------
__global__ __launch_bounds__(32)
void crf_forward_kernel(const float* __restrict__ logits, const int* __restrict__ amask,
                        const float* __restrict__ start_t, const float* __restrict__ end_t,
                        const float* __restrict__ trans, float* __restrict__ logZ) {
    __shared__ float lg[SS * NK];
    __shared__ float tr[NK * NK];
    __shared__ float alpha[2][NK];
    int b = blockIdx.x;
    int tid = threadIdx.x;
    const float* src = logits + (size_t)b * SS * NK;
    for (int i = tid; i < SS * NK; i += 32) lg[i] = src[i];
    for (int i = tid; i < NK * NK; i += 32) tr[i] = trans[i];
    if (tid < NK) alpha[0][tid] = start_t[tid] + lg[tid];
    __syncwarp();
    int cur = 0;
    for (int t = 1; t < SS; t++) {
        if (tid < NK) {
            int j = tid;
            float mx = -INFINITY;
            #pragma unroll
            for (int i = 0; i < NK; i++) mx = fmaxf(mx, alpha[cur][i] + tr[i * NK + j]);
            float s = 0.f;
            #pragma unroll
            for (int i = 0; i < NK; i++) s += expf(alpha[cur][i] + tr[i * NK + j] - mx);
            float cand = mx + logf(s) + lg[t * NK + j];
            alpha[cur ^ 1][j] = (amask[b * SS + t] > 0) ? cand : alpha[cur][j];
        }
        __syncwarp();
        cur ^= 1;
    }
    if (tid == 0) {
        float mx = -INFINITY;
        #pragma unroll
        for (int i = 0; i < NK; i++) mx = fmaxf(mx, alpha[cur][i] + end_t[i]);
        float s = 0.f;
        #pragma unroll
        for (int i = 0; i < NK; i++) s += expf(alpha[cur][i] + end_t[i] - mx);
        logZ[b] = mx + logf(s);
    }
}

// ---------------- final reduction ----------------
__global__ __launch_bounds__(32)
void final_kernel(const float* __restrict__ logZ, const float* __restrict__ score,
                  float* __restrict__ out) {
    int tid = threadIdx.x;
    float v = (tid < BB) ? (logZ[tid] - score[tid]) : 0.f;
    #pragma unroll
    for (int o = 16; o > 0; o >>= 1) v += __shfl_down_sync(0xffffffffu, v, o);
    if (tid == 0) out[0] = v;
}

// ---------------- launch ----------------
extern "C" void kernel_launch(void* const* d_in, const int* in_sizes, int n_in,
                              void* d_out, int out_size) {
    const int*   ids     = (const int*)d_in[0];
    const int*   am      = (const int*)d_in[1];
    const int*   labels  = (const int*)d_in[2];
    const float* emb     = (const float*)d_in[3];
    const float* pos     = (const float*)d_in[4];
    const float* lng     = (const float*)d_in[5];
    const float* lnb     = (const float*)d_in[6];
    const float* Wqkv    = (const float*)d_in[7];
    const float* bqkv    = (const float*)d_in[8];
    const float* Wo      = (const float*)d_in[9];
    const float* bo      = (const float*)d_in[10];
    const float* ln1g    = (const float*)d_in[11];
    const float* ln1b    = (const float*)d_in[12];
    const float* W1      = (const float*)d_in[13];
    const float* b1      = (const float*)d_in[14];
    const float* W2      = (const float*)d_in[15];
    const float* b2      = (const float*)d_in[16];
    const float* ln2g    = (const float*)d_in[17];
    const float* ln2b    = (const float*)d_in[18];
    const float* Wcls    = (const float*)d_in[19];
    const float* bcls    = (const float*)d_in[20];
    const float* start_t = (const float*)d_in[21];
    const float* end_t   = (const float*)d_in[22];
    const float* trans   = (const float*)d_in[23];

    float *xp, *qkvp, *attp, *ctxp, *ffnp, *tmpp, *logitsp, *logZp, *scorep;
    cudaGetSymbolAddress((void**)&xp, g_x);
    cudaGetSymbolAddress((void**)&qkvp, g_qkv);
    cudaGetSymbolAddress((void**)&attp, g_att);
    cudaGetSymbolAddress((void**)&ctxp, g_ctx);
    cudaGetSymbolAddress((void**)&ffnp, g_ffn);
    cudaGetSymbolAddress((void**)&tmpp, g_tmp);
    cudaGetSymbolAddress((void**)&logitsp, g_logits);
    cudaGetSymbolAddress((void**)&logZp, g_logZ);
    cudaGetSymbolAddress((void**)&scorep, g_score);

    // opt in to >48KB dynamic smem (host-side attribute; idempotent)
    cudaFuncSetAttribute(mma_gemm_kernel,
                         cudaFuncAttributeMaxDynamicSharedMemorySize, GEMM_SMEM_BYTES);
    cudaFuncSetAttribute(attn_scores_mma_kernel,
                         cudaFuncAttributeMaxDynamicSharedMemorySize, ATTN_SMEM_BYTES);
    cudaFuncSetAttribute(attn_ctx_mma_kernel,
                         cudaFuncAttributeMaxDynamicSharedMemorySize, ATTN_SMEM_BYTES);

    embed_ln_kernel<<<TT, 256>>>(ids, emb, pos, lng, lnb, xp);

    for (int l = 0; l < LL; l++) {
        mma_gemm_kernel<<<dim3(D3 / 128, TT / 128), 256, GEMM_SMEM_BYTES>>>(
            xp, Wqkv + (size_t)l * DD * D3, bqkv + (size_t)l * D3, qkvp, TT, D3, DD, 0);
        attn_scores_mma_kernel<<<dim3(SS / 64, BB * HH), 256, ATTN_SMEM_BYTES>>>(qkvp, am, attp);
        softmax_kernel<<<BB * HH * SS / 8, 256>>>(attp);
        attn_ctx_mma_kernel<<<dim3(SS / 64, BB * HH), 256, ATTN_SMEM_BYTES>>>(attp, qkvp, ctxp);
        mma_gemm_kernel<<<dim3(DD / 128, TT / 128), 256, GEMM_SMEM_BYTES>>>(
            ctxp, Wo + (size_t)l * DD * DD, bo + (size_t)l * DD, tmpp, TT, DD, DD, 0);
        ln_residual_kernel<<<TT, 256>>>(xp, tmpp, ln1g + (size_t)l * DD, ln1b + (size_t)l * DD, xp);
        mma_gemm_kernel<<<dim3(FF / 128, TT / 128), 256, GEMM_SMEM_BYTES>>>(
            xp, W1 + (size_t)l * DD * FF, b1 + (size_t)l * FF, ffnp, TT, FF, DD, 1);
        mma_gemm_kernel<<<dim3(DD / 128, TT / 128), 256, GEMM_SMEM_BYTES>>>(
            ffnp, W2 + (size_t)l * FF * DD, b2 + (size_t)l * DD, tmpp, TT, DD, FF, 0);
        ln_residual_kernel<<<TT, 256>>>(xp, tmpp, ln2g + (size_t)l * DD, ln2b + (size_t)l * DD, xp);
    }

    cls_kernel<<<TT, 288>>>(xp, Wcls, bcls, logitsp);
    crf_score_kernel<<<BB, 512>>>(labels, am, logitsp, start_t, end_t, trans, scorep);
    crf_forward_kernel<<<BB, 32>>>(logitsp, am, start_t, end_t, trans, logZp);
    final_kernel<<<1, 32>>>(logZp, scorep, (float*)d_out);
}

// round 7
// speedup vs baseline: 3.1187x; 1.2683x over previous
#include <cuda_runtime.h>
#include <cuda_bf16.h>
#include <math.h>
#include <stdint.h>
#include <stddef.h>

// Problem constants
#define BB 16
#define SS 512
#define DD 768
#define HH 12
#define LL 4
#define FF 3072
#define HDD 64
#define NK 9
#define TT (BB*SS)          // 8192 tokens
#define D3 (3*DD)           // 2304

// ---------------- scratch (static device globals) ----------------
__device__ float g_x[(size_t)TT*DD];
__device__ float g_qkv[(size_t)TT*D3];
__device__ float g_att[(size_t)BB*HH*SS*SS];
__device__ float g_tmp[(size_t)TT*DD];
__device__ float g_logits[(size_t)TT*NK];
__device__ float g_logZ[BB];
__device__ float g_score[BB];

// bf16 buffers
__device__ __nv_bfloat16 g_x_bf[(size_t)TT*DD];
__device__ __nv_bfloat16 g_ctx_bf[(size_t)TT*DD];
__device__ __nv_bfloat16 g_ffn_bf[(size_t)TT*FF];
__device__ __nv_bfloat16 g_Wqkv_t[(size_t)LL*D3*DD];   // [l][N=D3][K=DD]
__device__ __nv_bfloat16 g_Wo_t[(size_t)LL*DD*DD];     // [l][N=DD][K=DD]
__device__ __nv_bfloat16 g_W1_t[(size_t)LL*FF*DD];     // [l][N=FF][K=DD]
__device__ __nv_bfloat16 g_W2_t[(size_t)LL*DD*FF];     // [l][N=DD][K=FF]

// ---------------- helpers ----------------
__device__ __forceinline__ float blk_reduce256(float v, float* sh) {
    int tid = threadIdx.x;
    sh[tid] = v; __syncthreads();
    #pragma unroll
    for (int s = 128; s > 0; s >>= 1) {
        if (tid < s) sh[tid] += sh[tid + s];
        __syncthreads();
    }
    float r = sh[0]; __syncthreads();
    return r;
}

__device__ __forceinline__ void cp_async16(void* smem, const void* gmem) {
    uint32_t s = (uint32_t)__cvta_generic_to_shared(smem);
    asm volatile("cp.async.cg.shared.global [%0], [%1], 16;\n" :: "r"(s), "l"(gmem));
}
#define CP_COMMIT() asm volatile("cp.async.commit_group;\n")
#define CP_WAIT(n)  asm volatile("cp.async.wait_group %0;\n" :: "n"(n))

#define MMA_TF32(acc, a0,a1,a2,a3, b0,b1) \
    asm volatile( \
        "mma.sync.aligned.m16n8k8.row.col.f32.tf32.tf32.f32 " \
        "{%0,%1,%2,%3}, {%4,%5,%6,%7}, {%8,%9}, {%0,%1,%2,%3};" \
        : "+f"(acc[0]), "+f"(acc[1]), "+f"(acc[2]), "+f"(acc[3]) \
        : "r"(a0), "r"(a1), "r"(a2), "r"(a3), "r"(b0), "r"(b1))

#define MMA_BF16(acc, a0,a1,a2,a3, b0,b1) \
    asm volatile( \
        "mma.sync.aligned.m16n8k16.row.col.f32.bf16.bf16.f32 " \
        "{%0,%1,%2,%3}, {%4,%5,%6,%7}, {%8,%9}, {%0,%1,%2,%3};" \
        : "+f"(acc[0]), "+f"(acc[1]), "+f"(acc[2]), "+f"(acc[3]) \
        : "r"(a0), "r"(a1), "r"(a2), "r"(a3), "r"(b0), "r"(b1))

// ---------------- weight convert + transpose: fp32 [K][N] -> bf16 [N][K] ----------------
__global__ void wconv_kernel(const float* __restrict__ W, __nv_bfloat16* __restrict__ Wt,
                             int K, int N) {
    __shared__ float tile[32][33];
    int n0 = blockIdx.x * 32, k0 = blockIdx.y * 32;
    int tx = threadIdx.x, ty = threadIdx.y;
    #pragma unroll
    for (int j = ty; j < 32; j += 8)
        tile[j][tx] = W[(size_t)(k0 + j) * N + n0 + tx];
    __syncthreads();
    #pragma unroll
    for (int j = ty; j < 32; j += 8)
        Wt[(size_t)(n0 + j) * K + k0 + tx] = __float2bfloat16(tile[tx][j]);
}

// ---------------- embedding + LN (dual write fp32 + bf16) ----------------
__global__ void embed_ln_kernel(const int* __restrict__ ids, const float* __restrict__ emb,
                                const float* __restrict__ pos, const float* __restrict__ g,
                                const float* __restrict__ bta, float* __restrict__ out,
                                __nv_bfloat16* __restrict__ outb) {
    __shared__ float sh[256];
    int t = blockIdx.x, s = t % SS;
    int id = ids[t];
    const float* e = emb + (size_t)id * DD;
    const float* p = pos + (size_t)s * DD;
    float v[3]; float ls = 0.f, lq = 0.f;
    #pragma unroll
    for (int i = 0; i < 3; i++) {
        int d = threadIdx.x + i * 256;
        float w = e[d] + p[d];
        v[i] = w; ls += w; lq += w * w;
    }
    float sum = blk_reduce256(ls, sh);
    float sq  = blk_reduce256(lq, sh);
    float mean = sum * (1.0f / DD);
    float var  = sq * (1.0f / DD) - mean * mean;
    float rstd = rsqrtf(var + 1e-12f);
    float* o = out + (size_t)t * DD;
    __nv_bfloat16* ob = outb + (size_t)t * DD;
    #pragma unroll
    for (int i = 0; i < 3; i++) {
        int d = threadIdx.x + i * 256;
        float r = (v[i] - mean) * rstd * g[d] + bta[d];
        o[d] = r;
        ob[d] = __float2bfloat16(r);
    }
}

__global__ void ln_residual_kernel(const float* __restrict__ a, const float* __restrict__ r,
                                   const float* __restrict__ g, const float* __restrict__ bta,
                                   float* __restrict__ out, __nv_bfloat16* __restrict__ outb) {
    __shared__ float sh[256];
    int t = blockIdx.x;
    const float* ap = a + (size_t)t * DD;
    const float* rp = r + (size_t)t * DD;
    float v[3]; float ls = 0.f, lq = 0.f;
    #pragma unroll
    for (int i = 0; i < 3; i++) {
        int d = threadIdx.x + i * 256;
        float w = ap[d] + rp[d];
        v[i] = w; ls += w; lq += w * w;
    }
    float sum = blk_reduce256(ls, sh);
    float sq  = blk_reduce256(lq, sh);
    float mean = sum * (1.0f / DD);
    float var  = sq * (1.0f / DD) - mean * mean;
    float rstd = rsqrtf(var + 1e-12f);
    float* o = out + (size_t)t * DD;
    __nv_bfloat16* ob = outb + (size_t)t * DD;
    #pragma unroll
    for (int i = 0; i < 3; i++) {
        int d = threadIdx.x + i * 256;
        float rr = (v[i] - mean) * rstd * g[d] + bta[d];
        o[d] = rr;
        ob[d] = __float2bfloat16(rr);
    }
}

// ---------------- BF16 tensor-core GEMM, cp.async double buffered ----------------
// C[M,N] = A[M,K] @ Bt[N,K]^T + bias[N].  A row-major bf16, Bt = B transposed [N][K] bf16.
// 128x128 CTA tile, K-tile 64, 8 warps each 64x32 via m16n8k16.
// smem rows stored with stride 36 words (72 bf16): 36 = 4 (mod 32) -> conflict-free frags.
// act: 0 = none, 1 = tanh-GELU. Cf (fp32) and/or Cb (bf16) written if non-null.
#define GEMMB_SMEM (4 * 4608 * 4)   // 2 A bufs + 2 B bufs, each 128*36 words
__global__ __launch_bounds__(256)
void mma_gemm_bf16_kernel(const __nv_bfloat16* __restrict__ A,
                          const __nv_bfloat16* __restrict__ Bt,
                          const float* __restrict__ bias,
                          float* __restrict__ Cf, __nv_bfloat16* __restrict__ Cb,
                          int M, int N, int Kd, int act) {
    extern __shared__ uint32_t dw[];
    uint32_t* AsB[2] = { dw,        dw + 4608 };
    uint32_t* BsB[2] = { dw + 9216, dw + 13824 };

    const int tid  = threadIdx.x;
    const int warp = tid >> 5, lane = tid & 31;
    const int warpM = warp >> 2, warpN = warp & 3;
    const int g = lane >> 2, tg = lane & 3;
    const int rowBase = blockIdx.y * 128;
    const int colBase = blockIdx.x * 128;

    float acc[4][4][4];
    #pragma unroll
    for (int im = 0; im < 4; im++)
        #pragma unroll
        for (int in = 0; in < 4; in++)
            #pragma unroll
            for (int r = 0; r < 4; r++) acc[im][in][r] = 0.f;

    auto load_stage = [&](int k0, int buf) {
        uint32_t* as = AsB[buf];
        uint32_t* bs = BsB[buf];
        #pragma unroll
        for (int i = 0; i < 4; i++) {
            int idx = i * 256 + tid;
            int r = idx >> 3;
            int cw = (idx & 7) * 4;          // word offset in row
            int ch = (idx & 7) * 8;          // half offset in row
            cp_async16(as + r * 36 + cw, A  + (size_t)(rowBase + r) * Kd + k0 + ch);
            cp_async16(bs + r * 36 + cw, Bt + (size_t)(colBase + r) * Kd + k0 + ch);
        }
        CP_COMMIT();
    };

    load_stage(0, 0);
    int buf = 0;
    for (int k0 = 0; k0 < Kd; k0 += 64) {
        bool has_next = (k0 + 64 < Kd);
        if (has_next) load_stage(k0 + 64, buf ^ 1);
        if (has_next) { CP_WAIT(1); } else { CP_WAIT(0); }
        __syncthreads();

        const uint32_t* as = AsB[buf];
        const uint32_t* bs = BsB[buf];
        #pragma unroll
        for (int ks = 0; ks < 4; ks++) {
            const int kw = ks * 8;           // word offset of this k16 step
            uint32_t afr[4][4];
            #pragma unroll
            for (int im = 0; im < 4; im++) {
                int m = warpM * 64 + im * 16 + g;
                afr[im][0] = as[(m    ) * 36 + kw + tg    ];
                afr[im][1] = as[(m + 8) * 36 + kw + tg    ];
                afr[im][2] = as[(m    ) * 36 + kw + tg + 4];
                afr[im][3] = as[(m + 8) * 36 + kw + tg + 4];
            }
            uint32_t bfr[4][2];
            #pragma unroll
            for (int in = 0; in < 4; in++) {
                int n = warpN * 32 + in * 8 + g;
                bfr[in][0] = bs[n * 36 + kw + tg    ];
                bfr[in][1] = bs[n * 36 + kw + tg + 4];
            }
            #pragma unroll
            for (int im = 0; im < 4; im++)
                #pragma unroll
                for (int in = 0; in < 4; in++)
                    MMA_BF16(acc[im][in], afr[im][0], afr[im][1], afr[im][2], afr[im][3],
                             bfr[in][0], bfr[in][1]);
        }
        __syncthreads();
        buf ^= 1;
    }

    #pragma unroll
    for (int im = 0; im < 4; im++) {
        int row0 = rowBase + warpM * 64 + im * 16 + g;
        #pragma unroll
        for (int in = 0; in < 4; in++) {
            int col0 = colBase + warpN * 32 + in * 8 + tg * 2;
            float b0 = bias[col0], b1 = bias[col0 + 1];
            float v0 = acc[im][in][0] + b0;
            float v1 = acc[im][in][1] + b1;
            float v2 = acc[im][in][2] + b0;
            float v3 = acc[im][in][3] + b1;
            if (act) {
                float u, cc;
                u = v0; cc = 0.7978845608028654f * (u + 0.044715f * u * u * u); v0 = 0.5f * u * (1.0f + tanhf(cc));
                u = v1; cc = 0.7978845608028654f * (u + 0.044715f * u * u * u); v1 = 0.5f * u * (1.0f + tanhf(cc));
                u = v2; cc = 0.7978845608028654f * (u + 0.044715f * u * u * u); v2 = 0.5f * u * (1.0f + tanhf(cc));
                u = v3; cc = 0.7978845608028654f * (u + 0.044715f * u * u * u); v3 = 0.5f * u * (1.0f + tanhf(cc));
            }
            if (Cf) {
                Cf[(size_t)row0 * N + col0]           = v0;
                Cf[(size_t)row0 * N + col0 + 1]       = v1;
                Cf[(size_t)(row0 + 8) * N + col0]     = v2;
                Cf[(size_t)(row0 + 8) * N + col0 + 1] = v3;
            }
            if (Cb) {
                *(__nv_bfloat162*)(Cb + (size_t)row0 * N + col0)       = __floats2bfloat162_rn(v0, v1);
                *(__nv_bfloat162*)(Cb + (size_t)(row0 + 8) * N + col0) = __floats2bfloat162_rn(v2, v3);
            }
        }
    }
}

// ---------------- attention scores via mma (tf32): att = (Q@K^T)*0.125 + bias ----------------
#define ATTN_SMEM_BYTES ((64*72 + 64*68 + 64*68) * 4)
__global__ __launch_bounds__(256)
void attn_scores_mma_kernel(const float* __restrict__ qkv, const int* __restrict__ amask,
                            float* __restrict__ att) {
    extern __shared__ float dyn[];
    float* Qt = dyn;            // [d][q] stride 72
    float* Ks = dyn + 4608;     // [seq][d] stride 68
    float* Ss = dyn + 8960;     // [q][k] stride 68

    int bh = blockIdx.y;
    int b = bh / HH, h = bh % HH;
    int q0 = blockIdx.x * 64;
    const int tid = threadIdx.x;
    const int warp = tid >> 5, lane = tid & 31;
    const int lr = lane >> 2, lc = lane & 3;
    const int m0 = (warp >> 1) * 16;
    const int n0 = (warp & 1) * 32;

    const float* Qbase = qkv + (size_t)(b * SS + q0) * D3 + h * HDD;
    const float* Kbase = qkv + (size_t)(b * SS) * D3 + DD + h * HDD;
    float* outb = att + ((size_t)bh * SS + q0) * SS;

    {
        int r = tid >> 4, c = (tid & 15) * 4;
        #pragma unroll
        for (int rr = 0; rr < 4; rr++) {
            int row = r + rr * 16;
            float4 v = *(const float4*)(Qbase + (size_t)row * D3 + c);
            Qt[(c + 0) * 72 + row] = v.x; Qt[(c + 1) * 72 + row] = v.y;
            Qt[(c + 2) * 72 + row] = v.z; Qt[(c + 3) * 72 + row] = v.w;
        }
    }

    for (int kt = 0; kt < 8; kt++) {
        __syncthreads();
        {
            int r = tid >> 4, c = (tid & 15) * 4;
            #pragma unroll
            for (int rr = 0; rr < 4; rr++) {
                int row = r + rr * 16;
                *(float4*)&Ks[row * 68 + c] = *(const float4*)(Kbase + (size_t)(kt * 64 + row) * D3 + c);
            }
        }
        __syncthreads();

        float acc[4][4];
        #pragma unroll
        for (int in = 0; in < 4; in++)
            #pragma unroll
            for (int r = 0; r < 4; r++) acc[in][r] = 0.f;

        #pragma unroll
        for (int ks = 0; ks < 8; ks++) {
            const int kb = ks * 8;
            uint32_t a0 = __float_as_uint(Ks[(m0 + lr    ) * 68 + kb + lc    ]);
            uint32_t a1 = __float_as_uint(Ks[(m0 + lr + 8) * 68 + kb + lc    ]);
            uint32_t a2 = __float_as_uint(Ks[(m0 + lr    ) * 68 + kb + lc + 4]);
            uint32_t a3 = __float_as_uint(Ks[(m0 + lr + 8) * 68 + kb + lc + 4]);
            #pragma unroll
            for (int in = 0; in < 4; in++) {
                int n = n0 + in * 8 + lr;
                uint32_t b0 = __float_as_uint(Qt[(kb + lc    ) * 72 + n]);
                uint32_t b1 = __float_as_uint(Qt[(kb + lc + 4) * 72 + n]);
                MMA_TF32(acc[in], a0, a1, a2, a3, b0, b1);
            }
        }

        #pragma unroll
        for (int in = 0; in < 4; in++) {
            int q = n0 + in * 8 + 2 * lc;
            int k = m0 + lr;
            Ss[(q    ) * 68 + k    ] = acc[in][0];
            Ss[(q + 1) * 68 + k    ] = acc[in][1];
            Ss[(q    ) * 68 + k + 8] = acc[in][2];
            Ss[(q + 1) * 68 + k + 8] = acc[in][3];
        }
        __syncthreads();

        {
            int q = tid >> 2, c4 = (tid & 3) * 16;
            #pragma unroll
            for (int j = 0; j < 4; j++) {
                int col = c4 + j * 4;
                int kglob = kt * 64 + col;
                float4 v = *(float4*)&Ss[q * 68 + col];
                v.x = v.x * 0.125f + (1.0f - (float)amask[b * SS + kglob    ]) * -1e9f;
                v.y = v.y * 0.125f + (1.0f - (float)amask[b * SS + kglob + 1]) * -1e9f;
                v.z = v.z * 0.125f + (1.0f - (float)amask[b * SS + kglob + 2]) * -1e9f;
                v.w = v.w * 0.125f + (1.0f - (float)amask[b * SS + kglob + 3]) * -1e9f;
                *(float4*)(outb + (size_t)q * SS + kglob) = v;
            }
        }
    }
}

// ---------------- softmax: one warp per row ----------------
__global__ __launch_bounds__(256)
void softmax_kernel(float* __restrict__ att) {
    size_t row = (size_t)blockIdx.x * 8 + (threadIdx.x >> 5);
    int lane = threadIdx.x & 31;
    float* p = att + row * SS;
    float4 v[4];
    #pragma unroll
    for (int i = 0; i < 4; i++) v[i] = ((float4*)p)[i * 32 + lane];
    float mx = -INFINITY;
    #pragma unroll
    for (int i = 0; i < 4; i++)
        mx = fmaxf(mx, fmaxf(fmaxf(v[i].x, v[i].y), fmaxf(v[i].z, v[i].w)));
    #pragma unroll
    for (int o = 16; o > 0; o >>= 1) mx = fmaxf(mx, __shfl_xor_sync(0xffffffffu, mx, o));
    float sum = 0.f;
    #pragma unroll
    for (int i = 0; i < 4; i++) {
        v[i].x = expf(v[i].x - mx); v[i].y = expf(v[i].y - mx);
        v[i].z = expf(v[i].z - mx); v[i].w = expf(v[i].w - mx);
        sum += v[i].x + v[i].y + v[i].z + v[i].w;
    }
    #pragma unroll
    for (int o = 16; o > 0; o >>= 1) sum += __shfl_xor_sync(0xffffffffu, sum, o);
    float inv = 1.0f / sum;
    #pragma unroll
    for (int i = 0; i < 4; i++) {
        v[i].x *= inv; v[i].y *= inv; v[i].z *= inv; v[i].w *= inv;
        ((float4*)p)[i * 32 + lane] = v[i];
    }
}

// ---------------- ctx = att @ V via mma (tf32), bf16 output ----------------
__global__ __launch_bounds__(256)
void attn_ctx_mma_kernel(const float* __restrict__ att, const float* __restrict__ qkv,
                         __nv_bfloat16* __restrict__ ctxb) {
    extern __shared__ float dyn[];
    float* Ps = dyn;            // [q][seq] stride 68
    float* Vs = dyn + 4352;     // [seq][d] stride 72
    float* Cs = dyn + 8960;     // [q][d]   stride 68

    int bh = blockIdx.y;
    int b = bh / HH, h = bh % HH;
    int q0 = blockIdx.x * 64;
    const int tid = threadIdx.x;
    const int warp = tid >> 5, lane = tid & 31;
    const int lr = lane >> 2, lc = lane & 3;
    const int m0 = (warp >> 1) * 16;
    const int n0 = (warp & 1) * 32;

    const float* arow = att + ((size_t)bh * SS + q0) * SS;
    const float* Vbase = qkv + (size_t)(b * SS) * D3 + 2 * DD + h * HDD;

    float acc[4][4];
    #pragma unroll
    for (int in = 0; in < 4; in++)
        #pragma unroll
        for (int r = 0; r < 4; r++) acc[in][r] = 0.f;

    for (int kt = 0; kt < 8; kt++) {
        __syncthreads();
        {
            int r = tid >> 4, c = (tid & 15) * 4;
            #pragma unroll
            for (int rr = 0; rr < 4; rr++) {
                int row = r + rr * 16;
                *(float4*)&Ps[row * 68 + c] = *(const float4*)(arow + (size_t)row * SS + kt * 64 + c);
                *(float4*)&Vs[row * 72 + c] = *(const float4*)(Vbase + (size_t)(kt * 64 + row) * D3 + c);
            }
        }
        __syncthreads();

        #pragma unroll
        for (int ks = 0; ks < 8; ks++) {
            const int kb = ks * 8;
            uint32_t a0 = __float_as_uint(Ps[(m0 + lr    ) * 68 + kb + lc    ]);
            uint32_t a1 = __float_as_uint(Ps[(m0 + lr + 8) * 68 + kb + lc    ]);
            uint32_t a2 = __float_as_uint(Ps[(m0 + lr    ) * 68 + kb + lc + 4]);
            uint32_t a3 = __float_as_uint(Ps[(m0 + lr + 8) * 68 + kb + lc + 4]);
            #pragma unroll
            for (int in = 0; in < 4; in++) {
                int n = n0 + in * 8 + lr;
                uint32_t b0 = __float_as_uint(Vs[(kb + lc    ) * 72 + n]);
                uint32_t b1 = __float_as_uint(Vs[(kb + lc + 4) * 72 + n]);
                MMA_TF32(acc[in], a0, a1, a2, a3, b0, b1);
            }
        }
    }

    #pragma unroll
    for (int in = 0; in < 4; in++) {
        int d = n0 + in * 8 + 2 * lc;
        int q = m0 + lr;
        Cs[(q    ) * 68 + d    ] = acc[in][0];
        Cs[(q    ) * 68 + d + 1] = acc[in][1];
        Cs[(q + 8) * 68 + d    ] = acc[in][2];
        Cs[(q + 8) * 68 + d + 1] = acc[in][3];
    }
    __syncthreads();
    {
        int q = tid >> 2, c4 = (tid & 3) * 16;
        __nv_bfloat16* dst = ctxb + (size_t)(b * SS + q0 + q) * DD + h * HDD;
        #pragma unroll
        for (int j = 0; j < 4; j++) {
            int col = c4 + j * 4;
            float4 v = *(float4*)&Cs[q * 68 + col];
            *(__nv_bfloat162*)(dst + col)     = __floats2bfloat162_rn(v.x, v.y);
            *(__nv_bfloat162*)(dst + col + 2) = __floats2bfloat162_rn(v.z, v.w);
        }
    }
}

// ---------------- classifier ----------------
__global__ __launch_bounds__(288)
void cls_kernel(const float* __restrict__ x, const float* __restrict__ W,
                const float* __restrict__ bias, float* __restrict__ logits) {
    int t = blockIdx.x;
    int w = threadIdx.x >> 5;
    int lane = threadIdx.x & 31;
    const float* xp = x + (size_t)t * DD;
    float s = 0.f;
    for (int d = lane; d < DD; d += 32) s += xp[d] * W[(size_t)d * NK + w];
    #pragma unroll
    for (int o = 16; o > 0; o >>= 1) s += __shfl_down_sync(0xffffffffu, s, o);
    if (lane == 0) logits[(size_t)t * NK + w] = s + bias[w];
}

// ---------------- CRF gold-path score ----------------
__global__ __launch_bounds__(512)
void crf_score_kernel(const int* __restrict__ labels, const int* __restrict__ amask,
                      const float* __restrict__ logits, const float* __restrict__ start_t,
                      const float* __restrict__ end_t, const float* __restrict__ trans,
                      float* __restrict__ score) {
    __shared__ float sf[512];
    __shared__ int si[512];
    int b = blockIdx.x;
    int t = threadIdx.x;
    const int* lab = labels + b * SS;
    const int* m = amask + b * SS;
    const float* lg = logits + (size_t)b * SS * NK;
    float em = lg[t * NK + lab[t]];
    float contrib = (t == 0) ? em : (float)m[t] * (trans[lab[t - 1] * NK + lab[t]] + em);
    sf[t] = contrib; si[t] = m[t];
    __syncthreads();
    #pragma unroll
    for (int s = 256; s > 0; s >>= 1) {
        if (t < s) { sf[t] += sf[t + s]; si[t] += si[t + s]; }
        __syncthreads();
    }
    if (t == 0) {
        int last = si[0] - 1;
        score[b] = sf[0] + start_t[lab[0]] + end_t[lab[last]];
    }
}

// ---------------- CRF forward (logZ) ----------------
__global__ __launch_bounds__(32)
void crf_forward_kernel(const float* __restrict__ logits, const int* __restrict__ amask,
                        const float* __restrict__ start_t, const float* __restrict__ end_t,
                        const float* __restrict__ trans, float* __restrict__ logZ) {
    __shared__ float lg[SS * NK];
    __shared__ float tr[NK * NK];
    __shared__ float alpha[2][NK];
    int b = blockIdx.x;
    int tid = threadIdx.x;
    const float* src = logits + (size_t)b * SS * NK;
    for (int i = tid; i < SS * NK; i += 32) lg[i] = src[i];
    for (int i = tid; i < NK * NK; i += 32) tr[i] = trans[i];
    if (tid < NK) alpha[0][tid] = start_t[tid] + lg[tid];
    __syncwarp();
    int cur = 0;
    for (int t = 1; t < SS; t++) {
        if (tid < NK) {
            int j = tid;
            float mx = -INFINITY;
            #pragma unroll
            for (int i = 0; i < NK; i++) mx = fmaxf(mx, alpha[cur][i] + tr[i * NK + j]);
            float s = 0.f;
            #pragma unroll
            for (int i = 0; i < NK; i++) s += expf(alpha[cur][i] + tr[i * NK + j] - mx);
            float cand = mx + logf(s) + lg[t * NK + j];
            alpha[cur ^ 1][j] = (amask[b * SS + t] > 0) ? cand : alpha[cur][j];
        }
        __syncwarp();
        cur ^= 1;
    }
    if (tid == 0) {
        float mx = -INFINITY;
        #pragma unroll
        for (int i = 0; i < NK; i++) mx = fmaxf(mx, alpha[cur][i] + end_t[i]);
        float s = 0.f;
        #pragma unroll
        for (int i = 0; i < NK; i++) s += expf(alpha[cur][i] + end_t[i] - mx);
        logZ[b] = mx + logf(s);
    }
}

// ---------------- final reduction ----------------
__global__ __launch_bounds__(32)
void final_kernel(const float* __restrict__ logZ, const float* __restrict__ score,
                  float* __restrict__ out) {
    int tid = threadIdx.x;
    float v = (tid < BB) ? (logZ[tid] - score[tid]) : 0.f;
    #pragma unroll
    for (int o = 16; o > 0; o >>= 1) v += __shfl_down_sync(0xffffffffu, v, o);
    if (tid == 0) out[0] = v;
}

// ---------------- launch ----------------
extern "C" void kernel_launch(void* const* d_in, const int* in_sizes, int n_in,
                              void* d_out, int out_size) {
    const int*   ids     = (const int*)d_in[0];
    const int*   am      = (const int*)d_in[1];
    const int*   labels  = (const int*)d_in[2];
    const float* emb     = (const float*)d_in[3];
    const float* pos     = (const float*)d_in[4];
    const float* lng     = (const float*)d_in[5];
    const float* lnb     = (const float*)d_in[6];
    const float* Wqkv    = (const float*)d_in[7];
    const float* bqkv    = (const float*)d_in[8];
    const float* Wo      = (const float*)d_in[9];
    const float* bo      = (const float*)d_in[10];
    const float* ln1g    = (const float*)d_in[11];
    const float* ln1b    = (const float*)d_in[12];
    const float* W1      = (const float*)d_in[13];
    const float* b1      = (const float*)d_in[14];
    const float* W2      = (const float*)d_in[15];
    const float* b2      = (const float*)d_in[16];
    const float* ln2g    = (const float*)d_in[17];
    const float* ln2b    = (const float*)d_in[18];
    const float* Wcls    = (const float*)d_in[19];
    const float* bcls    = (const float*)d_in[20];
    const float* start_t = (const float*)d_in[21];
    const float* end_t   = (const float*)d_in[22];
    const float* trans   = (const float*)d_in[23];

    float *xp, *qkvp, *attp, *tmpp, *logitsp, *logZp, *scorep;
    __nv_bfloat16 *xbf, *ctxbf, *ffnbf, *wqkvt, *wot, *w1t, *w2t;
    cudaGetSymbolAddress((void**)&xp, g_x);
    cudaGetSymbolAddress((void**)&qkvp, g_qkv);
    cudaGetSymbolAddress((void**)&attp, g_att);
    cudaGetSymbolAddress((void**)&tmpp, g_tmp);
    cudaGetSymbolAddress((void**)&logitsp, g_logits);
    cudaGetSymbolAddress((void**)&logZp, g_logZ);
    cudaGetSymbolAddress((void**)&scorep, g_score);
    cudaGetSymbolAddress((void**)&xbf, g_x_bf);
    cudaGetSymbolAddress((void**)&ctxbf, g_ctx_bf);
    cudaGetSymbolAddress((void**)&ffnbf, g_ffn_bf);
    cudaGetSymbolAddress((void**)&wqkvt, g_Wqkv_t);
    cudaGetSymbolAddress((void**)&wot, g_Wo_t);
    cudaGetSymbolAddress((void**)&w1t, g_W1_t);
    cudaGetSymbolAddress((void**)&w2t, g_W2_t);

    cudaFuncSetAttribute(mma_gemm_bf16_kernel,
                         cudaFuncAttributeMaxDynamicSharedMemorySize, GEMMB_SMEM);
    cudaFuncSetAttribute(attn_scores_mma_kernel,
                         cudaFuncAttributeMaxDynamicSharedMemorySize, ATTN_SMEM_BYTES);
    cudaFuncSetAttribute(attn_ctx_mma_kernel,
                         cudaFuncAttributeMaxDynamicSharedMemorySize, ATTN_SMEM_BYTES);

    // weight conversion + transpose (bf16, [N][K])
    for (int l = 0; l < LL; l++) {
        wconv_kernel<<<dim3(D3 / 32, DD / 32), dim3(32, 8)>>>(
            Wqkv + (size_t)l * DD * D3, wqkvt + (size_t)l * D3 * DD, DD, D3);
        wconv_kernel<<<dim3(DD / 32, DD / 32), dim3(32, 8)>>>(
            Wo + (size_t)l * DD * DD, wot + (size_t)l * DD * DD, DD, DD);
        wconv_kernel<<<dim3(FF / 32, DD / 32), dim3(32, 8)>>>(
            W1 + (size_t)l * DD * FF, w1t + (size_t)l * FF * DD, DD, FF);
        wconv_kernel<<<dim3(DD / 32, FF / 32), dim3(32, 8)>>>(
            W2 + (size_t)l * FF * DD, w2t + (size_t)l * DD * FF, FF, DD);
    }

    embed_ln_kernel<<<TT, 256>>>(ids, emb, pos, lng, lnb, xp, xbf);

    for (int l = 0; l < LL; l++) {
        mma_gemm_bf16_kernel<<<dim3(D3 / 128, TT / 128), 256, GEMMB_SMEM>>>(
            xbf, wqkvt + (size_t)l * D3 * DD, bqkv + (size_t)l * D3,
            qkvp, (  __nv_bfloat16*)nullptr, TT, D3, DD, 0);
        attn_scores_mma_kernel<<<dim3(SS / 64, BB * HH), 256, ATTN_SMEM_BYTES>>>(qkvp, am, attp);
        softmax_kernel<<<BB * HH * SS / 8, 256>>>(attp);
        attn_ctx_mma_kernel<<<dim3(SS / 64, BB * HH), 256, ATTN_SMEM_BYTES>>>(attp, qkvp, ctxbf);
        mma_gemm_bf16_kernel<<<dim3(DD / 128, TT / 128), 256, GEMMB_SMEM>>>(
            ctxbf, wot + (size_t)l * DD * DD, bo + (size_t)l * DD,
            tmpp, (__nv_bfloat16*)nullptr, TT, DD, DD, 0);
        ln_residual_kernel<<<TT, 256>>>(xp, tmpp, ln1g + (size_t)l * DD, ln1b + (size_t)l * DD, xp, xbf);
        mma_gemm_bf16_kernel<<<dim3(FF / 128, TT / 128), 256, GEMMB_SMEM>>>(
            xbf, w1t + (size_t)l * FF * DD, b1 + (size_t)l * FF,
            (float*)nullptr, ffnbf, TT, FF, DD, 1);
        mma_gemm_bf16_kernel<<<dim3(DD / 128, TT / 128), 256, GEMMB_SMEM>>>(
            ffnbf, w2t + (size_t)l * DD * FF, b2 + (size_t)l * DD,
            tmpp, (__nv_bfloat16*)nullptr, TT, DD, FF, 0);
        ln_residual_kernel<<<TT, 256>>>(xp, tmpp, ln2g + (size_t)l * DD, ln2b + (size_t)l * DD, xp, xbf);
    }

    cls_kernel<<<TT, 288>>>(xp, Wcls, bcls, logitsp);
    crf_score_kernel<<<BB, 512>>>(labels, am, logitsp, start_t, end_t, trans, scorep);
    crf_forward_kernel<<<BB, 32>>>(logitsp, am, start_t, end_t, trans, logZp);
    final_kernel<<<1, 32>>>(logZp, scorep, (float*)d_out);
}

// round 8
// speedup vs baseline: 4.1071x; 1.3169x over previous
#include <cuda_runtime.h>
#include <cuda_bf16.h>
#include <math.h>
#include <stdint.h>
#include <stddef.h>

// Problem constants
#define BB 16
#define SS 512
#define DD 768
#define HH 12
#define LL 4
#define FF 3072
#define HDD 64
#define NK 9
#define TT (BB*SS)          // 8192 tokens
#define D3 (3*DD)           // 2304

// ---------------- scratch (static device globals) ----------------
__device__ float g_x[(size_t)TT*DD];
__device__ float g_tmp[(size_t)TT*DD];
__device__ float g_logits[(size_t)TT*NK];
__device__ float g_logZ[BB];
__device__ float g_score[BB];

__device__ __nv_bfloat16 g_x_bf[(size_t)TT*DD];
__device__ __nv_bfloat16 g_qkv_bf[(size_t)TT*D3];
__device__ __nv_bfloat16 g_ctx_bf[(size_t)TT*DD];
__device__ __nv_bfloat16 g_ffn_bf[(size_t)TT*FF];
__device__ __nv_bfloat16 g_Wqkv_t[(size_t)LL*D3*DD];   // [l][N=D3][K=DD]
__device__ __nv_bfloat16 g_Wo_t[(size_t)LL*DD*DD];
__device__ __nv_bfloat16 g_W1_t[(size_t)LL*FF*DD];
__device__ __nv_bfloat16 g_W2_t[(size_t)LL*DD*FF];

// ---------------- helpers ----------------
__device__ __forceinline__ float blk_reduce256(float v, float* sh) {
    int tid = threadIdx.x;
    sh[tid] = v; __syncthreads();
    #pragma unroll
    for (int s = 128; s > 0; s >>= 1) {
        if (tid < s) sh[tid] += sh[tid + s];
        __syncthreads();
    }
    float r = sh[0]; __syncthreads();
    return r;
}

__device__ __forceinline__ void cp_async16(void* smem, const void* gmem) {
    uint32_t s = (uint32_t)__cvta_generic_to_shared(smem);
    asm volatile("cp.async.cg.shared.global [%0], [%1], 16;\n" :: "r"(s), "l"(gmem));
}
#define CP_COMMIT() asm volatile("cp.async.commit_group;\n")
#define CP_WAIT(n)  asm volatile("cp.async.wait_group %0;\n" :: "n"(n))

#define MMA_BF16(acc, a0,a1,a2,a3, b0,b1) \
    asm volatile( \
        "mma.sync.aligned.m16n8k16.row.col.f32.bf16.bf16.f32 " \
        "{%0,%1,%2,%3}, {%4,%5,%6,%7}, {%8,%9}, {%0,%1,%2,%3};" \
        : "+f"(acc[0]), "+f"(acc[1]), "+f"(acc[2]), "+f"(acc[3]) \
        : "r"(a0), "r"(a1), "r"(a2), "r"(a3), "r"(b0), "r"(b1))

// ---------------- weight convert + transpose: fp32 [K][N] -> bf16 [N][K], layer = blockIdx.z ----------------
__global__ void wconv_kernel(const float* __restrict__ W, __nv_bfloat16* __restrict__ Wt,
                             int K, int N) {
    W  += (size_t)blockIdx.z * K * N;
    Wt += (size_t)blockIdx.z * N * K;
    __shared__ float tile[32][33];
    int n0 = blockIdx.x * 32, k0 = blockIdx.y * 32;
    int tx = threadIdx.x, ty = threadIdx.y;
    #pragma unroll
    for (int j = ty; j < 32; j += 8)
        tile[j][tx] = W[(size_t)(k0 + j) * N + n0 + tx];
    __syncthreads();
    #pragma unroll
    for (int j = ty; j < 32; j += 8)
        Wt[(size_t)(n0 + j) * K + k0 + tx] = __float2bfloat16(tile[tx][j]);
}

// ---------------- embedding + LN (dual write fp32 + bf16) ----------------
__global__ void embed_ln_kernel(const int* __restrict__ ids, const float* __restrict__ emb,
                                const float* __restrict__ pos, const float* __restrict__ g,
                                const float* __restrict__ bta, float* __restrict__ out,
                                __nv_bfloat16* __restrict__ outb) {
    __shared__ float sh[256];
    int t = blockIdx.x, s = t % SS;
    int id = ids[t];
    const float* e = emb + (size_t)id * DD;
    const float* p = pos + (size_t)s * DD;
    float v[3]; float ls = 0.f, lq = 0.f;
    #pragma unroll
    for (int i = 0; i < 3; i++) {
        int d = threadIdx.x + i * 256;
        float w = e[d] + p[d];
        v[i] = w; ls += w; lq += w * w;
    }
    float sum = blk_reduce256(ls, sh);
    float sq  = blk_reduce256(lq, sh);
    float mean = sum * (1.0f / DD);
    float var  = sq * (1.0f / DD) - mean * mean;
    float rstd = rsqrtf(var + 1e-12f);
    float* o = out + (size_t)t * DD;
    __nv_bfloat16* ob = outb + (size_t)t * DD;
    #pragma unroll
    for (int i = 0; i < 3; i++) {
        int d = threadIdx.x + i * 256;
        float r = (v[i] - mean) * rstd * g[d] + bta[d];
        o[d] = r;
        ob[d] = __float2bfloat16(r);
    }
}

__global__ void ln_residual_kernel(const float* __restrict__ a, const float* __restrict__ r,
                                   const float* __restrict__ g, const float* __restrict__ bta,
                                   float* __restrict__ out, __nv_bfloat16* __restrict__ outb) {
    __shared__ float sh[256];
    int t = blockIdx.x;
    const float* ap = a + (size_t)t * DD;
    const float* rp = r + (size_t)t * DD;
    float v[3]; float ls = 0.f, lq = 0.f;
    #pragma unroll
    for (int i = 0; i < 3; i++) {
        int d = threadIdx.x + i * 256;
        float w = ap[d] + rp[d];
        v[i] = w; ls += w; lq += w * w;
    }
    float sum = blk_reduce256(ls, sh);
    float sq  = blk_reduce256(lq, sh);
    float mean = sum * (1.0f / DD);
    float var  = sq * (1.0f / DD) - mean * mean;
    float rstd = rsqrtf(var + 1e-12f);
    float* o = out + (size_t)t * DD;
    __nv_bfloat16* ob = outb + (size_t)t * DD;
    #pragma unroll
    for (int i = 0; i < 3; i++) {
        int d = threadIdx.x + i * 256;
        float rr = (v[i] - mean) * rstd * g[d] + bta[d];
        o[d] = rr;
        ob[d] = __float2bfloat16(rr);
    }
}

// ---------------- BF16 tensor-core GEMM, cp.async double buffered ----------------
#define GEMMB_SMEM (4 * 4608 * 4)
__global__ __launch_bounds__(256)
void mma_gemm_bf16_kernel(const __nv_bfloat16* __restrict__ A,
                          const __nv_bfloat16* __restrict__ Bt,
                          const float* __restrict__ bias,
                          float* __restrict__ Cf, __nv_bfloat16* __restrict__ Cb,
                          int M, int N, int Kd, int act) {
    extern __shared__ uint32_t dw[];
    uint32_t* AsB[2] = { dw,        dw + 4608 };
    uint32_t* BsB[2] = { dw + 9216, dw + 13824 };

    const int tid  = threadIdx.x;
    const int warp = tid >> 5, lane = tid & 31;
    const int warpM = warp >> 2, warpN = warp & 3;
    const int g = lane >> 2, tg = lane & 3;
    const int rowBase = blockIdx.y * 128;
    const int colBase = blockIdx.x * 128;

    float acc[4][4][4];
    #pragma unroll
    for (int im = 0; im < 4; im++)
        #pragma unroll
        for (int in = 0; in < 4; in++)
            #pragma unroll
            for (int r = 0; r < 4; r++) acc[im][in][r] = 0.f;

    auto load_stage = [&](int k0, int buf) {
        uint32_t* as = AsB[buf];
        uint32_t* bs = BsB[buf];
        #pragma unroll
        for (int i = 0; i < 4; i++) {
            int idx = i * 256 + tid;
            int r = idx >> 3;
            int cw = (idx & 7) * 4;
            int ch = (idx & 7) * 8;
            cp_async16(as + r * 36 + cw, A  + (size_t)(rowBase + r) * Kd + k0 + ch);
            cp_async16(bs + r * 36 + cw, Bt + (size_t)(colBase + r) * Kd + k0 + ch);
        }
        CP_COMMIT();
    };

    load_stage(0, 0);
    int buf = 0;
    for (int k0 = 0; k0 < Kd; k0 += 64) {
        bool has_next = (k0 + 64 < Kd);
        if (has_next) load_stage(k0 + 64, buf ^ 1);
        if (has_next) { CP_WAIT(1); } else { CP_WAIT(0); }
        __syncthreads();

        const uint32_t* as = AsB[buf];
        const uint32_t* bs = BsB[buf];
        #pragma unroll
        for (int ks = 0; ks < 4; ks++) {
            const int kw = ks * 8;
            uint32_t afr[4][4];
            #pragma unroll
            for (int im = 0; im < 4; im++) {
                int m = warpM * 64 + im * 16 + g;
                afr[im][0] = as[(m    ) * 36 + kw + tg    ];
                afr[im][1] = as[(m + 8) * 36 + kw + tg    ];
                afr[im][2] = as[(m    ) * 36 + kw + tg + 4];
                afr[im][3] = as[(m + 8) * 36 + kw + tg + 4];
            }
            uint32_t bfr[4][2];
            #pragma unroll
            for (int in = 0; in < 4; in++) {
                int n = warpN * 32 + in * 8 + g;
                bfr[in][0] = bs[n * 36 + kw + tg    ];
                bfr[in][1] = bs[n * 36 + kw + tg + 4];
            }
            #pragma unroll
            for (int im = 0; im < 4; im++)
                #pragma unroll
                for (int in = 0; in < 4; in++)
                    MMA_BF16(acc[im][in], afr[im][0], afr[im][1], afr[im][2], afr[im][3],
                             bfr[in][0], bfr[in][1]);
        }
        __syncthreads();
        buf ^= 1;
    }

    #pragma unroll
    for (int im = 0; im < 4; im++) {
        int row0 = rowBase + warpM * 64 + im * 16 + g;
        #pragma unroll
        for (int in = 0; in < 4; in++) {
            int col0 = colBase + warpN * 32 + in * 8 + tg * 2;
            float b0 = bias[col0], b1 = bias[col0 + 1];
            float v0 = acc[im][in][0] + b0;
            float v1 = acc[im][in][1] + b1;
            float v2 = acc[im][in][2] + b0;
            float v3 = acc[im][in][3] + b1;
            if (act) {
                float u, cc;
                u = v0; cc = 0.7978845608028654f * (u + 0.044715f * u * u * u); v0 = 0.5f * u * (1.0f + tanhf(cc));
                u = v1; cc = 0.7978845608028654f * (u + 0.044715f * u * u * u); v1 = 0.5f * u * (1.0f + tanhf(cc));
                u = v2; cc = 0.7978845608028654f * (u + 0.044715f * u * u * u); v2 = 0.5f * u * (1.0f + tanhf(cc));
                u = v3; cc = 0.7978845608028654f * (u + 0.044715f * u * u * u); v3 = 0.5f * u * (1.0f + tanhf(cc));
            }
            if (Cf) {
                Cf[(size_t)row0 * N + col0]           = v0;
                Cf[(size_t)row0 * N + col0 + 1]       = v1;
                Cf[(size_t)(row0 + 8) * N + col0]     = v2;
                Cf[(size_t)(row0 + 8) * N + col0 + 1] = v3;
            }
            if (Cb) {
                *(__nv_bfloat162*)(Cb + (size_t)row0 * N + col0)       = __floats2bfloat162_rn(v0, v1);
                *(__nv_bfloat162*)(Cb + (size_t)(row0 + 8) * N + col0) = __floats2bfloat162_rn(v2, v3);
            }
        }
    }
}

// ---------------- fused flash attention (bf16 mma, online softmax) ----------------
// grid (SS/64, BB*HH), 128 threads (4 warps; warp owns 16 q-rows).
// K/V tiles double-buffered via cp.async. Score frags feed P@V directly in-register.
__global__ __launch_bounds__(128)
void flash_attn_kernel(const __nv_bfloat16* __restrict__ qkvb, const int* __restrict__ amask,
                       __nv_bfloat16* __restrict__ ctxb) {
    __shared__ uint32_t Qs[64 * 36];
    __shared__ uint32_t Ks[2][64 * 36];
    __shared__ uint32_t Vs[2][64 * 36];
    __shared__ float bias_s[SS];

    const int bh = blockIdx.y;
    const int b = bh / HH, h = bh % HH;
    const int q0 = blockIdx.x * 64;
    const int tid = threadIdx.x;
    const int warp = tid >> 5, lane = tid & 31;
    const int g = lane >> 2, tg = lane & 3;

    const __nv_bfloat16* Qg = qkvb + (size_t)(b * SS + q0) * D3 + h * HDD;
    const __nv_bfloat16* Kg = qkvb + (size_t)(b * SS) * D3 + DD + h * HDD;
    const __nv_bfloat16* Vg = qkvb + (size_t)(b * SS) * D3 + 2 * DD + h * HDD;

    #pragma unroll
    for (int i = 0; i < 4; i++) {
        int c = i * 128 + tid;
        bias_s[c] = (1.0f - (float)amask[b * SS + c]) * -1e9f;
    }
    #pragma unroll
    for (int i = 0; i < 4; i++) {
        int idx = i * 128 + tid;
        int row = idx >> 3, ch = idx & 7;
        cp_async16(Qs + row * 36 + ch * 4,    Qg + (size_t)row * D3 + ch * 8);
        cp_async16(Ks[0] + row * 36 + ch * 4, Kg + (size_t)row * D3 + ch * 8);
        cp_async16(Vs[0] + row * 36 + ch * 4, Vg + (size_t)row * D3 + ch * 8);
    }
    CP_COMMIT();

    float m0 = -INFINITY, m1 = -INFINITY, l0 = 0.f, l1 = 0.f;
    float o[8][4];
    #pragma unroll
    for (int j = 0; j < 8; j++)
        #pragma unroll
        for (int r = 0; r < 4; r++) o[j][r] = 0.f;

    const int mat = lane >> 3, r8 = lane & 7;
    int buf = 0;
    for (int kt = 0; kt < 8; kt++) {
        if (kt < 7) {
            #pragma unroll
            for (int i = 0; i < 4; i++) {
                int idx = i * 128 + tid;
                int row = idx >> 3, ch = idx & 7;
                int grow = (kt + 1) * 64 + row;
                cp_async16(Ks[buf ^ 1] + row * 36 + ch * 4, Kg + (size_t)grow * D3 + ch * 8);
                cp_async16(Vs[buf ^ 1] + row * 36 + ch * 4, Vg + (size_t)grow * D3 + ch * 8);
            }
            CP_COMMIT();
            CP_WAIT(1);
        } else {
            CP_WAIT(0);
        }
        __syncthreads();

        // scores S = Q @ K^T  (16 q-rows x 64 k-cols per warp)
        float s[8][4];
        #pragma unroll
        for (int j = 0; j < 8; j++)
            #pragma unroll
            for (int r = 0; r < 4; r++) s[j][r] = 0.f;
        const uint32_t* ksm = Ks[buf];
        #pragma unroll
        for (int ks = 0; ks < 4; ks++) {
            int m = warp * 16 + g;
            uint32_t a0 = Qs[(m    ) * 36 + ks * 8 + tg];
            uint32_t a1 = Qs[(m + 8) * 36 + ks * 8 + tg];
            uint32_t a2 = Qs[(m    ) * 36 + ks * 8 + tg + 4];
            uint32_t a3 = Qs[(m + 8) * 36 + ks * 8 + tg + 4];
            #pragma unroll
            for (int j = 0; j < 8; j++) {
                uint32_t b0 = ksm[(j * 8 + g) * 36 + ks * 8 + tg];
                uint32_t b1 = ksm[(j * 8 + g) * 36 + ks * 8 + tg + 4];
                MMA_BF16(s[j], a0, a1, a2, a3, b0, b1);
            }
        }

        // scale + mask bias, row max (rows g and g+8; quad-reduce across tg)
        float mx0 = -INFINITY, mx1 = -INFINITY;
        #pragma unroll
        for (int j = 0; j < 8; j++) {
            float bi0 = bias_s[kt * 64 + j * 8 + 2 * tg];
            float bi1 = bias_s[kt * 64 + j * 8 + 2 * tg + 1];
            s[j][0] = s[j][0] * 0.125f + bi0;
            s[j][1] = s[j][1] * 0.125f + bi1;
            s[j][2] = s[j][2] * 0.125f + bi0;
            s[j][3] = s[j][3] * 0.125f + bi1;
            mx0 = fmaxf(mx0, fmaxf(s[j][0], s[j][1]));
            mx1 = fmaxf(mx1, fmaxf(s[j][2], s[j][3]));
        }
        mx0 = fmaxf(mx0, __shfl_xor_sync(0xffffffffu, mx0, 1));
        mx0 = fmaxf(mx0, __shfl_xor_sync(0xffffffffu, mx0, 2));
        mx1 = fmaxf(mx1, __shfl_xor_sync(0xffffffffu, mx1, 1));
        mx1 = fmaxf(mx1, __shfl_xor_sync(0xffffffffu, mx1, 2));

        float mn0 = fmaxf(m0, mx0), mn1 = fmaxf(m1, mx1);
        float al0 = expf(m0 - mn0), al1 = expf(m1 - mn1);
        float sum0 = 0.f, sum1 = 0.f;
        uint32_t pl[8], ph[8];
        #pragma unroll
        for (int j = 0; j < 8; j++) {
            float p0 = expf(s[j][0] - mn0), p1 = expf(s[j][1] - mn0);
            float p2 = expf(s[j][2] - mn1), p3 = expf(s[j][3] - mn1);
            sum0 += p0 + p1; sum1 += p2 + p3;
            __nv_bfloat162 t0 = __floats2bfloat162_rn(p0, p1);
            __nv_bfloat162 t1 = __floats2bfloat162_rn(p2, p3);
            pl[j] = *(uint32_t*)&t0;
            ph[j] = *(uint32_t*)&t1;
        }
        sum0 += __shfl_xor_sync(0xffffffffu, sum0, 1);
        sum0 += __shfl_xor_sync(0xffffffffu, sum0, 2);
        sum1 += __shfl_xor_sync(0xffffffffu, sum1, 1);
        sum1 += __shfl_xor_sync(0xffffffffu, sum1, 2);
        l0 = l0 * al0 + sum0; l1 = l1 * al1 + sum1;
        m0 = mn0; m1 = mn1;
        #pragma unroll
        for (int j = 0; j < 8; j++) {
            o[j][0] *= al0; o[j][1] *= al0; o[j][2] *= al1; o[j][3] *= al1;
        }

        // O += P @ V  (V via ldmatrix.trans from natural [seq][d] layout)
        uint32_t vbase = (uint32_t)__cvta_generic_to_shared(Vs[buf]);
        #pragma unroll
        for (int ks = 0; ks < 4; ks++) {
            uint32_t a0 = pl[2 * ks], a1 = ph[2 * ks], a2 = pl[2 * ks + 1], a3 = ph[2 * ks + 1];
            #pragma unroll
            for (int jj = 0; jj < 4; jj++) {
                int rowv = ks * 16 + (mat & 1) * 8 + r8;
                int colh = jj * 16 + (mat >> 1) * 8;
                uint32_t addr = vbase + (uint32_t)(rowv * 144 + colh * 2);
                uint32_t r0, r1, r2, r3;
                asm volatile("ldmatrix.sync.aligned.m8n8.x4.trans.shared.b16 {%0,%1,%2,%3}, [%4];"
                             : "=r"(r0), "=r"(r1), "=r"(r2), "=r"(r3) : "r"(addr));
                MMA_BF16(o[2 * jj],     a0, a1, a2, a3, r0, r1);
                MMA_BF16(o[2 * jj + 1], a0, a1, a2, a3, r2, r3);
            }
        }
        __syncthreads();
        buf ^= 1;
    }

    float inv0 = 1.f / l0, inv1 = 1.f / l1;
    int rowg = b * SS + q0 + warp * 16 + g;
    __nv_bfloat16* dst0 = ctxb + (size_t)rowg * DD + h * HDD;
    __nv_bfloat16* dst1 = dst0 + (size_t)8 * DD;
    #pragma unroll
    for (int j = 0; j < 8; j++) {
        *(__nv_bfloat162*)(dst0 + j * 8 + 2 * tg) = __floats2bfloat162_rn(o[j][0] * inv0, o[j][1] * inv0);
        *(__nv_bfloat162*)(dst1 + j * 8 + 2 * tg) = __floats2bfloat162_rn(o[j][2] * inv1, o[j][3] * inv1);
    }
}

// ---------------- classifier ----------------
__global__ __launch_bounds__(288)
void cls_kernel(const float* __restrict__ x, const float* __restrict__ W,
                const float* __restrict__ bias, float* __restrict__ logits) {
    int t = blockIdx.x;
    int w = threadIdx.x >> 5;
    int lane = threadIdx.x & 31;
    const float* xp = x + (size_t)t * DD;
    float s = 0.f;
    for (int d = lane; d < DD; d += 32) s += xp[d] * W[(size_t)d * NK + w];
    #pragma unroll
    for (int o = 16; o > 0; o >>= 1) s += __shfl_down_sync(0xffffffffu, s, o);
    if (lane == 0) logits[(size_t)t * NK + w] = s + bias[w];
}

// ---------------- CRF gold-path score ----------------
__global__ __launch_bounds__(512)
void crf_score_kernel(const int* __restrict__ labels, const int* __restrict__ amask,
                      const float* __restrict__ logits, const float* __restrict__ start_t,
                      const float* __restrict__ end_t, const float* __restrict__ trans,
                      float* __restrict__ score) {
    __shared__ float sf[512];
    __shared__ int si[512];
    int b = blockIdx.x;
    int t = threadIdx.x;
    const int* lab = labels + b * SS;
    const int* m = amask + b * SS;
    const float* lg = logits + (size_t)b * SS * NK;
    float em = lg[t * NK + lab[t]];
    float contrib = (t == 0) ? em : (float)m[t] * (trans[lab[t - 1] * NK + lab[t]] + em);
    sf[t] = contrib; si[t] = m[t];
    __syncthreads();
    #pragma unroll
    for (int s = 256; s > 0; s >>= 1) {
        if (t < s) { sf[t] += sf[t + s]; si[t] += si[t + s]; }
        __syncthreads();
    }
    if (t == 0) {
        int last = si[0] - 1;
        score[b] = sf[0] + start_t[lab[0]] + end_t[lab[last]];
    }
}

// ---------------- CRF forward (logZ) ----------------
__global__ __launch_bounds__(32)
void crf_forward_kernel(const float* __restrict__ logits, const int* __restrict__ amask,
                        const float* __restrict__ start_t, const float* __restrict__ end_t,
                        const float* __restrict__ trans, float* __restrict__ logZ) {
    __shared__ float lg[SS * NK];
    __shared__ float tr[NK * NK];
    __shared__ float alpha[2][NK];
    int b = blockIdx.x;
    int tid = threadIdx.x;
    const float* src = logits + (size_t)b * SS * NK;
    for (int i = tid; i < SS * NK; i += 32) lg[i] = src[i];
    for (int i = tid; i < NK * NK; i += 32) tr[i] = trans[i];
    if (tid < NK) alpha[0][tid] = start_t[tid] + lg[tid];
    __syncwarp();
    int cur = 0;
    for (int t = 1; t < SS; t++) {
        if (tid < NK) {
            int j = tid;
            float mx = -INFINITY;
            #pragma unroll
            for (int i = 0; i < NK; i++) mx = fmaxf(mx, alpha[cur][i] + tr[i * NK + j]);
            float s = 0.f;
            #pragma unroll
            for (int i = 0; i < NK; i++) s += expf(alpha[cur][i] + tr[i * NK + j] - mx);
            float cand = mx + logf(s) + lg[t * NK + j];
            alpha[cur ^ 1][j] = (amask[b * SS + t] > 0) ? cand : alpha[cur][j];
        }
        __syncwarp();
        cur ^= 1;
    }
    if (tid == 0) {
        float mx = -INFINITY;
        #pragma unroll
        for (int i = 0; i < NK; i++) mx = fmaxf(mx, alpha[cur][i] + end_t[i]);
        float s = 0.f;
        #pragma unroll
        for (int i = 0; i < NK; i++) s += expf(alpha[cur][i] + end_t[i] - mx);
        logZ[b] = mx + logf(s);
    }
}

// ---------------- final reduction ----------------
__global__ __launch_bounds__(32)
void final_kernel(const float* __restrict__ logZ, const float* __restrict__ score,
                  float* __restrict__ out) {
    int tid = threadIdx.x;
    float v = (tid < BB) ? (logZ[tid] - score[tid]) : 0.f;
    #pragma unroll
    for (int o = 16; o > 0; o >>= 1) v += __shfl_down_sync(0xffffffffu, v, o);
    if (tid == 0) out[0] = v;
}

// ---------------- launch ----------------
extern "C" void kernel_launch(void* const* d_in, const int* in_sizes, int n_in,
                              void* d_out, int out_size) {
    const int*   ids     = (const int*)d_in[0];
    const int*   am      = (const int*)d_in[1];
    const int*   labels  = (const int*)d_in[2];
    const float* emb     = (const float*)d_in[3];
    const float* pos     = (const float*)d_in[4];
    const float* lng     = (const float*)d_in[5];
    const float* lnb     = (const float*)d_in[6];
    const float* Wqkv    = (const float*)d_in[7];
    const float* bqkv    = (const float*)d_in[8];
    const float* Wo      = (const float*)d_in[9];
    const float* bo      = (const float*)d_in[10];
    const float* ln1g    = (const float*)d_in[11];
    const float* ln1b    = (const float*)d_in[12];
    const float* W1      = (const float*)d_in[13];
    const float* b1      = (const float*)d_in[14];
    const float* W2      = (const float*)d_in[15];
    const float* b2      = (const float*)d_in[16];
    const float* ln2g    = (const float*)d_in[17];
    const float* ln2b    = (const float*)d_in[18];
    const float* Wcls    = (const float*)d_in[19];
    const float* bcls    = (const float*)d_in[20];
    const float* start_t = (const float*)d_in[21];
    const float* end_t   = (const float*)d_in[22];
    const float* trans   = (const float*)d_in[23];

    float *xp, *tmpp, *logitsp, *logZp, *scorep;
    __nv_bfloat16 *xbf, *qkvbf, *ctxbf, *ffnbf, *wqkvt, *wot, *w1t, *w2t;
    cudaGetSymbolAddress((void**)&xp, g_x);
    cudaGetSymbolAddress((void**)&tmpp, g_tmp);
    cudaGetSymbolAddress((void**)&logitsp, g_logits);
    cudaGetSymbolAddress((void**)&logZp, g_logZ);
    cudaGetSymbolAddress((void**)&scorep, g_score);
    cudaGetSymbolAddress((void**)&xbf, g_x_bf);
    cudaGetSymbolAddress((void**)&qkvbf, g_qkv_bf);
    cudaGetSymbolAddress((void**)&ctxbf, g_ctx_bf);
    cudaGetSymbolAddress((void**)&ffnbf, g_ffn_bf);
    cudaGetSymbolAddress((void**)&wqkvt, g_Wqkv_t);
    cudaGetSymbolAddress((void**)&wot, g_Wo_t);
    cudaGetSymbolAddress((void**)&w1t, g_W1_t);
    cudaGetSymbolAddress((void**)&w2t, g_W2_t);

    cudaFuncSetAttribute(mma_gemm_bf16_kernel,
                         cudaFuncAttributeMaxDynamicSharedMemorySize, GEMMB_SMEM);

    // weight conversion + transpose, batched across layers via gridDim.z
    wconv_kernel<<<dim3(D3 / 32, DD / 32, LL), dim3(32, 8)>>>(Wqkv, wqkvt, DD, D3);
    wconv_kernel<<<dim3(DD / 32, DD / 32, LL), dim3(32, 8)>>>(Wo, wot, DD, DD);
    wconv_kernel<<<dim3(FF / 32, DD / 32, LL), dim3(32, 8)>>>(W1, w1t, DD, FF);
    wconv_kernel<<<dim3(DD / 32, FF / 32, LL), dim3(32, 8)>>>(W2, w2t, FF, DD);

    embed_ln_kernel<<<TT, 256>>>(ids, emb, pos, lng, lnb, xp, xbf);

    for (int l = 0; l < LL; l++) {
        mma_gemm_bf16_kernel<<<dim3(D3 / 128, TT / 128), 256, GEMMB_SMEM>>>(
            xbf, wqkvt + (size_t)l * D3 * DD, bqkv + (size_t)l * D3,
            (float*)nullptr, qkvbf, TT, D3, DD, 0);
        flash_attn_kernel<<<dim3(SS / 64, BB * HH), 128>>>(qkvbf, am, ctxbf);
        mma_gemm_bf16_kernel<<<dim3(DD / 128, TT / 128), 256, GEMMB_SMEM>>>(
            ctxbf, wot + (size_t)l * DD * DD, bo + (size_t)l * DD,
            tmpp, (__nv_bfloat16*)nullptr, TT, DD, DD, 0);
        ln_residual_kernel<<<TT, 256>>>(xp, tmpp, ln1g + (size_t)l * DD, ln1b + (size_t)l * DD, xp, xbf);
        mma_gemm_bf16_kernel<<<dim3(FF / 128, TT / 128), 256, GEMMB_SMEM>>>(
            xbf, w1t + (size_t)l * FF * DD, b1 + (size_t)l * FF,
            (float*)nullptr, ffnbf, TT, FF, DD, 1);
        mma_gemm_bf16_kernel<<<dim3(DD / 128, TT / 128), 256, GEMMB_SMEM>>>(
            ffnbf, w2t + (size_t)l * DD * FF, b2 + (size_t)l * DD,
            tmpp, (__nv_bfloat16*)nullptr, TT, DD, FF, 0);
        ln_residual_kernel<<<TT, 256>>>(xp, tmpp, ln2g + (size_t)l * DD, ln2b + (size_t)l * DD, xp, xbf);
    }

    cls_kernel<<<TT, 288>>>(xp, Wcls, bcls, logitsp);
    crf_score_kernel<<<BB, 512>>>(labels, am, logitsp, start_t, end_t, trans, scorep);
    crf_forward_kernel<<<BB, 32>>>(logitsp, am, start_t, end_t, trans, logZp);
    final_kernel<<<1, 32>>>(logZp, scorep, (float*)d_out);
}

// round 9
// speedup vs baseline: 5.9134x; 1.4398x over previous
#include <cuda_runtime.h>
#include <cuda_bf16.h>
#include <math.h>
#include <stdint.h>
#include <stddef.h>

// Problem constants
#define BB 16
#define SS 512
#define DD 768
#define HH 12
#define LL 4
#define FF 3072
#define HDD 64
#define NK 9
#define TT (BB*SS)          // 8192 tokens
#define D3 (3*DD)           // 2304

// ---------------- scratch (static device globals) ----------------
__device__ float g_x[(size_t)TT*DD];
__device__ float g_tmp[(size_t)TT*DD];
__device__ float g_logits[(size_t)TT*NK];
__device__ float g_logZ[BB];
__device__ float g_score[BB];

__device__ __nv_bfloat16 g_x_bf[(size_t)TT*DD];
__device__ __nv_bfloat16 g_qkv_bf[(size_t)TT*D3];
__device__ __nv_bfloat16 g_ctx_bf[(size_t)TT*DD];
__device__ __nv_bfloat16 g_ffn_bf[(size_t)TT*FF];
__device__ __nv_bfloat16 g_Wqkv_t[(size_t)LL*D3*DD];   // [l][N=D3][K=DD]
__device__ __nv_bfloat16 g_Wo_t[(size_t)LL*DD*DD];
__device__ __nv_bfloat16 g_W1_t[(size_t)LL*FF*DD];
__device__ __nv_bfloat16 g_W2_t[(size_t)LL*DD*FF];

// ---------------- helpers ----------------
__device__ __forceinline__ float blk_reduce256(float v, float* sh) {
    int tid = threadIdx.x;
    sh[tid] = v; __syncthreads();
    #pragma unroll
    for (int s = 128; s > 0; s >>= 1) {
        if (tid < s) sh[tid] += sh[tid + s];
        __syncthreads();
    }
    float r = sh[0]; __syncthreads();
    return r;
}

__device__ __forceinline__ void cp_async16(void* smem, const void* gmem) {
    uint32_t s = (uint32_t)__cvta_generic_to_shared(smem);
    asm volatile("cp.async.cg.shared.global [%0], [%1], 16;\n" :: "r"(s), "l"(gmem));
}
#define CP_COMMIT() asm volatile("cp.async.commit_group;\n")
#define CP_WAIT(n)  asm volatile("cp.async.wait_group %0;\n" :: "n"(n))

#define MMA_BF16(acc, a0,a1,a2,a3, b0,b1) \
    asm volatile( \
        "mma.sync.aligned.m16n8k16.row.col.f32.bf16.bf16.f32 " \
        "{%0,%1,%2,%3}, {%4,%5,%6,%7}, {%8,%9}, {%0,%1,%2,%3};" \
        : "+f"(acc[0]), "+f"(acc[1]), "+f"(acc[2]), "+f"(acc[3]) \
        : "r"(a0), "r"(a1), "r"(a2), "r"(a3), "r"(b0), "r"(b1))

#define LDMX4(r0,r1,r2,r3, addr) \
    asm volatile("ldmatrix.sync.aligned.m8n8.x4.shared.b16 {%0,%1,%2,%3}, [%4];" \
        : "=r"(r0), "=r"(r1), "=r"(r2), "=r"(r3) : "r"(addr))

__device__ __forceinline__ float fast_tanh(float x) {
    float y;
    asm("tanh.approx.f32 %0, %1;" : "=f"(y) : "f"(x));
    return y;
}

// ---------------- weight convert + transpose: fp32 [K][N] -> bf16 [N][K], layer = blockIdx.z ----------------
__global__ void wconv_kernel(const float* __restrict__ W, __nv_bfloat16* __restrict__ Wt,
                             int K, int N) {
    W  += (size_t)blockIdx.z * K * N;
    Wt += (size_t)blockIdx.z * N * K;
    __shared__ float tile[32][33];
    int n0 = blockIdx.x * 32, k0 = blockIdx.y * 32;
    int tx = threadIdx.x, ty = threadIdx.y;
    #pragma unroll
    for (int j = ty; j < 32; j += 8)
        tile[j][tx] = W[(size_t)(k0 + j) * N + n0 + tx];
    __syncthreads();
    #pragma unroll
    for (int j = ty; j < 32; j += 8)
        Wt[(size_t)(n0 + j) * K + k0 + tx] = __float2bfloat16(tile[tx][j]);
}

// ---------------- embedding + LN (dual write fp32 + bf16) ----------------
__global__ void embed_ln_kernel(const int* __restrict__ ids, const float* __restrict__ emb,
                                const float* __restrict__ pos, const float* __restrict__ g,
                                const float* __restrict__ bta, float* __restrict__ out,
                                __nv_bfloat16* __restrict__ outb) {
    __shared__ float sh[256];
    int t = blockIdx.x, s = t % SS;
    int id = ids[t];
    const float* e = emb + (size_t)id * DD;
    const float* p = pos + (size_t)s * DD;
    float v[3]; float ls = 0.f, lq = 0.f;
    #pragma unroll
    for (int i = 0; i < 3; i++) {
        int d = threadIdx.x + i * 256;
        float w = e[d] + p[d];
        v[i] = w; ls += w; lq += w * w;
    }
    float sum = blk_reduce256(ls, sh);
    float sq  = blk_reduce256(lq, sh);
    float mean = sum * (1.0f / DD);
    float var  = sq * (1.0f / DD) - mean * mean;
    float rstd = rsqrtf(var + 1e-12f);
    float* o = out + (size_t)t * DD;
    __nv_bfloat16* ob = outb + (size_t)t * DD;
    #pragma unroll
    for (int i = 0; i < 3; i++) {
        int d = threadIdx.x + i * 256;
        float r = (v[i] - mean) * rstd * g[d] + bta[d];
        o[d] = r;
        ob[d] = __float2bfloat16(r);
    }
}

__global__ void ln_residual_kernel(const float* __restrict__ a, const float* __restrict__ r,
                                   const float* __restrict__ g, const float* __restrict__ bta,
                                   float* __restrict__ out, __nv_bfloat16* __restrict__ outb) {
    __shared__ float sh[256];
    int t = blockIdx.x;
    const float* ap = a + (size_t)t * DD;
    const float* rp = r + (size_t)t * DD;
    float v[3]; float ls = 0.f, lq = 0.f;
    #pragma unroll
    for (int i = 0; i < 3; i++) {
        int d = threadIdx.x + i * 256;
        float w = ap[d] + rp[d];
        v[i] = w; ls += w; lq += w * w;
    }
    float sum = blk_reduce256(ls, sh);
    float sq  = blk_reduce256(lq, sh);
    float mean = sum * (1.0f / DD);
    float var  = sq * (1.0f / DD) - mean * mean;
    float rstd = rsqrtf(var + 1e-12f);
    float* o = out + (size_t)t * DD;
    __nv_bfloat16* ob = outb + (size_t)t * DD;
    #pragma unroll
    for (int i = 0; i < 3; i++) {
        int d = threadIdx.x + i * 256;
        float rr = (v[i] - mean) * rstd * g[d] + bta[d];
        o[d] = rr;
        ob[d] = __float2bfloat16(rr);
    }
}

// ---------------- BF16 tensor-core GEMM: ldmatrix frags + 3-stage cp.async ----------------
// C[M,N] = A[M,K] @ Bt[N,K]^T + bias[N]. Per stage: A 128x64h (36 words/row) + B 128x64h.
// Stage s: A at word s*9216, B at word s*9216+4608. 3 stages = 110592 bytes.
#define GEMM_STAGES 3
#define GEMMB_SMEM (GEMM_STAGES * 9216 * 4)
__global__ __launch_bounds__(256)
void mma_gemm_bf16_kernel(const __nv_bfloat16* __restrict__ A,
                          const __nv_bfloat16* __restrict__ Bt,
                          const float* __restrict__ bias,
                          float* __restrict__ Cf, __nv_bfloat16* __restrict__ Cb,
                          int M, int N, int Kd, int act) {
    extern __shared__ uint32_t dw[];

    const int tid  = threadIdx.x;
    const int warp = tid >> 5, lane = tid & 31;
    const int warpM = warp >> 2, warpN = warp & 3;
    const int g = lane >> 2, tg = lane & 3;
    const int rowBase = blockIdx.y * 128;
    const int colBase = blockIdx.x * 128;

    // ldmatrix per-lane addressing
    const int sub = lane >> 3, rr = lane & 7;
    const int rowA  = warpM * 64 + (sub & 1) * 8 + rr;   // + im*16
    const int koffA = (sub >> 1) * 8;                     // halves
    const int rowB  = warpN * 32 + ((sub >> 1) & 1) * 8 + rr;  // + inp*16
    const int koffB = (sub & 1) * 8;
    const uint32_t smem0 = (uint32_t)__cvta_generic_to_shared(dw);

    float acc[4][4][4];
    #pragma unroll
    for (int im = 0; im < 4; im++)
        #pragma unroll
        for (int in = 0; in < 4; in++)
            #pragma unroll
            for (int r = 0; r < 4; r++) acc[im][in][r] = 0.f;

    auto load_stage = [&](int k0, int s) {
        uint32_t* as = dw + s * 9216;
        uint32_t* bs = as + 4608;
        #pragma unroll
        for (int i = 0; i < 4; i++) {
            int idx = i * 256 + tid;
            int r = idx >> 3;
            int cw = (idx & 7) * 4;
            int ch = (idx & 7) * 8;
            cp_async16(as + r * 36 + cw, A  + (size_t)(rowBase + r) * Kd + k0 + ch);
            cp_async16(bs + r * 36 + cw, Bt + (size_t)(colBase + r) * Kd + k0 + ch);
        }
    };

    const int nK = Kd >> 6;
    load_stage(0, 0); CP_COMMIT();
    load_stage(64, 1); CP_COMMIT();
    int buf = 0;
    for (int kt = 0; kt < nK; kt++) {
        if (kt + 2 < nK) load_stage((kt + 2) << 6, (buf + 2) % 3);
        CP_COMMIT();
        CP_WAIT(2);
        __syncthreads();

        const uint32_t aBase = smem0 + (uint32_t)(buf * 9216) * 4;
        const uint32_t bBase = aBase + 4608 * 4;
        #pragma unroll
        for (int ks = 0; ks < 4; ks++) {
            uint32_t afr[4][4];
            #pragma unroll
            for (int im = 0; im < 4; im++) {
                uint32_t ad = aBase + (uint32_t)(((rowA + im * 16) * 72 + ks * 16 + koffA) * 2);
                LDMX4(afr[im][0], afr[im][1], afr[im][2], afr[im][3], ad);
            }
            uint32_t bq[2][4];
            #pragma unroll
            for (int inp = 0; inp < 2; inp++) {
                uint32_t bd = bBase + (uint32_t)(((rowB + inp * 16) * 72 + ks * 16 + koffB) * 2);
                LDMX4(bq[inp][0], bq[inp][1], bq[inp][2], bq[inp][3], bd);
            }
            #pragma unroll
            for (int im = 0; im < 4; im++)
                #pragma unroll
                for (int in = 0; in < 4; in++) {
                    if (in & 1)
                        MMA_BF16(acc[im][in], afr[im][0], afr[im][1], afr[im][2], afr[im][3],
                                 bq[in >> 1][2], bq[in >> 1][3]);
                    else
                        MMA_BF16(acc[im][in], afr[im][0], afr[im][1], afr[im][2], afr[im][3],
                                 bq[in >> 1][0], bq[in >> 1][1]);
                }
        }
        __syncthreads();
        buf = (buf + 1) % 3;
    }

    #pragma unroll
    for (int im = 0; im < 4; im++) {
        int row0 = rowBase + warpM * 64 + im * 16 + g;
        #pragma unroll
        for (int in = 0; in < 4; in++) {
            int col0 = colBase + warpN * 32 + in * 8 + tg * 2;
            float b0 = bias[col0], b1 = bias[col0 + 1];
            float v0 = acc[im][in][0] + b0;
            float v1 = acc[im][in][1] + b1;
            float v2 = acc[im][in][2] + b0;
            float v3 = acc[im][in][3] + b1;
            if (act) {
                float u, cc;
                u = v0; cc = 0.7978845608028654f * (u + 0.044715f * u * u * u); v0 = 0.5f * u * (1.0f + fast_tanh(cc));
                u = v1; cc = 0.7978845608028654f * (u + 0.044715f * u * u * u); v1 = 0.5f * u * (1.0f + fast_tanh(cc));
                u = v2; cc = 0.7978845608028654f * (u + 0.044715f * u * u * u); v2 = 0.5f * u * (1.0f + fast_tanh(cc));
                u = v3; cc = 0.7978845608028654f * (u + 0.044715f * u * u * u); v3 = 0.5f * u * (1.0f + fast_tanh(cc));
            }
            if (Cf) {
                Cf[(size_t)row0 * N + col0]           = v0;
                Cf[(size_t)row0 * N + col0 + 1]       = v1;
                Cf[(size_t)(row0 + 8) * N + col0]     = v2;
                Cf[(size_t)(row0 + 8) * N + col0 + 1] = v3;
            }
            if (Cb) {
                *(__nv_bfloat162*)(Cb + (size_t)row0 * N + col0)       = __floats2bfloat162_rn(v0, v1);
                *(__nv_bfloat162*)(Cb + (size_t)(row0 + 8) * N + col0) = __floats2bfloat162_rn(v2, v3);
            }
        }
    }
}

// ---------------- fused flash attention (bf16 mma, online softmax, ldmatrix frags) ----------------
__global__ __launch_bounds__(128)
void flash_attn_kernel(const __nv_bfloat16* __restrict__ qkvb, const int* __restrict__ amask,
                       __nv_bfloat16* __restrict__ ctxb) {
    __shared__ uint32_t Qs[64 * 36];
    __shared__ uint32_t Ks[2][64 * 36];
    __shared__ uint32_t Vs[2][64 * 36];
    __shared__ float bias_s[SS];

    const int bh = blockIdx.y;
    const int b = bh / HH, h = bh % HH;
    const int q0 = blockIdx.x * 64;
    const int tid = threadIdx.x;
    const int warp = tid >> 5, lane = tid & 31;
    const int g = lane >> 2, tg = lane & 3;
    const int sub = lane >> 3, rr8 = lane & 7;

    const __nv_bfloat16* Qg = qkvb + (size_t)(b * SS + q0) * D3 + h * HDD;
    const __nv_bfloat16* Kg = qkvb + (size_t)(b * SS) * D3 + DD + h * HDD;
    const __nv_bfloat16* Vg = qkvb + (size_t)(b * SS) * D3 + 2 * DD + h * HDD;

    const uint32_t qbase = (uint32_t)__cvta_generic_to_shared(Qs);
    const uint32_t kbase0 = (uint32_t)__cvta_generic_to_shared(Ks[0]);
    const uint32_t vbase0 = (uint32_t)__cvta_generic_to_shared(Vs[0]);

    // ldmatrix lane addressing (A-frag for Q, B-frag for K)
    const int rowQa  = warp * 16 + (sub & 1) * 8 + rr8;
    const int koffQa = (sub >> 1) * 8;
    const int rowKb  = ((sub >> 1) & 1) * 8 + rr8;   // + jp*16
    const int koffKb = (sub & 1) * 8;

    #pragma unroll
    for (int i = 0; i < 4; i++) {
        int c = i * 128 + tid;
        bias_s[c] = (1.0f - (float)amask[b * SS + c]) * -1e9f;
    }
    #pragma unroll
    for (int i = 0; i < 4; i++) {
        int idx = i * 128 + tid;
        int row = idx >> 3, ch = idx & 7;
        cp_async16(Qs + row * 36 + ch * 4,    Qg + (size_t)row * D3 + ch * 8);
        cp_async16(Ks[0] + row * 36 + ch * 4, Kg + (size_t)row * D3 + ch * 8);
        cp_async16(Vs[0] + row * 36 + ch * 4, Vg + (size_t)row * D3 + ch * 8);
    }
    CP_COMMIT();

    float m0 = -INFINITY, m1 = -INFINITY, l0 = 0.f, l1 = 0.f;
    float o[8][4];
    #pragma unroll
    for (int j = 0; j < 8; j++)
        #pragma unroll
        for (int r = 0; r < 4; r++) o[j][r] = 0.f;

    const int mat = lane >> 3, r8 = lane & 7;
    int buf = 0;
    for (int kt = 0; kt < 8; kt++) {
        if (kt < 7) {
            #pragma unroll
            for (int i = 0; i < 4; i++) {
                int idx = i * 128 + tid;
                int row = idx >> 3, ch = idx & 7;
                int grow = (kt + 1) * 64 + row;
                cp_async16(Ks[buf ^ 1] + row * 36 + ch * 4, Kg + (size_t)grow * D3 + ch * 8);
                cp_async16(Vs[buf ^ 1] + row * 36 + ch * 4, Vg + (size_t)grow * D3 + ch * 8);
            }
            CP_COMMIT();
            CP_WAIT(1);
        } else {
            CP_WAIT(0);
        }
        __syncthreads();

        // scores S = Q @ K^T
        float s[8][4];
        #pragma unroll
        for (int j = 0; j < 8; j++)
            #pragma unroll
            for (int r = 0; r < 4; r++) s[j][r] = 0.f;
        const uint32_t kbase = kbase0 + (uint32_t)(buf * 64 * 36 * 4);
        #pragma unroll
        for (int ks = 0; ks < 4; ks++) {
            uint32_t a0, a1, a2, a3;
            uint32_t qa = qbase + (uint32_t)((rowQa * 72 + ks * 16 + koffQa) * 2);
            LDMX4(a0, a1, a2, a3, qa);
            #pragma unroll
            for (int jp = 0; jp < 4; jp++) {
                uint32_t b0, b1, b2, b3;
                uint32_t kd = kbase + (uint32_t)(((rowKb + jp * 16) * 72 + ks * 16 + koffKb) * 2);
                LDMX4(b0, b1, b2, b3, kd);
                MMA_BF16(s[2 * jp],     a0, a1, a2, a3, b0, b1);
                MMA_BF16(s[2 * jp + 1], a0, a1, a2, a3, b2, b3);
            }
        }

        // scale + mask bias, online softmax
        float mx0 = -INFINITY, mx1 = -INFINITY;
        #pragma unroll
        for (int j = 0; j < 8; j++) {
            float bi0 = bias_s[kt * 64 + j * 8 + 2 * tg];
            float bi1 = bias_s[kt * 64 + j * 8 + 2 * tg + 1];
            s[j][0] = s[j][0] * 0.125f + bi0;
            s[j][1] = s[j][1] * 0.125f + bi1;
            s[j][2] = s[j][2] * 0.125f + bi0;
            s[j][3] = s[j][3] * 0.125f + bi1;
            mx0 = fmaxf(mx0, fmaxf(s[j][0], s[j][1]));
            mx1 = fmaxf(mx1, fmaxf(s[j][2], s[j][3]));
        }
        mx0 = fmaxf(mx0, __shfl_xor_sync(0xffffffffu, mx0, 1));
        mx0 = fmaxf(mx0, __shfl_xor_sync(0xffffffffu, mx0, 2));
        mx1 = fmaxf(mx1, __shfl_xor_sync(0xffffffffu, mx1, 1));
        mx1 = fmaxf(mx1, __shfl_xor_sync(0xffffffffu, mx1, 2));

        float mn0 = fmaxf(m0, mx0), mn1 = fmaxf(m1, mx1);
        float al0 = __expf(m0 - mn0), al1 = __expf(m1 - mn1);
        float sum0 = 0.f, sum1 = 0.f;
        uint32_t pl[8], ph[8];
        #pragma unroll
        for (int j = 0; j < 8; j++) {
            float p0 = __expf(s[j][0] - mn0), p1 = __expf(s[j][1] - mn0);
            float p2 = __expf(s[j][2] - mn1), p3 = __expf(s[j][3] - mn1);
            sum0 += p0 + p1; sum1 += p2 + p3;
            __nv_bfloat162 t0 = __floats2bfloat162_rn(p0, p1);
            __nv_bfloat162 t1 = __floats2bfloat162_rn(p2, p3);
            pl[j] = *(uint32_t*)&t0;
            ph[j] = *(uint32_t*)&t1;
        }
        sum0 += __shfl_xor_sync(0xffffffffu, sum0, 1);
        sum0 += __shfl_xor_sync(0xffffffffu, sum0, 2);
        sum1 += __shfl_xor_sync(0xffffffffu, sum1, 1);
        sum1 += __shfl_xor_sync(0xffffffffu, sum1, 2);
        l0 = l0 * al0 + sum0; l1 = l1 * al1 + sum1;
        m0 = mn0; m1 = mn1;
        #pragma unroll
        for (int j = 0; j < 8; j++) {
            o[j][0] *= al0; o[j][1] *= al0; o[j][2] *= al1; o[j][3] *= al1;
        }

        // O += P @ V
        uint32_t vbase = vbase0 + (uint32_t)(buf * 64 * 36 * 4);
        #pragma unroll
        for (int ks = 0; ks < 4; ks++) {
            uint32_t a0 = pl[2 * ks], a1 = ph[2 * ks], a2 = pl[2 * ks + 1], a3 = ph[2 * ks + 1];
            #pragma unroll
            for (int jj = 0; jj < 4; jj++) {
                int rowv = ks * 16 + (mat & 1) * 8 + r8;
                int colh = jj * 16 + (mat >> 1) * 8;
                uint32_t addr = vbase + (uint32_t)(rowv * 144 + colh * 2);
                uint32_t r0, r1, r2, r3;
                asm volatile("ldmatrix.sync.aligned.m8n8.x4.trans.shared.b16 {%0,%1,%2,%3}, [%4];"
                             : "=r"(r0), "=r"(r1), "=r"(r2), "=r"(r3) : "r"(addr));
                MMA_BF16(o[2 * jj],     a0, a1, a2, a3, r0, r1);
                MMA_BF16(o[2 * jj + 1], a0, a1, a2, a3, r2, r3);
            }
        }
        __syncthreads();
        buf ^= 1;
    }

    float inv0 = 1.f / l0, inv1 = 1.f / l1;
    int rowg = b * SS + q0 + warp * 16 + g;
    __nv_bfloat16* dst0 = ctxb + (size_t)rowg * DD + h * HDD;
    __nv_bfloat16* dst1 = dst0 + (size_t)8 * DD;
    #pragma unroll
    for (int j = 0; j < 8; j++) {
        *(__nv_bfloat162*)(dst0 + j * 8 + 2 * tg) = __floats2bfloat162_rn(o[j][0] * inv0, o[j][1] * inv0);
        *(__nv_bfloat162*)(dst1 + j * 8 + 2 * tg) = __floats2bfloat162_rn(o[j][2] * inv1, o[j][3] * inv1);
    }
}

// ---------------- classifier ----------------
__global__ __launch_bounds__(288)
void cls_kernel(const float* __restrict__ x, const float* __restrict__ W,
                const float* __restrict__ bias, float* __restrict__ logits) {
    int t = blockIdx.x;
    int w = threadIdx.x >> 5;
    int lane = threadIdx.x & 31;
    const float* xp = x + (size_t)t * DD;
    float s = 0.f;
    for (int d = lane; d < DD; d += 32) s += xp[d] * W[(size_t)d * NK + w];
    #pragma unroll
    for (int o = 16; o > 0; o >>= 1) s += __shfl_down_sync(0xffffffffu, s, o);
    if (lane == 0) logits[(size_t)t * NK + w] = s + bias[w];
}

// ---------------- CRF gold-path score ----------------
__global__ __launch_bounds__(512)
void crf_score_kernel(const int* __restrict__ labels, const int* __restrict__ amask,
                      const float* __restrict__ logits, const float* __restrict__ start_t,
                      const float* __restrict__ end_t, const float* __restrict__ trans,
                      float* __restrict__ score) {
    __shared__ float sf[512];
    __shared__ int si[512];
    int b = blockIdx.x;
    int t = threadIdx.x;
    const int* lab = labels + b * SS;
    const int* m = amask + b * SS;
    const float* lg = logits + (size_t)b * SS * NK;
    float em = lg[t * NK + lab[t]];
    float contrib = (t == 0) ? em : (float)m[t] * (trans[lab[t - 1] * NK + lab[t]] + em);
    sf[t] = contrib; si[t] = m[t];
    __syncthreads();
    #pragma unroll
    for (int s = 256; s > 0; s >>= 1) {
        if (t < s) { sf[t] += sf[t + s]; si[t] += si[t + s]; }
        __syncthreads();
    }
    if (t == 0) {
        int last = si[0] - 1;
        score[b] = sf[0] + start_t[lab[0]] + end_t[lab[last]];
    }
}

// ---------------- CRF forward (logZ) ----------------
__global__ __launch_bounds__(32)
void crf_forward_kernel(const float* __restrict__ logits, const int* __restrict__ amask,
                        const float* __restrict__ start_t, const float* __restrict__ end_t,
                        const float* __restrict__ trans, float* __restrict__ logZ) {
    __shared__ float lg[SS * NK];
    __shared__ float tr[NK * NK];
    __shared__ float alpha[2][NK];
    int b = blockIdx.x;
    int tid = threadIdx.x;
    const float* src = logits + (size_t)b * SS * NK;
    for (int i = tid; i < SS * NK; i += 32) lg[i] = src[i];
    for (int i = tid; i < NK * NK; i += 32) tr[i] = trans[i];
    if (tid < NK) alpha[0][tid] = start_t[tid] + lg[tid];
    __syncwarp();
    int cur = 0;
    for (int t = 1; t < SS; t++) {
        if (tid < NK) {
            int j = tid;
            float mx = -INFINITY;
            #pragma unroll
            for (int i = 0; i < NK; i++) mx = fmaxf(mx, alpha[cur][i] + tr[i * NK + j]);
            float s = 0.f;
            #pragma unroll
            for (int i = 0; i < NK; i++) s += expf(alpha[cur][i] + tr[i * NK + j] - mx);
            float cand = mx + logf(s) + lg[t * NK + j];
            alpha[cur ^ 1][j] = (amask[b * SS + t] > 0) ? cand : alpha[cur][j];
        }
        __syncwarp();
        cur ^= 1;
    }
    if (tid == 0) {
        float mx = -INFINITY;
        #pragma unroll
        for (int i = 0; i < NK; i++) mx = fmaxf(mx, alpha[cur][i] + end_t[i]);
        float s = 0.f;
        #pragma unroll
        for (int i = 0; i < NK; i++) s += expf(alpha[cur][i] + end_t[i] - mx);
        logZ[b] = mx + logf(s);
    }
}

// ---------------- final reduction ----------------
__global__ __launch_bounds__(32)
void final_kernel(const float* __restrict__ logZ, const float* __restrict__ score,
                  float* __restrict__ out) {
    int tid = threadIdx.x;
    float v = (tid < BB) ? (logZ[tid] - score[tid]) : 0.f;
    #pragma unroll
    for (int o = 16; o > 0; o >>= 1) v += __shfl_down_sync(0xffffffffu, v, o);
    if (tid == 0) out[0] = v;
}

// ---------------- launch ----------------
extern "C" void kernel_launch(void* const* d_in, const int* in_sizes, int n_in,
                              void* d_out, int out_size) {
    const int*   ids     = (const int*)d_in[0];
    const int*   am      = (const int*)d_in[1];
    const int*   labels  = (const int*)d_in[2];
    const float* emb     = (const float*)d_in[3];
    const float* pos     = (const float*)d_in[4];
    const float* lng     = (const float*)d_in[5];
    const float* lnb     = (const float*)d_in[6];
    const float* Wqkv    = (const float*)d_in[7];
    const float* bqkv    = (const float*)d_in[8];
    const float* Wo      = (const float*)d_in[9];
    const float* bo      = (const float*)d_in[10];
    const float* ln1g    = (const float*)d_in[11];
    const float* ln1b    = (const float*)d_in[12];
    const float* W1      = (const float*)d_in[13];
    const float* b1      = (const float*)d_in[14];
    const float* W2      = (const float*)d_in[15];
    const float* b2      = (const float*)d_in[16];
    const float* ln2g    = (const float*)d_in[17];
    const float* ln2b    = (const float*)d_in[18];
    const float* Wcls    = (const float*)d_in[19];
    const float* bcls    = (const float*)d_in[20];
    const float* start_t = (const float*)d_in[21];
    const float* end_t   = (const float*)d_in[22];
    const float* trans   = (const float*)d_in[23];

    float *xp, *tmpp, *logitsp, *logZp, *scorep;
    __nv_bfloat16 *xbf, *qkvbf, *ctxbf, *ffnbf, *wqkvt, *wot, *w1t, *w2t;
    cudaGetSymbolAddress((void**)&xp, g_x);
    cudaGetSymbolAddress((void**)&tmpp, g_tmp);
    cudaGetSymbolAddress((void**)&logitsp, g_logits);
    cudaGetSymbolAddress((void**)&logZp, g_logZ);
    cudaGetSymbolAddress((void**)&scorep, g_score);
    cudaGetSymbolAddress((void**)&xbf, g_x_bf);
    cudaGetSymbolAddress((void**)&qkvbf, g_qkv_bf);
    cudaGetSymbolAddress((void**)&ctxbf, g_ctx_bf);
    cudaGetSymbolAddress((void**)&ffnbf, g_ffn_bf);
    cudaGetSymbolAddress((void**)&wqkvt, g_Wqkv_t);
    cudaGetSymbolAddress((void**)&wot, g_Wo_t);
    cudaGetSymbolAddress((void**)&w1t, g_W1_t);
    cudaGetSymbolAddress((void**)&w2t, g_W2_t);

    cudaFuncSetAttribute(mma_gemm_bf16_kernel,
                         cudaFuncAttributeMaxDynamicSharedMemorySize, GEMMB_SMEM);

    // weight conversion + transpose, batched across layers via gridDim.z
    wconv_kernel<<<dim3(D3 / 32, DD / 32, LL), dim3(32, 8)>>>(Wqkv, wqkvt, DD, D3);
    wconv_kernel<<<dim3(DD / 32, DD / 32, LL), dim3(32, 8)>>>(Wo, wot, DD, DD);
    wconv_kernel<<<dim3(FF / 32, DD / 32, LL), dim3(32, 8)>>>(W1, w1t, DD, FF);
    wconv_kernel<<<dim3(DD / 32, FF / 32, LL), dim3(32, 8)>>>(W2, w2t, FF, DD);

    embed_ln_kernel<<<TT, 256>>>(ids, emb, pos, lng, lnb, xp, xbf);

    for (int l = 0; l < LL; l++) {
        mma_gemm_bf16_kernel<<<dim3(D3 / 128, TT / 128), 256, GEMMB_SMEM>>>(
            xbf, wqkvt + (size_t)l * D3 * DD, bqkv + (size_t)l * D3,
            (float*)nullptr, qkvbf, TT, D3, DD, 0);
        flash_attn_kernel<<<dim3(SS / 64, BB * HH), 128>>>(qkvbf, am, ctxbf);
        mma_gemm_bf16_kernel<<<dim3(DD / 128, TT / 128), 256, GEMMB_SMEM>>>(
            ctxbf, wot + (size_t)l * DD * DD, bo + (size_t)l * DD,
            tmpp, (__nv_bfloat16*)nullptr, TT, DD, DD, 0);
        ln_residual_kernel<<<TT, 256>>>(xp, tmpp, ln1g + (size_t)l * DD, ln1b + (size_t)l * DD, xp, xbf);
        mma_gemm_bf16_kernel<<<dim3(FF / 128, TT / 128), 256, GEMMB_SMEM>>>(
            xbf, w1t + (size_t)l * FF * DD, b1 + (size_t)l * FF,
            (float*)nullptr, ffnbf, TT, FF, DD, 1);
        mma_gemm_bf16_kernel<<<dim3(DD / 128, TT / 128), 256, GEMMB_SMEM>>>(
            ffnbf, w2t + (size_t)l * DD * FF, b2 + (size_t)l * DD,
            tmpp, (__nv_bfloat16*)nullptr, TT, DD, FF, 0);
        ln_residual_kernel<<<TT, 256>>>(xp, tmpp, ln2g + (size_t)l * DD, ln2b + (size_t)l * DD, xp, xbf);
    }

    cls_kernel<<<TT, 288>>>(xp, Wcls, bcls, logitsp);
    crf_score_kernel<<<BB, 512>>>(labels, am, logitsp, start_t, end_t, trans, scorep);
    crf_forward_kernel<<<BB, 32>>>(logitsp, am, start_t, end_t, trans, logZp);
    final_kernel<<<1, 32>>>(logZp, scorep, (float*)d_out);
}

// round 12
// speedup vs baseline: 6.0072x; 1.0159x over previous
#include <cuda_runtime.h>
#include <cuda_bf16.h>
#include <math.h>
#include <stdint.h>
#include <stddef.h>

// Problem constants
#define BB 16
#define SS 512
#define DD 768
#define HH 12
#define LL 4
#define FF 3072
#define HDD 64
#define NK 9
#define TT (BB*SS)          // 8192 tokens
#define D3 (3*DD)           // 2304

// ---------------- scratch (static device globals) ----------------
__device__ float g_x[(size_t)TT*DD];
__device__ float g_logits[(size_t)TT*NK];
__device__ float g_logZ[BB];
__device__ float g_score[BB];

__device__ __nv_bfloat16 g_x_bf[(size_t)TT*DD];
__device__ __nv_bfloat16 g_tmp_bf[(size_t)TT*DD];
__device__ __nv_bfloat16 g_qkv_bf[(size_t)TT*D3];
__device__ __nv_bfloat16 g_ctx_bf[(size_t)TT*DD];
__device__ __nv_bfloat16 g_ffn_bf[(size_t)TT*FF];
__device__ __nv_bfloat16 g_Wqkv_t[(size_t)LL*D3*DD];   // [l][N=D3][K=DD]
__device__ __nv_bfloat16 g_Wo_t[(size_t)LL*DD*DD];
__device__ __nv_bfloat16 g_W1_t[(size_t)LL*FF*DD];
__device__ __nv_bfloat16 g_W2_t[(size_t)LL*DD*FF];

// ---------------- helpers ----------------
__device__ __forceinline__ float blk_reduce256(float v, float* sh) {
    int tid = threadIdx.x;
    sh[tid] = v; __syncthreads();
    #pragma unroll
    for (int s = 128; s > 0; s >>= 1) {
        if (tid < s) sh[tid] += sh[tid + s];
        __syncthreads();
    }
    float r = sh[0]; __syncthreads();
    return r;
}

__device__ __forceinline__ void cp_async16(void* smem, const void* gmem) {
    uint32_t s = (uint32_t)__cvta_generic_to_shared(smem);
    asm volatile("cp.async.cg.shared.global [%0], [%1], 16;\n" :: "r"(s), "l"(gmem));
}
#define CP_COMMIT() asm volatile("cp.async.commit_group;\n")
#define CP_WAIT(n)  asm volatile("cp.async.wait_group %0;\n" :: "n"(n))

#define MMA_BF16(acc, a0,a1,a2,a3, b0,b1) \
    asm volatile( \
        "mma.sync.aligned.m16n8k16.row.col.f32.bf16.bf16.f32 " \
        "{%0,%1,%2,%3}, {%4,%5,%6,%7}, {%8,%9}, {%0,%1,%2,%3};" \
        : "+f"(acc[0]), "+f"(acc[1]), "+f"(acc[2]), "+f"(acc[3]) \
        : "r"(a0), "r"(a1), "r"(a2), "r"(a3), "r"(b0), "r"(b1))

#define LDMX4(r0,r1,r2,r3, addr) \
    asm volatile("ldmatrix.sync.aligned.m8n8.x4.shared.b16 {%0,%1,%2,%3}, [%4];" \
        : "=r"(r0), "=r"(r1), "=r"(r2), "=r"(r3) : "r"(addr))

__device__ __forceinline__ float fast_tanh(float x) {
    float y;
    asm("tanh.approx.f32 %0, %1;" : "=f"(y) : "f"(x));
    return y;
}

// ---------------- weight convert + transpose: fp32 [K][N] -> bf16 [N][K], layer = blockIdx.z ----------------
__global__ void wconv_kernel(const float* __restrict__ W, __nv_bfloat16* __restrict__ Wt,
                             int K, int N) {
    W  += (size_t)blockIdx.z * K * N;
    Wt += (size_t)blockIdx.z * N * K;
    __shared__ float tile[32][33];
    int n0 = blockIdx.x * 32, k0 = blockIdx.y * 32;
    int tx = threadIdx.x, ty = threadIdx.y;
    #pragma unroll
    for (int j = ty; j < 32; j += 8)
        tile[j][tx] = W[(size_t)(k0 + j) * N + n0 + tx];
    __syncthreads();
    #pragma unroll
    for (int j = ty; j < 32; j += 8)
        Wt[(size_t)(n0 + j) * K + k0 + tx] = __float2bfloat16(tile[tx][j]);
}

// ---------------- embedding + LN (dual write fp32 + bf16) ----------------
__global__ void embed_ln_kernel(const int* __restrict__ ids, const float* __restrict__ emb,
                                const float* __restrict__ pos, const float* __restrict__ g,
                                const float* __restrict__ bta, float* __restrict__ out,
                                __nv_bfloat16* __restrict__ outb) {
    __shared__ float sh[256];
    int t = blockIdx.x, s = t % SS;
    int id = ids[t];
    const float* e = emb + (size_t)id * DD;
    const float* p = pos + (size_t)s * DD;
    float v[3]; float ls = 0.f, lq = 0.f;
    #pragma unroll
    for (int i = 0; i < 3; i++) {
        int d = threadIdx.x + i * 256;
        float w = e[d] + p[d];
        v[i] = w; ls += w; lq += w * w;
    }
    float sum = blk_reduce256(ls, sh);
    float sq  = blk_reduce256(lq, sh);
    float mean = sum * (1.0f / DD);
    float var  = sq * (1.0f / DD) - mean * mean;
    float rstd = rsqrtf(var + 1e-12f);
    float* o = out + (size_t)t * DD;
    __nv_bfloat16* ob = outb + (size_t)t * DD;
    #pragma unroll
    for (int i = 0; i < 3; i++) {
        int d = threadIdx.x + i * 256;
        float r = (v[i] - mean) * rstd * g[d] + bta[d];
        o[d] = r;
        ob[d] = __float2bfloat16(r);
    }
}

// out = LN(a + r) with r in bf16; writes fp32 + bf16
__global__ void ln_residual_kernel(const float* __restrict__ a, const __nv_bfloat16* __restrict__ r,
                                   const float* __restrict__ g, const float* __restrict__ bta,
                                   float* __restrict__ out, __nv_bfloat16* __restrict__ outb) {
    __shared__ float sh[256];
    int t = blockIdx.x;
    const float* ap = a + (size_t)t * DD;
    const __nv_bfloat16* rp = r + (size_t)t * DD;
    float v[3]; float ls = 0.f, lq = 0.f;
    #pragma unroll
    for (int i = 0; i < 3; i++) {
        int d = threadIdx.x + i * 256;
        float w = ap[d] + __bfloat162float(rp[d]);
        v[i] = w; ls += w; lq += w * w;
    }
    float sum = blk_reduce256(ls, sh);
    float sq  = blk_reduce256(lq, sh);
    float mean = sum * (1.0f / DD);
    float var  = sq * (1.0f / DD) - mean * mean;
    float rstd = rsqrtf(var + 1e-12f);
    float* o = out + (size_t)t * DD;
    __nv_bfloat16* ob = outb + (size_t)t * DD;
    #pragma unroll
    for (int i = 0; i < 3; i++) {
        int d = threadIdx.x + i * 256;
        float rr = (v[i] - mean) * rstd * g[d] + bta[d];
        o[d] = rr;
        ob[d] = __float2bfloat16(rr);
    }
}

// ---------------- BF16 tensor-core GEMM: ldmatrix frags + 3-stage cp.async (proven R9) ----------------
#define GEMM_STAGES 3
#define GEMMB_SMEM (GEMM_STAGES * 9216 * 4)
__global__ __launch_bounds__(256)
void mma_gemm_bf16_kernel(const __nv_bfloat16* __restrict__ A,
                          const __nv_bfloat16* __restrict__ Bt,
                          const float* __restrict__ bias,
                          float* __restrict__ Cf, __nv_bfloat16* __restrict__ Cb,
                          int M, int N, int Kd, int act) {
    extern __shared__ uint32_t dw[];

    const int tid  = threadIdx.x;
    const int warp = tid >> 5, lane = tid & 31;
    const int warpM = warp >> 2, warpN = warp & 3;
    const int g = lane >> 2, tg = lane & 3;
    const int rowBase = blockIdx.y * 128;
    const int colBase = blockIdx.x * 128;

    const int sub = lane >> 3, rr = lane & 7;
    const int rowA  = warpM * 64 + (sub & 1) * 8 + rr;
    const int koffA = (sub >> 1) * 8;
    const int rowB  = warpN * 32 + ((sub >> 1) & 1) * 8 + rr;
    const int koffB = (sub & 1) * 8;
    const uint32_t smem0 = (uint32_t)__cvta_generic_to_shared(dw);

    float acc[4][4][4];
    #pragma unroll
    for (int im = 0; im < 4; im++)
        #pragma unroll
        for (int in = 0; in < 4; in++)
            #pragma unroll
            for (int r = 0; r < 4; r++) acc[im][in][r] = 0.f;

    auto load_stage = [&](int k0, int s) {
        uint32_t* as = dw + s * 9216;
        uint32_t* bs = as + 4608;
        #pragma unroll
        for (int i = 0; i < 4; i++) {
            int idx = i * 256 + tid;
            int r = idx >> 3;
            int cw = (idx & 7) * 4;
            int ch = (idx & 7) * 8;
            cp_async16(as + r * 36 + cw, A  + (size_t)(rowBase + r) * Kd + k0 + ch);
            cp_async16(bs + r * 36 + cw, Bt + (size_t)(colBase + r) * Kd + k0 + ch);
        }
    };

    const int nK = Kd >> 6;
    load_stage(0, 0); CP_COMMIT();
    load_stage(64, 1); CP_COMMIT();
    int buf = 0;
    for (int kt = 0; kt < nK; kt++) {
        if (kt + 2 < nK) load_stage((kt + 2) << 6, (buf + 2) % 3);
        CP_COMMIT();
        CP_WAIT(2);
        __syncthreads();

        const uint32_t aBase = smem0 + (uint32_t)(buf * 9216) * 4;
        const uint32_t bBase = aBase + 4608 * 4;
        #pragma unroll
        for (int ks = 0; ks < 4; ks++) {
            uint32_t afr[4][4];
            #pragma unroll
            for (int im = 0; im < 4; im++) {
                uint32_t ad = aBase + (uint32_t)(((rowA + im * 16) * 72 + ks * 16 + koffA) * 2);
                LDMX4(afr[im][0], afr[im][1], afr[im][2], afr[im][3], ad);
            }
            uint32_t bq[2][4];
            #pragma unroll
            for (int inp = 0; inp < 2; inp++) {
                uint32_t bd = bBase + (uint32_t)(((rowB + inp * 16) * 72 + ks * 16 + koffB) * 2);
                LDMX4(bq[inp][0], bq[inp][1], bq[inp][2], bq[inp][3], bd);
            }
            #pragma unroll
            for (int im = 0; im < 4; im++)
                #pragma unroll
                for (int in = 0; in < 4; in++) {
                    if (in & 1)
                        MMA_BF16(acc[im][in], afr[im][0], afr[im][1], afr[im][2], afr[im][3],
                                 bq[in >> 1][2], bq[in >> 1][3]);
                    else
                        MMA_BF16(acc[im][in], afr[im][0], afr[im][1], afr[im][2], afr[im][3],
                                 bq[in >> 1][0], bq[in >> 1][1]);
                }
        }
        __syncthreads();
        buf = (buf + 1) % 3;
    }

    #pragma unroll
    for (int im = 0; im < 4; im++) {
        int row0 = rowBase + warpM * 64 + im * 16 + g;
        #pragma unroll
        for (int in = 0; in < 4; in++) {
            int col0 = colBase + warpN * 32 + in * 8 + tg * 2;
            float b0 = bias[col0], b1 = bias[col0 + 1];
            float v0 = acc[im][in][0] + b0;
            float v1 = acc[im][in][1] + b1;
            float v2 = acc[im][in][2] + b0;
            float v3 = acc[im][in][3] + b1;
            if (act) {
                float u, cc;
                u = v0; cc = 0.7978845608028654f * (u + 0.044715f * u * u * u); v0 = 0.5f * u * (1.0f + fast_tanh(cc));
                u = v1; cc = 0.7978845608028654f * (u + 0.044715f * u * u * u); v1 = 0.5f * u * (1.0f + fast_tanh(cc));
                u = v2; cc = 0.7978845608028654f * (u + 0.044715f * u * u * u); v2 = 0.5f * u * (1.0f + fast_tanh(cc));
                u = v3; cc = 0.7978845608028654f * (u + 0.044715f * u * u * u); v3 = 0.5f * u * (1.0f + fast_tanh(cc));
            }
            if (Cf) {
                Cf[(size_t)row0 * N + col0]           = v0;
                Cf[(size_t)row0 * N + col0 + 1]       = v1;
                Cf[(size_t)(row0 + 8) * N + col0]     = v2;
                Cf[(size_t)(row0 + 8) * N + col0 + 1] = v3;
            }
            if (Cb) {
                *(__nv_bfloat162*)(Cb + (size_t)row0 * N + col0)       = __floats2bfloat162_rn(v0, v1);
                *(__nv_bfloat162*)(Cb + (size_t)(row0 + 8) * N + col0) = __floats2bfloat162_rn(v2, v3);
            }
        }
    }
}

// ---------------- fused flash attention (bf16 mma, online softmax, ldmatrix frags) ----------------
__global__ __launch_bounds__(128)
void flash_attn_kernel(const __nv_bfloat16* __restrict__ qkvb, const int* __restrict__ amask,
                       __nv_bfloat16* __restrict__ ctxb) {
    __shared__ uint32_t Qs[64 * 36];
    __shared__ uint32_t Ks[2][64 * 36];
    __shared__ uint32_t Vs[2][64 * 36];
    __shared__ float bias_s[SS];

    const int bh = blockIdx.y;
    const int b = bh / HH, h = bh % HH;
    const int q0 = blockIdx.x * 64;
    const int tid = threadIdx.x;
    const int warp = tid >> 5, lane = tid & 31;
    const int g = lane >> 2, tg = lane & 3;
    const int sub = lane >> 3, rr8 = lane & 7;

    const __nv_bfloat16* Qg = qkvb + (size_t)(b * SS + q0) * D3 + h * HDD;
    const __nv_bfloat16* Kg = qkvb + (size_t)(b * SS) * D3 + DD + h * HDD;
    const __nv_bfloat16* Vg = qkvb + (size_t)(b * SS) * D3 + 2 * DD + h * HDD;

    const uint32_t qbase = (uint32_t)__cvta_generic_to_shared(Qs);
    const uint32_t kbase0 = (uint32_t)__cvta_generic_to_shared(Ks[0]);
    const uint32_t vbase0 = (uint32_t)__cvta_generic_to_shared(Vs[0]);

    const int rowQa  = warp * 16 + (sub & 1) * 8 + rr8;
    const int koffQa = (sub >> 1) * 8;
    const int rowKb  = ((sub >> 1) & 1) * 8 + rr8;
    const int koffKb = (sub & 1) * 8;

    #pragma unroll
    for (int i = 0; i < 4; i++) {
        int c = i * 128 + tid;
        bias_s[c] = (1.0f - (float)amask[b * SS + c]) * -1e9f;
    }
    #pragma unroll
    for (int i = 0; i < 4; i++) {
        int idx = i * 128 + tid;
        int row = idx >> 3, ch = idx & 7;
        cp_async16(Qs + row * 36 + ch * 4,    Qg + (size_t)row * D3 + ch * 8);
        cp_async16(Ks[0] + row * 36 + ch * 4, Kg + (size_t)row * D3 + ch * 8);
        cp_async16(Vs[0] + row * 36 + ch * 4, Vg + (size_t)row * D3 + ch * 8);
    }
    CP_COMMIT();

    float m0 = -INFINITY, m1 = -INFINITY, l0 = 0.f, l1 = 0.f;
    float o[8][4];
    #pragma unroll
    for (int j = 0; j < 8; j++)
        #pragma unroll
        for (int r = 0; r < 4; r++) o[j][r] = 0.f;

    const int mat = lane >> 3, r8 = lane & 7;
    int buf = 0;
    for (int kt = 0; kt < 8; kt++) {
        if (kt < 7) {
            #pragma unroll
            for (int i = 0; i < 4; i++) {
                int idx = i * 128 + tid;
                int row = idx >> 3, ch = idx & 7;
                int grow = (kt + 1) * 64 + row;
                cp_async16(Ks[buf ^ 1] + row * 36 + ch * 4, Kg + (size_t)grow * D3 + ch * 8);
                cp_async16(Vs[buf ^ 1] + row * 36 + ch * 4, Vg + (size_t)grow * D3 + ch * 8);
            }
            CP_COMMIT();
            CP_WAIT(1);
        } else {
            CP_WAIT(0);
        }
        __syncthreads();

        float s[8][4];
        #pragma unroll
        for (int j = 0; j < 8; j++)
            #pragma unroll
            for (int r = 0; r < 4; r++) s[j][r] = 0.f;
        const uint32_t kbase = kbase0 + (uint32_t)(buf * 64 * 36 * 4);
        #pragma unroll
        for (int ks = 0; ks < 4; ks++) {
            uint32_t a0, a1, a2, a3;
            uint32_t qa = qbase + (uint32_t)((rowQa * 72 + ks * 16 + koffQa) * 2);
            LDMX4(a0, a1, a2, a3, qa);
            #pragma unroll
            for (int jp = 0; jp < 4; jp++) {
                uint32_t b0, b1, b2, b3;
                uint32_t kd = kbase + (uint32_t)(((rowKb + jp * 16) * 72 + ks * 16 + koffKb) * 2);
                LDMX4(b0, b1, b2, b3, kd);
                MMA_BF16(s[2 * jp],     a0, a1, a2, a3, b0, b1);
                MMA_BF16(s[2 * jp + 1], a0, a1, a2, a3, b2, b3);
            }
        }

        float mx0 = -INFINITY, mx1 = -INFINITY;
        #pragma unroll
        for (int j = 0; j < 8; j++) {
            float bi0 = bias_s[kt * 64 + j * 8 + 2 * tg];
            float bi1 = bias_s[kt * 64 + j * 8 + 2 * tg + 1];
            s[j][0] = s[j][0] * 0.125f + bi0;
            s[j][1] = s[j][1] * 0.125f + bi1;
            s[j][2] = s[j][2] * 0.125f + bi0;
            s[j][3] = s[j][3] * 0.125f + bi1;
            mx0 = fmaxf(mx0, fmaxf(s[j][0], s[j][1]));
            mx1 = fmaxf(mx1, fmaxf(s[j][2], s[j][3]));
        }
        mx0 = fmaxf(mx0, __shfl_xor_sync(0xffffffffu, mx0, 1));
        mx0 = fmaxf(mx0, __shfl_xor_sync(0xffffffffu, mx0, 2));
        mx1 = fmaxf(mx1, __shfl_xor_sync(0xffffffffu, mx1, 1));
        mx1 = fmaxf(mx1, __shfl_xor_sync(0xffffffffu, mx1, 2));

        float mn0 = fmaxf(m0, mx0), mn1 = fmaxf(m1, mx1);
        float al0 = __expf(m0 - mn0), al1 = __expf(m1 - mn1);
        float sum0 = 0.f, sum1 = 0.f;
        uint32_t pl[8], ph[8];
        #pragma unroll
        for (int j = 0; j < 8; j++) {
            float p0 = __expf(s[j][0] - mn0), p1 = __expf(s[j][1] - mn0);
            float p2 = __expf(s[j][2] - mn1), p3 = __expf(s[j][3] - mn1);
            sum0 += p0 + p1; sum1 += p2 + p3;
            __nv_bfloat162 t0 = __floats2bfloat162_rn(p0, p1);
            __nv_bfloat162 t1 = __floats2bfloat162_rn(p2, p3);
            pl[j] = *(uint32_t*)&t0;
            ph[j] = *(uint32_t*)&t1;
        }
        sum0 += __shfl_xor_sync(0xffffffffu, sum0, 1);
        sum0 += __shfl_xor_sync(0xffffffffu, sum0, 2);
        sum1 += __shfl_xor_sync(0xffffffffu, sum1, 1);
        sum1 += __shfl_xor_sync(0xffffffffu, sum1, 2);
        l0 = l0 * al0 + sum0; l1 = l1 * al1 + sum1;
        m0 = mn0; m1 = mn1;
        #pragma unroll
        for (int j = 0; j < 8; j++) {
            o[j][0] *= al0; o[j][1] *= al0; o[j][2] *= al1; o[j][3] *= al1;
        }

        uint32_t vbase = vbase0 + (uint32_t)(buf * 64 * 36 * 4);
        #pragma unroll
        for (int ks = 0; ks < 4; ks++) {
            uint32_t a0 = pl[2 * ks], a1 = ph[2 * ks], a2 = pl[2 * ks + 1], a3 = ph[2 * ks + 1];
            #pragma unroll
            for (int jj = 0; jj < 4; jj++) {
                int rowv = ks * 16 + (mat & 1) * 8 + r8;
                int colh = jj * 16 + (mat >> 1) * 8;
                uint32_t addr = vbase + (uint32_t)(rowv * 144 + colh * 2);
                uint32_t r0, r1, r2, r3;
                asm volatile("ldmatrix.sync.aligned.m8n8.x4.trans.shared.b16 {%0,%1,%2,%3}, [%4];"
                             : "=r"(r0), "=r"(r1), "=r"(r2), "=r"(r3) : "r"(addr));
                MMA_BF16(o[2 * jj],     a0, a1, a2, a3, r0, r1);
                MMA_BF16(o[2 * jj + 1], a0, a1, a2, a3, r2, r3);
            }
        }
        __syncthreads();
        buf ^= 1;
    }

    float inv0 = 1.f / l0, inv1 = 1.f / l1;
    int rowg = b * SS + q0 + warp * 16 + g;
    __nv_bfloat16* dst0 = ctxb + (size_t)rowg * DD + h * HDD;
    __nv_bfloat16* dst1 = dst0 + (size_t)8 * DD;
    #pragma unroll
    for (int j = 0; j < 8; j++) {
        *(__nv_bfloat162*)(dst0 + j * 8 + 2 * tg) = __floats2bfloat162_rn(o[j][0] * inv0, o[j][1] * inv0);
        *(__nv_bfloat162*)(dst1 + j * 8 + 2 * tg) = __floats2bfloat162_rn(o[j][2] * inv1, o[j][3] * inv1);
    }
}

// ---------------- classifier (bf16 activations) ----------------
__global__ __launch_bounds__(288)
void cls_kernel(const __nv_bfloat16* __restrict__ x, const float* __restrict__ W,
                const float* __restrict__ bias, float* __restrict__ logits) {
    int t = blockIdx.x;
    int w = threadIdx.x >> 5;
    int lane = threadIdx.x & 31;
    const __nv_bfloat16* xp = x + (size_t)t * DD;
    float s = 0.f;
    for (int d = lane; d < DD; d += 32) s += __bfloat162float(xp[d]) * W[(size_t)d * NK + w];
    #pragma unroll
    for (int o = 16; o > 0; o >>= 1) s += __shfl_down_sync(0xffffffffu, s, o);
    if (lane == 0) logits[(size_t)t * NK + w] = s + bias[w];
}

// ---------------- CRF gold-path score ----------------
__global__ __launch_bounds__(512)
void crf_score_kernel(const int* __restrict__ labels, const int* __restrict__ amask,
                      const float* __restrict__ logits, const float* __restrict__ start_t,
                      const float* __restrict__ end_t, const float* __restrict__ trans,
                      float* __restrict__ score) {
    __shared__ float sf[512];
    __shared__ int si[512];
    int b = blockIdx.x;
    int t = threadIdx.x;
    const int* lab = labels + b * SS;
    const int* m = amask + b * SS;
    const float* lg = logits + (size_t)b * SS * NK;
    float em = lg[t * NK + lab[t]];
    float contrib = (t == 0) ? em : (float)m[t] * (trans[lab[t - 1] * NK + lab[t]] + em);
    sf[t] = contrib; si[t] = m[t];
    __syncthreads();
    #pragma unroll
    for (int s = 256; s > 0; s >>= 1) {
        if (t < s) { sf[t] += sf[t + s]; si[t] += si[t + s]; }
        __syncthreads();
    }
    if (t == 0) {
        int last = si[0] - 1;
        score[b] = sf[0] + start_t[lab[0]] + end_t[lab[last]];
    }
}

// ---------------- CRF forward (logZ) ----------------
__global__ __launch_bounds__(32)
void crf_forward_kernel(const float* __restrict__ logits, const int* __restrict__ amask,
                        const float* __restrict__ start_t, const float* __restrict__ end_t,
                        const float* __restrict__ trans, float* __restrict__ logZ) {
    __shared__ float lg[SS * NK];
    __shared__ float tr[NK * NK];
    __shared__ float alpha[2][NK];
    int b = blockIdx.x;
    int tid = threadIdx.x;
    const float* src = logits + (size_t)b * SS * NK;
    for (int i = tid; i < SS * NK; i += 32) lg[i] = src[i];
    for (int i = tid; i < NK * NK; i += 32) tr[i] = trans[i];
    if (tid < NK) alpha[0][tid] = start_t[tid] + lg[tid];
    __syncwarp();
    int cur = 0;
    for (int t = 1; t < SS; t++) {
        if (tid < NK) {
            int j = tid;
            float mx = -INFINITY;
            #pragma unroll
            for (int i = 0; i < NK; i++) mx = fmaxf(mx, alpha[cur][i] + tr[i * NK + j]);
            float s = 0.f;
            #pragma unroll
            for (int i = 0; i < NK; i++) s += expf(alpha[cur][i] + tr[i * NK + j] - mx);
            float cand = mx + logf(s) + lg[t * NK + j];
            alpha[cur ^ 1][j] = (amask[b * SS + t] > 0) ? cand : alpha[cur][j];
        }
        __syncwarp();
        cur ^= 1;
    }
    if (tid == 0) {
        float mx = -INFINITY;
        #pragma unroll
        for (int i = 0; i < NK; i++) mx = fmaxf(mx, alpha[cur][i] + end_t[i]);
        float s = 0.f;
        #pragma unroll
        for (int i = 0; i < NK; i++) s += expf(alpha[cur][i] + end_t[i] - mx);
        logZ[b] = mx + logf(s);
    }
}

// ---------------- final reduction ----------------
__global__ __launch_bounds__(32)
void final_kernel(const float* __restrict__ logZ, const float* __restrict__ score,
                  float* __restrict__ out) {
    int tid = threadIdx.x;
    float v = (tid < BB) ? (logZ[tid] - score[tid]) : 0.f;
    #pragma unroll
    for (int o = 16; o > 0; o >>= 1) v += __shfl_down_sync(0xffffffffu, v, o);
    if (tid == 0) out[0] = v;
}

// ---------------- launch ----------------
extern "C" void kernel_launch(void* const* d_in, const int* in_sizes, int n_in,
                              void* d_out, int out_size) {
    const int*   ids     = (const int*)d_in[0];
    const int*   am      = (const int*)d_in[1];
    const int*   labels  = (const int*)d_in[2];
    const float* emb     = (const float*)d_in[3];
    const float* pos     = (const float*)d_in[4];
    const float* lng     = (const float*)d_in[5];
    const float* lnb     = (const float*)d_in[6];
    const float* Wqkv    = (const float*)d_in[7];
    const float* bqkv    = (const float*)d_in[8];
    const float* Wo      = (const float*)d_in[9];
    const float* bo      = (const float*)d_in[10];
    const float* ln1g    = (const float*)d_in[11];
    const float* ln1b    = (const float*)d_in[12];
    const float* W1      = (const float*)d_in[13];
    const float* b1      = (const float*)d_in[14];
    const float* W2      = (const float*)d_in[15];
    const float* b2      = (const float*)d_in[16];
    const float* ln2g    = (const float*)d_in[17];
    const float* ln2b    = (const float*)d_in[18];
    const float* Wcls    = (const float*)d_in[19];
    const float* bcls    = (const float*)d_in[20];
    const float* start_t = (const float*)d_in[21];
    const float* end_t   = (const float*)d_in[22];
    const float* trans   = (const float*)d_in[23];

    float *xp, *logitsp, *logZp, *scorep;
    __nv_bfloat16 *xbf, *tmpbf, *qkvbf, *ctxbf, *ffnbf, *wqkvt, *wot, *w1t, *w2t;
    cudaGetSymbolAddress((void**)&xp, g_x);
    cudaGetSymbolAddress((void**)&logitsp, g_logits);
    cudaGetSymbolAddress((void**)&logZp, g_logZ);
    cudaGetSymbolAddress((void**)&scorep, g_score);
    cudaGetSymbolAddress((void**)&xbf, g_x_bf);
    cudaGetSymbolAddress((void**)&tmpbf, g_tmp_bf);
    cudaGetSymbolAddress((void**)&qkvbf, g_qkv_bf);
    cudaGetSymbolAddress((void**)&ctxbf, g_ctx_bf);
    cudaGetSymbolAddress((void**)&ffnbf, g_ffn_bf);
    cudaGetSymbolAddress((void**)&wqkvt, g_Wqkv_t);
    cudaGetSymbolAddress((void**)&wot, g_Wo_t);
    cudaGetSymbolAddress((void**)&w1t, g_W1_t);
    cudaGetSymbolAddress((void**)&w2t, g_W2_t);

    cudaFuncSetAttribute(mma_gemm_bf16_kernel,
                         cudaFuncAttributeMaxDynamicSharedMemorySize, GEMMB_SMEM);

    // weight conversion + transpose, batched across layers via gridDim.z
    wconv_kernel<<<dim3(D3 / 32, DD / 32, LL), dim3(32, 8)>>>(Wqkv, wqkvt, DD, D3);
    wconv_kernel<<<dim3(DD / 32, DD / 32, LL), dim3(32, 8)>>>(Wo, wot, DD, DD);
    wconv_kernel<<<dim3(FF / 32, DD / 32, LL), dim3(32, 8)>>>(W1, w1t, DD, FF);
    wconv_kernel<<<dim3(DD / 32, FF / 32, LL), dim3(32, 8)>>>(W2, w2t, FF, DD);

    embed_ln_kernel<<<TT, 256>>>(ids, emb, pos, lng, lnb, xp, xbf);

    for (int l = 0; l < LL; l++) {
        mma_gemm_bf16_kernel<<<dim3(D3 / 128, TT / 128), 256, GEMMB_SMEM>>>(
            xbf, wqkvt + (size_t)l * D3 * DD, bqkv + (size_t)l * D3,
            (float*)nullptr, qkvbf, TT, D3, DD, 0);
        flash_attn_kernel<<<dim3(SS / 64, BB * HH), 128>>>(qkvbf, am, ctxbf);
        mma_gemm_bf16_kernel<<<dim3(DD / 128, TT / 128), 256, GEMMB_SMEM>>>(
            ctxbf, wot + (size_t)l * DD * DD, bo + (size_t)l * DD,
            (float*)nullptr, tmpbf, TT, DD, DD, 0);
        ln_residual_kernel<<<TT, 256>>>(xp, tmpbf, ln1g + (size_t)l * DD, ln1b + (size_t)l * DD, xp, xbf);
        mma_gemm_bf16_kernel<<<dim3(FF / 128, TT / 128), 256, GEMMB_SMEM>>>(
            xbf, w1t + (size_t)l * FF * DD, b1 + (size_t)l * FF,
            (float*)nullptr, ffnbf, TT, FF, DD, 1);
        mma_gemm_bf16_kernel<<<dim3(DD / 128, TT / 128), 256, GEMMB_SMEM>>>(
            ffnbf, w2t + (size_t)l * DD * FF, b2 + (size_t)l * DD,
            (float*)nullptr, tmpbf, TT, DD, FF, 0);
        ln_residual_kernel<<<TT, 256>>>(xp, tmpbf, ln2g + (size_t)l * DD, ln2b + (size_t)l * DD, xp, xbf);
    }

    cls_kernel<<<TT, 288>>>(xbf, Wcls, bcls, logitsp);
    crf_score_kernel<<<BB, 512>>>(labels, am, logitsp, start_t, end_t, trans, scorep);
    crf_forward_kernel<<<BB, 32>>>(logitsp, am, start_t, end_t, trans, logZp);
    final_kernel<<<1, 32>>>(logZp, scorep, (float*)d_out);
}

// round 13
// speedup vs baseline: 6.0525x; 1.0075x over previous
#include <cuda_runtime.h>
#include <cuda_bf16.h>
#include <math.h>
#include <stdint.h>
#include <stddef.h>

// Problem constants
#define BB 16
#define SS 512
#define DD 768
#define HH 12
#define LL 4
#define FF 3072
#define HDD 64
#define NK 9
#define TT (BB*SS)          // 8192 tokens
#define D3 (3*DD)           // 2304

// ---------------- scratch (static device globals) ----------------
__device__ float g_x[(size_t)TT*DD];
__device__ float g_logits[(size_t)TT*NK];
__device__ float g_logZ[BB];
__device__ float g_score[BB];

__device__ __nv_bfloat16 g_x_bf[(size_t)TT*DD];
__device__ __nv_bfloat16 g_tmp_bf[(size_t)TT*DD];
__device__ __nv_bfloat16 g_qkv_bf[(size_t)TT*D3];
__device__ __nv_bfloat16 g_ctx_bf[(size_t)TT*DD];
__device__ __nv_bfloat16 g_ffn_bf[(size_t)TT*FF];
__device__ __nv_bfloat16 g_Wqkv_t[(size_t)LL*D3*DD];   // [l][N=D3][K=DD]
__device__ __nv_bfloat16 g_Wo_t[(size_t)LL*DD*DD];
__device__ __nv_bfloat16 g_W1_t[(size_t)LL*FF*DD];
__device__ __nv_bfloat16 g_W2_t[(size_t)LL*DD*FF];

// ---------------- helpers ----------------
__device__ __forceinline__ float blk_reduce256(float v, float* sh) {
    int tid = threadIdx.x;
    sh[tid] = v; __syncthreads();
    #pragma unroll
    for (int s = 128; s > 0; s >>= 1) {
        if (tid < s) sh[tid] += sh[tid + s];
        __syncthreads();
    }
    float r = sh[0]; __syncthreads();
    return r;
}

__device__ __forceinline__ void cp_async16(void* smem, const void* gmem) {
    uint32_t s = (uint32_t)__cvta_generic_to_shared(smem);
    asm volatile("cp.async.cg.shared.global [%0], [%1], 16;\n" :: "r"(s), "l"(gmem));
}
#define CP_COMMIT() asm volatile("cp.async.commit_group;\n")
#define CP_WAIT(n)  asm volatile("cp.async.wait_group %0;\n" :: "n"(n))

#define MMA_BF16(acc, a0,a1,a2,a3, b0,b1) \
    asm volatile( \
        "mma.sync.aligned.m16n8k16.row.col.f32.bf16.bf16.f32 " \
        "{%0,%1,%2,%3}, {%4,%5,%6,%7}, {%8,%9}, {%0,%1,%2,%3};" \
        : "+f"(acc[0]), "+f"(acc[1]), "+f"(acc[2]), "+f"(acc[3]) \
        : "r"(a0), "r"(a1), "r"(a2), "r"(a3), "r"(b0), "r"(b1))

#define LDMX4(r0,r1,r2,r3, addr) \
    asm volatile("ldmatrix.sync.aligned.m8n8.x4.shared.b16 {%0,%1,%2,%3}, [%4];" \
        : "=r"(r0), "=r"(r1), "=r"(r2), "=r"(r3) : "r"(addr))

__device__ __forceinline__ float fast_tanh(float x) {
    float y;
    asm("tanh.approx.f32 %0, %1;" : "=f"(y) : "f"(x));
    return y;
}

// ---------------- weight convert + transpose: fp32 [K][N] -> bf16 [N][K] ----------------
// Each block: 32 k-rows x 128 n-cols. layer = blockIdx.z.
__global__ void wconv_kernel(const float* __restrict__ W, __nv_bfloat16* __restrict__ Wt,
                             int K, int N) {
    W  += (size_t)blockIdx.z * K * N;
    Wt += (size_t)blockIdx.z * N * K;
    __shared__ float tile[32][133];   // stride 133 mod 32 = 5 -> conflict-free col reads
    int n0 = blockIdx.x * 128, k0 = blockIdx.y * 32;
    int tx = threadIdx.x, ty = threadIdx.y;
    #pragma unroll
    for (int j = ty; j < 32; j += 8) {
        const float* src = W + (size_t)(k0 + j) * N + n0;
        #pragma unroll
        for (int c = 0; c < 4; c++)
            tile[j][tx + 32 * c] = src[tx + 32 * c];
    }
    __syncthreads();
    #pragma unroll
    for (int jn = ty; jn < 128; jn += 8)
        Wt[(size_t)(n0 + jn) * K + k0 + tx] = __float2bfloat16(tile[tx][jn]);
}

// ---------------- embedding + LN (dual write fp32 + bf16) ----------------
__global__ void embed_ln_kernel(const int* __restrict__ ids, const float* __restrict__ emb,
                                const float* __restrict__ pos, const float* __restrict__ g,
                                const float* __restrict__ bta, float* __restrict__ out,
                                __nv_bfloat16* __restrict__ outb) {
    __shared__ float sh[256];
    int t = blockIdx.x, s = t % SS;
    int id = ids[t];
    const float* e = emb + (size_t)id * DD;
    const float* p = pos + (size_t)s * DD;
    float v[3]; float ls = 0.f, lq = 0.f;
    #pragma unroll
    for (int i = 0; i < 3; i++) {
        int d = threadIdx.x + i * 256;
        float w = e[d] + p[d];
        v[i] = w; ls += w; lq += w * w;
    }
    float sum = blk_reduce256(ls, sh);
    float sq  = blk_reduce256(lq, sh);
    float mean = sum * (1.0f / DD);
    float var  = sq * (1.0f / DD) - mean * mean;
    float rstd = rsqrtf(var + 1e-12f);
    float* o = out + (size_t)t * DD;
    __nv_bfloat16* ob = outb + (size_t)t * DD;
    #pragma unroll
    for (int i = 0; i < 3; i++) {
        int d = threadIdx.x + i * 256;
        float r = (v[i] - mean) * rstd * g[d] + bta[d];
        o[d] = r;
        ob[d] = __float2bfloat16(r);
    }
}

// out = LN(a + r) with r in bf16; writes fp32 + bf16
__global__ void ln_residual_kernel(const float* __restrict__ a, const __nv_bfloat16* __restrict__ r,
                                   const float* __restrict__ g, const float* __restrict__ bta,
                                   float* __restrict__ out, __nv_bfloat16* __restrict__ outb) {
    __shared__ float sh[256];
    int t = blockIdx.x;
    const float* ap = a + (size_t)t * DD;
    const __nv_bfloat16* rp = r + (size_t)t * DD;
    float v[3]; float ls = 0.f, lq = 0.f;
    #pragma unroll
    for (int i = 0; i < 3; i++) {
        int d = threadIdx.x + i * 256;
        float w = ap[d] + __bfloat162float(rp[d]);
        v[i] = w; ls += w; lq += w * w;
    }
    float sum = blk_reduce256(ls, sh);
    float sq  = blk_reduce256(lq, sh);
    float mean = sum * (1.0f / DD);
    float var  = sq * (1.0f / DD) - mean * mean;
    float rstd = rsqrtf(var + 1e-12f);
    float* o = out + (size_t)t * DD;
    __nv_bfloat16* ob = outb + (size_t)t * DD;
    #pragma unroll
    for (int i = 0; i < 3; i++) {
        int d = threadIdx.x + i * 256;
        float rr = (v[i] - mean) * rstd * g[d] + bta[d];
        o[d] = rr;
        ob[d] = __float2bfloat16(rr);
    }
}

// ---------------- BF16 tensor-core GEMM: ldmatrix frags + 3-stage cp.async (proven R9) ----------------
#define GEMM_STAGES 3
#define GEMMB_SMEM (GEMM_STAGES * 9216 * 4)
__global__ __launch_bounds__(256)
void mma_gemm_bf16_kernel(const __nv_bfloat16* __restrict__ A,
                          const __nv_bfloat16* __restrict__ Bt,
                          const float* __restrict__ bias,
                          float* __restrict__ Cf, __nv_bfloat16* __restrict__ Cb,
                          int M, int N, int Kd, int act) {
    extern __shared__ uint32_t dw[];

    const int tid  = threadIdx.x;
    const int warp = tid >> 5, lane = tid & 31;
    const int warpM = warp >> 2, warpN = warp & 3;
    const int g = lane >> 2, tg = lane & 3;
    const int rowBase = blockIdx.y * 128;
    const int colBase = blockIdx.x * 128;

    const int sub = lane >> 3, rr = lane & 7;
    const int rowA  = warpM * 64 + (sub & 1) * 8 + rr;
    const int koffA = (sub >> 1) * 8;
    const int rowB  = warpN * 32 + ((sub >> 1) & 1) * 8 + rr;
    const int koffB = (sub & 1) * 8;
    const uint32_t smem0 = (uint32_t)__cvta_generic_to_shared(dw);

    float acc[4][4][4];
    #pragma unroll
    for (int im = 0; im < 4; im++)
        #pragma unroll
        for (int in = 0; in < 4; in++)
            #pragma unroll
            for (int r = 0; r < 4; r++) acc[im][in][r] = 0.f;

    auto load_stage = [&](int k0, int s) {
        uint32_t* as = dw + s * 9216;
        uint32_t* bs = as + 4608;
        #pragma unroll
        for (int i = 0; i < 4; i++) {
            int idx = i * 256 + tid;
            int r = idx >> 3;
            int cw = (idx & 7) * 4;
            int ch = (idx & 7) * 8;
            cp_async16(as + r * 36 + cw, A  + (size_t)(rowBase + r) * Kd + k0 + ch);
            cp_async16(bs + r * 36 + cw, Bt + (size_t)(colBase + r) * Kd + k0 + ch);
        }
    };

    const int nK = Kd >> 6;
    load_stage(0, 0); CP_COMMIT();
    load_stage(64, 1); CP_COMMIT();
    int buf = 0;
    for (int kt = 0; kt < nK; kt++) {
        if (kt + 2 < nK) load_stage((kt + 2) << 6, (buf + 2) % 3);
        CP_COMMIT();
        CP_WAIT(2);
        __syncthreads();

        const uint32_t aBase = smem0 + (uint32_t)(buf * 9216) * 4;
        const uint32_t bBase = aBase + 4608 * 4;
        #pragma unroll
        for (int ks = 0; ks < 4; ks++) {
            uint32_t afr[4][4];
            #pragma unroll
            for (int im = 0; im < 4; im++) {
                uint32_t ad = aBase + (uint32_t)(((rowA + im * 16) * 72 + ks * 16 + koffA) * 2);
                LDMX4(afr[im][0], afr[im][1], afr[im][2], afr[im][3], ad);
            }
            uint32_t bq[2][4];
            #pragma unroll
            for (int inp = 0; inp < 2; inp++) {
                uint32_t bd = bBase + (uint32_t)(((rowB + inp * 16) * 72 + ks * 16 + koffB) * 2);
                LDMX4(bq[inp][0], bq[inp][1], bq[inp][2], bq[inp][3], bd);
            }
            #pragma unroll
            for (int im = 0; im < 4; im++)
                #pragma unroll
                for (int in = 0; in < 4; in++) {
                    if (in & 1)
                        MMA_BF16(acc[im][in], afr[im][0], afr[im][1], afr[im][2], afr[im][3],
                                 bq[in >> 1][2], bq[in >> 1][3]);
                    else
                        MMA_BF16(acc[im][in], afr[im][0], afr[im][1], afr[im][2], afr[im][3],
                                 bq[in >> 1][0], bq[in >> 1][1]);
                }
        }
        __syncthreads();
        buf = (buf + 1) % 3;
    }

    #pragma unroll
    for (int im = 0; im < 4; im++) {
        int row0 = rowBase + warpM * 64 + im * 16 + g;
        #pragma unroll
        for (int in = 0; in < 4; in++) {
            int col0 = colBase + warpN * 32 + in * 8 + tg * 2;
            float b0 = bias[col0], b1 = bias[col0 + 1];
            float v0 = acc[im][in][0] + b0;
            float v1 = acc[im][in][1] + b1;
            float v2 = acc[im][in][2] + b0;
            float v3 = acc[im][in][3] + b1;
            if (act) {
                float u, cc;
                u = v0; cc = 0.7978845608028654f * (u + 0.044715f * u * u * u); v0 = 0.5f * u * (1.0f + fast_tanh(cc));
                u = v1; cc = 0.7978845608028654f * (u + 0.044715f * u * u * u); v1 = 0.5f * u * (1.0f + fast_tanh(cc));
                u = v2; cc = 0.7978845608028654f * (u + 0.044715f * u * u * u); v2 = 0.5f * u * (1.0f + fast_tanh(cc));
                u = v3; cc = 0.7978845608028654f * (u + 0.044715f * u * u * u); v3 = 0.5f * u * (1.0f + fast_tanh(cc));
            }
            if (Cf) {
                Cf[(size_t)row0 * N + col0]           = v0;
                Cf[(size_t)row0 * N + col0 + 1]       = v1;
                Cf[(size_t)(row0 + 8) * N + col0]     = v2;
                Cf[(size_t)(row0 + 8) * N + col0 + 1] = v3;
            }
            if (Cb) {
                *(__nv_bfloat162*)(Cb + (size_t)row0 * N + col0)       = __floats2bfloat162_rn(v0, v1);
                *(__nv_bfloat162*)(Cb + (size_t)(row0 + 8) * N + col0) = __floats2bfloat162_rn(v2, v3);
            }
        }
    }
}

// ---------------- fused flash attention: 128 q-rows per block, 8 warps ----------------
// Dynamic smem (words): Qs[0..4608) 128x36 | Ks 4608+buf*2304 | Vs 9216+buf*2304 | bias @13824
#define FLASH_SMEM (14336 * 4)
__global__ __launch_bounds__(256)
void flash_attn_kernel(const __nv_bfloat16* __restrict__ qkvb, const int* __restrict__ amask,
                       __nv_bfloat16* __restrict__ ctxb) {
    extern __shared__ uint32_t dyn[];
    uint32_t* Qs = dyn;
    float* bias_s = (float*)(dyn + 13824);

    const int bh = blockIdx.y;
    const int b = bh / HH, h = bh % HH;
    const int q0 = blockIdx.x * 128;
    const int tid = threadIdx.x;
    const int warp = tid >> 5, lane = tid & 31;
    const int g = lane >> 2, tg = lane & 3;
    const int sub = lane >> 3, rr8 = lane & 7;

    const __nv_bfloat16* Qg = qkvb + (size_t)(b * SS + q0) * D3 + h * HDD;
    const __nv_bfloat16* Kg = qkvb + (size_t)(b * SS) * D3 + DD + h * HDD;
    const __nv_bfloat16* Vg = qkvb + (size_t)(b * SS) * D3 + 2 * DD + h * HDD;

    const uint32_t dbase = (uint32_t)__cvta_generic_to_shared(dyn);
    const uint32_t qbase = dbase;
    const uint32_t kbase0 = dbase + 4608 * 4;
    const uint32_t vbase0 = dbase + 9216 * 4;

    const int rowQa  = warp * 16 + (sub & 1) * 8 + rr8;
    const int koffQa = (sub >> 1) * 8;
    const int rowKb  = ((sub >> 1) & 1) * 8 + rr8;
    const int koffKb = (sub & 1) * 8;

    #pragma unroll
    for (int i = 0; i < 2; i++) {
        int c = i * 256 + tid;
        bias_s[c] = (1.0f - (float)amask[b * SS + c]) * -1e9f;
    }
    // Q: 128 rows x 8 chunks = 1024 / 256 thr = 4 iters
    #pragma unroll
    for (int i = 0; i < 4; i++) {
        int idx = i * 256 + tid;
        int row = idx >> 3, ch = idx & 7;
        cp_async16(Qs + row * 36 + ch * 4, Qg + (size_t)row * D3 + ch * 8);
    }
    // K/V tile 0: 64 rows x 8 chunks = 512 / 256 = 2 iters
    #pragma unroll
    for (int i = 0; i < 2; i++) {
        int idx = i * 256 + tid;
        int row = idx >> 3, ch = idx & 7;
        cp_async16(dyn + 4608 + row * 36 + ch * 4, Kg + (size_t)row * D3 + ch * 8);
        cp_async16(dyn + 9216 + row * 36 + ch * 4, Vg + (size_t)row * D3 + ch * 8);
    }
    CP_COMMIT();

    float m0 = -INFINITY, m1 = -INFINITY, l0 = 0.f, l1 = 0.f;
    float o[8][4];
    #pragma unroll
    for (int j = 0; j < 8; j++)
        #pragma unroll
        for (int r = 0; r < 4; r++) o[j][r] = 0.f;

    const int mat = lane >> 3, r8 = lane & 7;
    int buf = 0;
    for (int kt = 0; kt < 8; kt++) {
        if (kt < 7) {
            #pragma unroll
            for (int i = 0; i < 2; i++) {
                int idx = i * 256 + tid;
                int row = idx >> 3, ch = idx & 7;
                int grow = (kt + 1) * 64 + row;
                cp_async16(dyn + 4608 + (buf ^ 1) * 2304 + row * 36 + ch * 4, Kg + (size_t)grow * D3 + ch * 8);
                cp_async16(dyn + 9216 + (buf ^ 1) * 2304 + row * 36 + ch * 4, Vg + (size_t)grow * D3 + ch * 8);
            }
            CP_COMMIT();
            CP_WAIT(1);
        } else {
            CP_WAIT(0);
        }
        __syncthreads();

        float s[8][4];
        #pragma unroll
        for (int j = 0; j < 8; j++)
            #pragma unroll
            for (int r = 0; r < 4; r++) s[j][r] = 0.f;
        const uint32_t kbase = kbase0 + (uint32_t)(buf * 2304 * 4);
        #pragma unroll
        for (int ks = 0; ks < 4; ks++) {
            uint32_t a0, a1, a2, a3;
            uint32_t qa = qbase + (uint32_t)((rowQa * 72 + ks * 16 + koffQa) * 2);
            LDMX4(a0, a1, a2, a3, qa);
            #pragma unroll
            for (int jp = 0; jp < 4; jp++) {
                uint32_t b0, b1, b2, b3;
                uint32_t kd = kbase + (uint32_t)(((rowKb + jp * 16) * 72 + ks * 16 + koffKb) * 2);
                LDMX4(b0, b1, b2, b3, kd);
                MMA_BF16(s[2 * jp],     a0, a1, a2, a3, b0, b1);
                MMA_BF16(s[2 * jp + 1], a0, a1, a2, a3, b2, b3);
            }
        }

        float mx0 = -INFINITY, mx1 = -INFINITY;
        #pragma unroll
        for (int j = 0; j < 8; j++) {
            float bi0 = bias_s[kt * 64 + j * 8 + 2 * tg];
            float bi1 = bias_s[kt * 64 + j * 8 + 2 * tg + 1];
            s[j][0] = s[j][0] * 0.125f + bi0;
            s[j][1] = s[j][1] * 0.125f + bi1;
            s[j][2] = s[j][2] * 0.125f + bi0;
            s[j][3] = s[j][3] * 0.125f + bi1;
            mx0 = fmaxf(mx0, fmaxf(s[j][0], s[j][1]));
            mx1 = fmaxf(mx1, fmaxf(s[j][2], s[j][3]));
        }
        mx0 = fmaxf(mx0, __shfl_xor_sync(0xffffffffu, mx0, 1));
        mx0 = fmaxf(mx0, __shfl_xor_sync(0xffffffffu, mx0, 2));
        mx1 = fmaxf(mx1, __shfl_xor_sync(0xffffffffu, mx1, 1));
        mx1 = fmaxf(mx1, __shfl_xor_sync(0xffffffffu, mx1, 2));

        float mn0 = fmaxf(m0, mx0), mn1 = fmaxf(m1, mx1);
        float al0 = __expf(m0 - mn0), al1 = __expf(m1 - mn1);
        float sum0 = 0.f, sum1 = 0.f;
        uint32_t pl[8], ph[8];
        #pragma unroll
        for (int j = 0; j < 8; j++) {
            float p0 = __expf(s[j][0] - mn0), p1 = __expf(s[j][1] - mn0);
            float p2 = __expf(s[j][2] - mn1), p3 = __expf(s[j][3] - mn1);
            sum0 += p0 + p1; sum1 += p2 + p3;
            __nv_bfloat162 t0 = __floats2bfloat162_rn(p0, p1);
            __nv_bfloat162 t1 = __floats2bfloat162_rn(p2, p3);
            pl[j] = *(uint32_t*)&t0;
            ph[j] = *(uint32_t*)&t1;
        }
        sum0 += __shfl_xor_sync(0xffffffffu, sum0, 1);
        sum0 += __shfl_xor_sync(0xffffffffu, sum0, 2);
        sum1 += __shfl_xor_sync(0xffffffffu, sum1, 1);
        sum1 += __shfl_xor_sync(0xffffffffu, sum1, 2);
        l0 = l0 * al0 + sum0; l1 = l1 * al1 + sum1;
        m0 = mn0; m1 = mn1;
        #pragma unroll
        for (int j = 0; j < 8; j++) {
            o[j][0] *= al0; o[j][1] *= al0; o[j][2] *= al1; o[j][3] *= al1;
        }

        uint32_t vbase = vbase0 + (uint32_t)(buf * 2304 * 4);
        #pragma unroll
        for (int ks = 0; ks < 4; ks++) {
            uint32_t a0 = pl[2 * ks], a1 = ph[2 * ks], a2 = pl[2 * ks + 1], a3 = ph[2 * ks + 1];
            #pragma unroll
            for (int jj = 0; jj < 4; jj++) {
                int rowv = ks * 16 + (mat & 1) * 8 + r8;
                int colh = jj * 16 + (mat >> 1) * 8;
                uint32_t addr = vbase + (uint32_t)(rowv * 144 + colh * 2);
                uint32_t r0, r1, r2, r3;
                asm volatile("ldmatrix.sync.aligned.m8n8.x4.trans.shared.b16 {%0,%1,%2,%3}, [%4];"
                             : "=r"(r0), "=r"(r1), "=r"(r2), "=r"(r3) : "r"(addr));
                MMA_BF16(o[2 * jj],     a0, a1, a2, a3, r0, r1);
                MMA_BF16(o[2 * jj + 1], a0, a1, a2, a3, r2, r3);
            }
        }
        __syncthreads();
        buf ^= 1;
    }

    float inv0 = 1.f / l0, inv1 = 1.f / l1;
    int rowg = b * SS + q0 + warp * 16 + g;
    __nv_bfloat16* dst0 = ctxb + (size_t)rowg * DD + h * HDD;
    __nv_bfloat16* dst1 = dst0 + (size_t)8 * DD;
    #pragma unroll
    for (int j = 0; j < 8; j++) {
        *(__nv_bfloat162*)(dst0 + j * 8 + 2 * tg) = __floats2bfloat162_rn(o[j][0] * inv0, o[j][1] * inv0);
        *(__nv_bfloat162*)(dst1 + j * 8 + 2 * tg) = __floats2bfloat162_rn(o[j][2] * inv1, o[j][3] * inv1);
    }
}

// ---------------- classifier (bf16 activations) ----------------
__global__ __launch_bounds__(288)
void cls_kernel(const __nv_bfloat16* __restrict__ x, const float* __restrict__ W,
                const float* __restrict__ bias, float* __restrict__ logits) {
    int t = blockIdx.x;
    int w = threadIdx.x >> 5;
    int lane = threadIdx.x & 31;
    const __nv_bfloat16* xp = x + (size_t)t * DD;
    float s = 0.f;
    for (int d = lane; d < DD; d += 32) s += __bfloat162float(xp[d]) * W[(size_t)d * NK + w];
    #pragma unroll
    for (int o = 16; o > 0; o >>= 1) s += __shfl_down_sync(0xffffffffu, s, o);
    if (lane == 0) logits[(size_t)t * NK + w] = s + bias[w];
}

// ---------------- CRF gold-path score ----------------
__global__ __launch_bounds__(512)
void crf_score_kernel(const int* __restrict__ labels, const int* __restrict__ amask,
                      const float* __restrict__ logits, const float* __restrict__ start_t,
                      const float* __restrict__ end_t, const float* __restrict__ trans,
                      float* __restrict__ score) {
    __shared__ float sf[512];
    __shared__ int si[512];
    int b = blockIdx.x;
    int t = threadIdx.x;
    const int* lab = labels + b * SS;
    const int* m = amask + b * SS;
    const float* lg = logits + (size_t)b * SS * NK;
    float em = lg[t * NK + lab[t]];
    float contrib = (t == 0) ? em : (float)m[t] * (trans[lab[t - 1] * NK + lab[t]] + em);
    sf[t] = contrib; si[t] = m[t];
    __syncthreads();
    #pragma unroll
    for (int s = 256; s > 0; s >>= 1) {
        if (t < s) { sf[t] += sf[t + s]; si[t] += si[t + s]; }
        __syncthreads();
    }
    if (t == 0) {
        int last = si[0] - 1;
        score[b] = sf[0] + start_t[lab[0]] + end_t[lab[last]];
    }
}

// ---------------- CRF forward (logZ) ----------------
__global__ __launch_bounds__(32)
void crf_forward_kernel(const float* __restrict__ logits, const int* __restrict__ amask,
                        const float* __restrict__ start_t, const float* __restrict__ end_t,
                        const float* __restrict__ trans, float* __restrict__ logZ) {
    __shared__ float lg[SS * NK];
    __shared__ float tr[NK * NK];
    __shared__ float alpha[2][NK];
    int b = blockIdx.x;
    int tid = threadIdx.x;
    const float* src = logits + (size_t)b * SS * NK;
    for (int i = tid; i < SS * NK; i += 32) lg[i] = src[i];
    for (int i = tid; i < NK * NK; i += 32) tr[i] = trans[i];
    if (tid < NK) alpha[0][tid] = start_t[tid] + lg[tid];
    __syncwarp();
    int cur = 0;
    for (int t = 1; t < SS; t++) {
        if (tid < NK) {
            int j = tid;
            float mx = -INFINITY;
            #pragma unroll
            for (int i = 0; i < NK; i++) mx = fmaxf(mx, alpha[cur][i] + tr[i * NK + j]);
            float s = 0.f;
            #pragma unroll
            for (int i = 0; i < NK; i++) s += __expf(alpha[cur][i] + tr[i * NK + j] - mx);
            float cand = mx + __logf(s) + lg[t * NK + j];
            alpha[cur ^ 1][j] = (amask[b * SS + t] > 0) ? cand : alpha[cur][j];
        }
        __syncwarp();
        cur ^= 1;
    }
    if (tid == 0) {
        float mx = -INFINITY;
        #pragma unroll
        for (int i = 0; i < NK; i++) mx = fmaxf(mx, alpha[cur][i] + end_t[i]);
        float s = 0.f;
        #pragma unroll
        for (int i = 0; i < NK; i++) s += __expf(alpha[cur][i] + end_t[i] - mx);
        logZ[b] = mx + __logf(s);
    }
}

// ---------------- final reduction ----------------
__global__ __launch_bounds__(32)
void final_kernel(const float* __restrict__ logZ, const float* __restrict__ score,
                  float* __restrict__ out) {
    int tid = threadIdx.x;
    float v = (tid < BB) ? (logZ[tid] - score[tid]) : 0.f;
    #pragma unroll
    for (int o = 16; o > 0; o >>= 1) v += __shfl_down_sync(0xffffffffu, v, o);
    if (tid == 0) out[0] = v;
}

// ---------------- launch ----------------
extern "C" void kernel_launch(void* const* d_in, const int* in_sizes, int n_in,
                              void* d_out, int out_size) {
    const int*   ids     = (const int*)d_in[0];
    const int*   am      = (const int*)d_in[1];
    const int*   labels  = (const int*)d_in[2];
    const float* emb     = (const float*)d_in[3];
    const float* pos     = (const float*)d_in[4];
    const float* lng     = (const float*)d_in[5];
    const float* lnb     = (const float*)d_in[6];
    const float* Wqkv    = (const float*)d_in[7];
    const float* bqkv    = (const float*)d_in[8];
    const float* Wo      = (const float*)d_in[9];
    const float* bo      = (const float*)d_in[10];
    const float* ln1g    = (const float*)d_in[11];
    const float* ln1b    = (const float*)d_in[12];
    const float* W1      = (const float*)d_in[13];
    const float* b1      = (const float*)d_in[14];
    const float* W2      = (const float*)d_in[15];
    const float* b2      = (const float*)d_in[16];
    const float* ln2g    = (const float*)d_in[17];
    const float* ln2b    = (const float*)d_in[18];
    const float* Wcls    = (const float*)d_in[19];
    const float* bcls    = (const float*)d_in[20];
    const float* start_t = (const float*)d_in[21];
    const float* end_t   = (const float*)d_in[22];
    const float* trans   = (const float*)d_in[23];

    float *xp, *logitsp, *logZp, *scorep;
    __nv_bfloat16 *xbf, *tmpbf, *qkvbf, *ctxbf, *ffnbf, *wqkvt, *wot, *w1t, *w2t;
    cudaGetSymbolAddress((void**)&xp, g_x);
    cudaGetSymbolAddress((void**)&logitsp, g_logits);
    cudaGetSymbolAddress((void**)&logZp, g_logZ);
    cudaGetSymbolAddress((void**)&scorep, g_score);
    cudaGetSymbolAddress((void**)&xbf, g_x_bf);
    cudaGetSymbolAddress((void**)&tmpbf, g_tmp_bf);
    cudaGetSymbolAddress((void**)&qkvbf, g_qkv_bf);
    cudaGetSymbolAddress((void**)&ctxbf, g_ctx_bf);
    cudaGetSymbolAddress((void**)&ffnbf, g_ffn_bf);
    cudaGetSymbolAddress((void**)&wqkvt, g_Wqkv_t);
    cudaGetSymbolAddress((void**)&wot, g_Wo_t);
    cudaGetSymbolAddress((void**)&w1t, g_W1_t);
    cudaGetSymbolAddress((void**)&w2t, g_W2_t);

    cudaFuncSetAttribute(mma_gemm_bf16_kernel,
                         cudaFuncAttributeMaxDynamicSharedMemorySize, GEMMB_SMEM);
    cudaFuncSetAttribute(flash_attn_kernel,
                         cudaFuncAttributeMaxDynamicSharedMemorySize, FLASH_SMEM);

    // weight conversion + transpose, batched across layers via gridDim.z
    wconv_kernel<<<dim3(D3 / 128, DD / 32, LL), dim3(32, 8)>>>(Wqkv, wqkvt, DD, D3);
    wconv_kernel<<<dim3(DD / 128, DD / 32, LL), dim3(32, 8)>>>(Wo, wot, DD, DD);
    wconv_kernel<<<dim3(FF / 128, DD / 32, LL), dim3(32, 8)>>>(W1, w1t, DD, FF);
    wconv_kernel<<<dim3(DD / 128, FF / 32, LL), dim3(32, 8)>>>(W2, w2t, FF, DD);

    embed_ln_kernel<<<TT, 256>>>(ids, emb, pos, lng, lnb, xp, xbf);

    for (int l = 0; l < LL; l++) {
        mma_gemm_bf16_kernel<<<dim3(D3 / 128, TT / 128), 256, GEMMB_SMEM>>>(
            xbf, wqkvt + (size_t)l * D3 * DD, bqkv + (size_t)l * D3,
            (float*)nullptr, qkvbf, TT, D3, DD, 0);
        flash_attn_kernel<<<dim3(SS / 128, BB * HH), 256, FLASH_SMEM>>>(qkvbf, am, ctxbf);
        mma_gemm_bf16_kernel<<<dim3(DD / 128, TT / 128), 256, GEMMB_SMEM>>>(
            ctxbf, wot + (size_t)l * DD * DD, bo + (size_t)l * DD,
            (float*)nullptr, tmpbf, TT, DD, DD, 0);
        ln_residual_kernel<<<TT, 256>>>(xp, tmpbf, ln1g + (size_t)l * DD, ln1b + (size_t)l * DD, xp, xbf);
        mma_gemm_bf16_kernel<<<dim3(FF / 128, TT / 128), 256, GEMMB_SMEM>>>(
            xbf, w1t + (size_t)l * FF * DD, b1 + (size_t)l * FF,
            (float*)nullptr, ffnbf, TT, FF, DD, 1);
        mma_gemm_bf16_kernel<<<dim3(DD / 128, TT / 128), 256, GEMMB_SMEM>>>(
            ffnbf, w2t + (size_t)l * DD * FF, b2 + (size_t)l * DD,
            (float*)nullptr, tmpbf, TT, DD, FF, 0);
        ln_residual_kernel<<<TT, 256>>>(xp, tmpbf, ln2g + (size_t)l * DD, ln2b + (size_t)l * DD, xp, xbf);
    }

    cls_kernel<<<TT, 288>>>(xbf, Wcls, bcls, logitsp);
    crf_score_kernel<<<BB, 512>>>(labels, am, logitsp, start_t, end_t, trans, scorep);
    crf_forward_kernel<<<BB, 32>>>(logitsp, am, start_t, end_t, trans, logZp);
    final_kernel<<<1, 32>>>(logZp, scorep, (float*)d_out);
}

// round 14
// speedup vs baseline: 6.0775x; 1.0041x over previous
#include <cuda_runtime.h>
#include <cuda_bf16.h>
#include <math.h>
#include <stdint.h>
#include <stddef.h>

// Problem constants
#define BB 16
#define SS 512
#define DD 768
#define HH 12
#define LL 4
#define FF 3072
#define HDD 64
#define NK 9
#define TT (BB*SS)          // 8192 tokens
#define D3 (3*DD)           // 2304

// ---------------- scratch (static device globals) ----------------
__device__ float g_logits[(size_t)TT*NK];
__device__ float g_logZ[BB];
__device__ float g_score[BB];

__device__ __nv_bfloat16 g_x_bf[(size_t)TT*DD];
__device__ __nv_bfloat16 g_tmp_bf[(size_t)TT*DD];
__device__ __nv_bfloat16 g_qkv_bf[(size_t)TT*D3];
__device__ __nv_bfloat16 g_ctx_bf[(size_t)TT*DD];
__device__ __nv_bfloat16 g_ffn_bf[(size_t)TT*FF];
__device__ __nv_bfloat16 g_Wqkv_t[(size_t)LL*D3*DD];   // [l][N=D3][K=DD]
__device__ __nv_bfloat16 g_Wo_t[(size_t)LL*DD*DD];
__device__ __nv_bfloat16 g_W1_t[(size_t)LL*FF*DD];
__device__ __nv_bfloat16 g_W2_t[(size_t)LL*DD*FF];

// ---------------- helpers ----------------
__device__ __forceinline__ float blk_reduce256(float v, float* sh) {
    int tid = threadIdx.x;
    sh[tid] = v; __syncthreads();
    #pragma unroll
    for (int s = 128; s > 0; s >>= 1) {
        if (tid < s) sh[tid] += sh[tid + s];
        __syncthreads();
    }
    float r = sh[0]; __syncthreads();
    return r;
}

__device__ __forceinline__ void cp_async16(void* smem, const void* gmem) {
    uint32_t s = (uint32_t)__cvta_generic_to_shared(smem);
    asm volatile("cp.async.cg.shared.global [%0], [%1], 16;\n" :: "r"(s), "l"(gmem));
}
#define CP_COMMIT() asm volatile("cp.async.commit_group;\n")
#define CP_WAIT(n)  asm volatile("cp.async.wait_group %0;\n" :: "n"(n))

#define MMA_BF16(acc, a0,a1,a2,a3, b0,b1) \
    asm volatile( \
        "mma.sync.aligned.m16n8k16.row.col.f32.bf16.bf16.f32 " \
        "{%0,%1,%2,%3}, {%4,%5,%6,%7}, {%8,%9}, {%0,%1,%2,%3};" \
        : "+f"(acc[0]), "+f"(acc[1]), "+f"(acc[2]), "+f"(acc[3]) \
        : "r"(a0), "r"(a1), "r"(a2), "r"(a3), "r"(b0), "r"(b1))

#define LDMX4(r0,r1,r2,r3, addr) \
    asm volatile("ldmatrix.sync.aligned.m8n8.x4.shared.b16 {%0,%1,%2,%3}, [%4];" \
        : "=r"(r0), "=r"(r1), "=r"(r2), "=r"(r3) : "r"(addr))

__device__ __forceinline__ float fast_tanh(float x) {
    float y;
    asm("tanh.approx.f32 %0, %1;" : "=f"(y) : "f"(x));
    return y;
}

// ---------------- weight convert + transpose: fp32 [K][N] -> bf16 [N][K] ----------------
// Each block: 32 k-rows x 128 n-cols. layer = blockIdx.z.
__global__ void wconv_kernel(const float* __restrict__ W, __nv_bfloat16* __restrict__ Wt,
                             int K, int N) {
    W  += (size_t)blockIdx.z * K * N;
    Wt += (size_t)blockIdx.z * N * K;
    __shared__ float tile[32][133];   // stride 133 mod 32 = 5 -> conflict-free col reads
    int n0 = blockIdx.x * 128, k0 = blockIdx.y * 32;
    int tx = threadIdx.x, ty = threadIdx.y;
    #pragma unroll
    for (int j = ty; j < 32; j += 8) {
        const float* src = W + (size_t)(k0 + j) * N + n0;
        #pragma unroll
        for (int c = 0; c < 4; c++)
            tile[j][tx + 32 * c] = src[tx + 32 * c];
    }
    __syncthreads();
    #pragma unroll
    for (int jn = ty; jn < 128; jn += 8)
        Wt[(size_t)(n0 + jn) * K + k0 + tx] = __float2bfloat16(tile[tx][jn]);
}

// ---------------- embedding + LN (bf16 out) ----------------
__global__ void embed_ln_kernel(const int* __restrict__ ids, const float* __restrict__ emb,
                                const float* __restrict__ pos, const float* __restrict__ g,
                                const float* __restrict__ bta,
                                __nv_bfloat16* __restrict__ outb) {
    __shared__ float sh[256];
    int t = blockIdx.x, s = t % SS;
    int id = ids[t];
    const float* e = emb + (size_t)id * DD;
    const float* p = pos + (size_t)s * DD;
    float v[3]; float ls = 0.f, lq = 0.f;
    #pragma unroll
    for (int i = 0; i < 3; i++) {
        int d = threadIdx.x + i * 256;
        float w = e[d] + p[d];
        v[i] = w; ls += w; lq += w * w;
    }
    float sum = blk_reduce256(ls, sh);
    float sq  = blk_reduce256(lq, sh);
    float mean = sum * (1.0f / DD);
    float var  = sq * (1.0f / DD) - mean * mean;
    float rstd = rsqrtf(var + 1e-12f);
    __nv_bfloat16* ob = outb + (size_t)t * DD;
    #pragma unroll
    for (int i = 0; i < 3; i++) {
        int d = threadIdx.x + i * 256;
        float r = (v[i] - mean) * rstd * g[d] + bta[d];
        ob[d] = __float2bfloat16(r);
    }
}

// out = LN(a + r), all bf16 (fp32 internal math); in-place on a is safe (block owns row)
__global__ void ln_residual_kernel(const __nv_bfloat16* __restrict__ a,
                                   const __nv_bfloat16* __restrict__ r,
                                   const float* __restrict__ g, const float* __restrict__ bta,
                                   __nv_bfloat16* __restrict__ outb) {
    __shared__ float sh[256];
    int t = blockIdx.x;
    const __nv_bfloat16* ap = a + (size_t)t * DD;
    const __nv_bfloat16* rp = r + (size_t)t * DD;
    float v[3]; float ls = 0.f, lq = 0.f;
    #pragma unroll
    for (int i = 0; i < 3; i++) {
        int d = threadIdx.x + i * 256;
        float w = __bfloat162float(ap[d]) + __bfloat162float(rp[d]);
        v[i] = w; ls += w; lq += w * w;
    }
    float sum = blk_reduce256(ls, sh);
    float sq  = blk_reduce256(lq, sh);
    float mean = sum * (1.0f / DD);
    float var  = sq * (1.0f / DD) - mean * mean;
    float rstd = rsqrtf(var + 1e-12f);
    __nv_bfloat16* ob = outb + (size_t)t * DD;
    #pragma unroll
    for (int i = 0; i < 3; i++) {
        int d = threadIdx.x + i * 256;
        float rr = (v[i] - mean) * rstd * g[d] + bta[d];
        ob[d] = __float2bfloat16(rr);
    }
}

// ---------------- BF16 tensor-core GEMM: ldmatrix frags + 3-stage cp.async (proven R9) ----------------
#define GEMM_STAGES 3
#define GEMMB_SMEM (GEMM_STAGES * 9216 * 4)
__global__ __launch_bounds__(256)
void mma_gemm_bf16_kernel(const __nv_bfloat16* __restrict__ A,
                          const __nv_bfloat16* __restrict__ Bt,
                          const float* __restrict__ bias,
                          float* __restrict__ Cf, __nv_bfloat16* __restrict__ Cb,
                          int M, int N, int Kd, int act) {
    extern __shared__ uint32_t dw[];

    const int tid  = threadIdx.x;
    const int warp = tid >> 5, lane = tid & 31;
    const int warpM = warp >> 2, warpN = warp & 3;
    const int g = lane >> 2, tg = lane & 3;
    const int rowBase = blockIdx.y * 128;
    const int colBase = blockIdx.x * 128;

    const int sub = lane >> 3, rr = lane & 7;
    const int rowA  = warpM * 64 + (sub & 1) * 8 + rr;
    const int koffA = (sub >> 1) * 8;
    const int rowB  = warpN * 32 + ((sub >> 1) & 1) * 8 + rr;
    const int koffB = (sub & 1) * 8;
    const uint32_t smem0 = (uint32_t)__cvta_generic_to_shared(dw);

    float acc[4][4][4];
    #pragma unroll
    for (int im = 0; im < 4; im++)
        #pragma unroll
        for (int in = 0; in < 4; in++)
            #pragma unroll
            for (int r = 0; r < 4; r++) acc[im][in][r] = 0.f;

    auto load_stage = [&](int k0, int s) {
        uint32_t* as = dw + s * 9216;
        uint32_t* bs = as + 4608;
        #pragma unroll
        for (int i = 0; i < 4; i++) {
            int idx = i * 256 + tid;
            int r = idx >> 3;
            int cw = (idx & 7) * 4;
            int ch = (idx & 7) * 8;
            cp_async16(as + r * 36 + cw, A  + (size_t)(rowBase + r) * Kd + k0 + ch);
            cp_async16(bs + r * 36 + cw, Bt + (size_t)(colBase + r) * Kd + k0 + ch);
        }
    };

    const int nK = Kd >> 6;
    load_stage(0, 0); CP_COMMIT();
    load_stage(64, 1); CP_COMMIT();
    int buf = 0;
    for (int kt = 0; kt < nK; kt++) {
        if (kt + 2 < nK) load_stage((kt + 2) << 6, (buf + 2) % 3);
        CP_COMMIT();
        CP_WAIT(2);
        __syncthreads();

        const uint32_t aBase = smem0 + (uint32_t)(buf * 9216) * 4;
        const uint32_t bBase = aBase + 4608 * 4;
        #pragma unroll
        for (int ks = 0; ks < 4; ks++) {
            uint32_t afr[4][4];
            #pragma unroll
            for (int im = 0; im < 4; im++) {
                uint32_t ad = aBase + (uint32_t)(((rowA + im * 16) * 72 + ks * 16 + koffA) * 2);
                LDMX4(afr[im][0], afr[im][1], afr[im][2], afr[im][3], ad);
            }
            uint32_t bq[2][4];
            #pragma unroll
            for (int inp = 0; inp < 2; inp++) {
                uint32_t bd = bBase + (uint32_t)(((rowB + inp * 16) * 72 + ks * 16 + koffB) * 2);
                LDMX4(bq[inp][0], bq[inp][1], bq[inp][2], bq[inp][3], bd);
            }
            #pragma unroll
            for (int im = 0; im < 4; im++)
                #pragma unroll
                for (int in = 0; in < 4; in++) {
                    if (in & 1)
                        MMA_BF16(acc[im][in], afr[im][0], afr[im][1], afr[im][2], afr[im][3],
                                 bq[in >> 1][2], bq[in >> 1][3]);
                    else
                        MMA_BF16(acc[im][in], afr[im][0], afr[im][1], afr[im][2], afr[im][3],
                                 bq[in >> 1][0], bq[in >> 1][1]);
                }
        }
        __syncthreads();
        buf = (buf + 1) % 3;
    }

    #pragma unroll
    for (int im = 0; im < 4; im++) {
        int row0 = rowBase + warpM * 64 + im * 16 + g;
        #pragma unroll
        for (int in = 0; in < 4; in++) {
            int col0 = colBase + warpN * 32 + in * 8 + tg * 2;
            float b0 = bias[col0], b1 = bias[col0 + 1];
            float v0 = acc[im][in][0] + b0;
            float v1 = acc[im][in][1] + b1;
            float v2 = acc[im][in][2] + b0;
            float v3 = acc[im][in][3] + b1;
            if (act) {
                float u, cc;
                u = v0; cc = 0.7978845608028654f * (u + 0.044715f * u * u * u); v0 = 0.5f * u * (1.0f + fast_tanh(cc));
                u = v1; cc = 0.7978845608028654f * (u + 0.044715f * u * u * u); v1 = 0.5f * u * (1.0f + fast_tanh(cc));
                u = v2; cc = 0.7978845608028654f * (u + 0.044715f * u * u * u); v2 = 0.5f * u * (1.0f + fast_tanh(cc));
                u = v3; cc = 0.7978845608028654f * (u + 0.044715f * u * u * u); v3 = 0.5f * u * (1.0f + fast_tanh(cc));
            }
            if (Cf) {
                Cf[(size_t)row0 * N + col0]           = v0;
                Cf[(size_t)row0 * N + col0 + 1]       = v1;
                Cf[(size_t)(row0 + 8) * N + col0]     = v2;
                Cf[(size_t)(row0 + 8) * N + col0 + 1] = v3;
            }
            if (Cb) {
                *(__nv_bfloat162*)(Cb + (size_t)row0 * N + col0)       = __floats2bfloat162_rn(v0, v1);
                *(__nv_bfloat162*)(Cb + (size_t)(row0 + 8) * N + col0) = __floats2bfloat162_rn(v2, v3);
            }
        }
    }
}

// ---------------- fused flash attention: 128 q-rows per block, 8 warps ----------------
// Dynamic smem (words): Qs[0..4608) 128x36 | Ks 4608+buf*2304 | Vs 9216+buf*2304 | bias @13824
#define FLASH_SMEM (14336 * 4)
__global__ __launch_bounds__(256)
void flash_attn_kernel(const __nv_bfloat16* __restrict__ qkvb, const int* __restrict__ amask,
                       __nv_bfloat16* __restrict__ ctxb) {
    extern __shared__ uint32_t dyn[];
    uint32_t* Qs = dyn;
    float* bias_s = (float*)(dyn + 13824);

    const int bh = blockIdx.y;
    const int b = bh / HH, h = bh % HH;
    const int q0 = blockIdx.x * 128;
    const int tid = threadIdx.x;
    const int warp = tid >> 5, lane = tid & 31;
    const int g = lane >> 2, tg = lane & 3;
    const int sub = lane >> 3, rr8 = lane & 7;

    const __nv_bfloat16* Qg = qkvb + (size_t)(b * SS + q0) * D3 + h * HDD;
    const __nv_bfloat16* Kg = qkvb + (size_t)(b * SS) * D3 + DD + h * HDD;
    const __nv_bfloat16* Vg = qkvb + (size_t)(b * SS) * D3 + 2 * DD + h * HDD;

    const uint32_t dbase = (uint32_t)__cvta_generic_to_shared(dyn);
    const uint32_t qbase = dbase;
    const uint32_t kbase0 = dbase + 4608 * 4;
    const uint32_t vbase0 = dbase + 9216 * 4;

    const int rowQa  = warp * 16 + (sub & 1) * 8 + rr8;
    const int koffQa = (sub >> 1) * 8;
    const int rowKb  = ((sub >> 1) & 1) * 8 + rr8;
    const int koffKb = (sub & 1) * 8;

    #pragma unroll
    for (int i = 0; i < 2; i++) {
        int c = i * 256 + tid;
        bias_s[c] = (1.0f - (float)amask[b * SS + c]) * -1e9f;
    }
    #pragma unroll
    for (int i = 0; i < 4; i++) {
        int idx = i * 256 + tid;
        int row = idx >> 3, ch = idx & 7;
        cp_async16(Qs + row * 36 + ch * 4, Qg + (size_t)row * D3 + ch * 8);
    }
    #pragma unroll
    for (int i = 0; i < 2; i++) {
        int idx = i * 256 + tid;
        int row = idx >> 3, ch = idx & 7;
        cp_async16(dyn + 4608 + row * 36 + ch * 4, Kg + (size_t)row * D3 + ch * 8);
        cp_async16(dyn + 9216 + row * 36 + ch * 4, Vg + (size_t)row * D3 + ch * 8);
    }
    CP_COMMIT();

    float m0 = -INFINITY, m1 = -INFINITY, l0 = 0.f, l1 = 0.f;
    float o[8][4];
    #pragma unroll
    for (int j = 0; j < 8; j++)
        #pragma unroll
        for (int r = 0; r < 4; r++) o[j][r] = 0.f;

    const int mat = lane >> 3, r8 = lane & 7;
    int buf = 0;
    for (int kt = 0; kt < 8; kt++) {
        if (kt < 7) {
            #pragma unroll
            for (int i = 0; i < 2; i++) {
                int idx = i * 256 + tid;
                int row = idx >> 3, ch = idx & 7;
                int grow = (kt + 1) * 64 + row;
                cp_async16(dyn + 4608 + (buf ^ 1) * 2304 + row * 36 + ch * 4, Kg + (size_t)grow * D3 + ch * 8);
                cp_async16(dyn + 9216 + (buf ^ 1) * 2304 + row * 36 + ch * 4, Vg + (size_t)grow * D3 + ch * 8);
            }
            CP_COMMIT();
            CP_WAIT(1);
        } else {
            CP_WAIT(0);
        }
        __syncthreads();

        float s[8][4];
        #pragma unroll
        for (int j = 0; j < 8; j++)
            #pragma unroll
            for (int r = 0; r < 4; r++) s[j][r] = 0.f;
        const uint32_t kbase = kbase0 + (uint32_t)(buf * 2304 * 4);
        #pragma unroll
        for (int ks = 0; ks < 4; ks++) {
            uint32_t a0, a1, a2, a3;
            uint32_t qa = qbase + (uint32_t)((rowQa * 72 + ks * 16 + koffQa) * 2);
            LDMX4(a0, a1, a2, a3, qa);
            #pragma unroll
            for (int jp = 0; jp < 4; jp++) {
                uint32_t b0, b1, b2, b3;
                uint32_t kd = kbase + (uint32_t)(((rowKb + jp * 16) * 72 + ks * 16 + koffKb) * 2);
                LDMX4(b0, b1, b2, b3, kd);
                MMA_BF16(s[2 * jp],     a0, a1, a2, a3, b0, b1);
                MMA_BF16(s[2 * jp + 1], a0, a1, a2, a3, b2, b3);
            }
        }

        float mx0 = -INFINITY, mx1 = -INFINITY;
        #pragma unroll
        for (int j = 0; j < 8; j++) {
            float bi0 = bias_s[kt * 64 + j * 8 + 2 * tg];
            float bi1 = bias_s[kt * 64 + j * 8 + 2 * tg + 1];
            s[j][0] = s[j][0] * 0.125f + bi0;
            s[j][1] = s[j][1] * 0.125f + bi1;
            s[j][2] = s[j][2] * 0.125f + bi0;
            s[j][3] = s[j][3] * 0.125f + bi1;
            mx0 = fmaxf(mx0, fmaxf(s[j][0], s[j][1]));
            mx1 = fmaxf(mx1, fmaxf(s[j][2], s[j][3]));
        }
        mx0 = fmaxf(mx0, __shfl_xor_sync(0xffffffffu, mx0, 1));
        mx0 = fmaxf(mx0, __shfl_xor_sync(0xffffffffu, mx0, 2));
        mx1 = fmaxf(mx1, __shfl_xor_sync(0xffffffffu, mx1, 1));
        mx1 = fmaxf(mx1, __shfl_xor_sync(0xffffffffu, mx1, 2));

        float mn0 = fmaxf(m0, mx0), mn1 = fmaxf(m1, mx1);
        float al0 = __expf(m0 - mn0), al1 = __expf(m1 - mn1);
        float sum0 = 0.f, sum1 = 0.f;
        uint32_t pl[8], ph[8];
        #pragma unroll
        for (int j = 0; j < 8; j++) {
            float p0 = __expf(s[j][0] - mn0), p1 = __expf(s[j][1] - mn0);
            float p2 = __expf(s[j][2] - mn1), p3 = __expf(s[j][3] - mn1);
            sum0 += p0 + p1; sum1 += p2 + p3;
            __nv_bfloat162 t0 = __floats2bfloat162_rn(p0, p1);
            __nv_bfloat162 t1 = __floats2bfloat162_rn(p2, p3);
            pl[j] = *(uint32_t*)&t0;
            ph[j] = *(uint32_t*)&t1;
        }
        sum0 += __shfl_xor_sync(0xffffffffu, sum0, 1);
        sum0 += __shfl_xor_sync(0xffffffffu, sum0, 2);
        sum1 += __shfl_xor_sync(0xffffffffu, sum1, 1);
        sum1 += __shfl_xor_sync(0xffffffffu, sum1, 2);
        l0 = l0 * al0 + sum0; l1 = l1 * al1 + sum1;
        m0 = mn0; m1 = mn1;
        #pragma unroll
        for (int j = 0; j < 8; j++) {
            o[j][0] *= al0; o[j][1] *= al0; o[j][2] *= al1; o[j][3] *= al1;
        }

        uint32_t vbase = vbase0 + (uint32_t)(buf * 2304 * 4);
        #pragma unroll
        for (int ks = 0; ks < 4; ks++) {
            uint32_t a0 = pl[2 * ks], a1 = ph[2 * ks], a2 = pl[2 * ks + 1], a3 = ph[2 * ks + 1];
            #pragma unroll
            for (int jj = 0; jj < 4; jj++) {
                int rowv = ks * 16 + (mat & 1) * 8 + r8;
                int colh = jj * 16 + (mat >> 1) * 8;
                uint32_t addr = vbase + (uint32_t)(rowv * 144 + colh * 2);
                uint32_t r0, r1, r2, r3;
                asm volatile("ldmatrix.sync.aligned.m8n8.x4.trans.shared.b16 {%0,%1,%2,%3}, [%4];"
                             : "=r"(r0), "=r"(r1), "=r"(r2), "=r"(r3) : "r"(addr));
                MMA_BF16(o[2 * jj],     a0, a1, a2, a3, r0, r1);
                MMA_BF16(o[2 * jj + 1], a0, a1, a2, a3, r2, r3);
            }
        }
        __syncthreads();
        buf ^= 1;
    }

    float inv0 = 1.f / l0, inv1 = 1.f / l1;
    int rowg = b * SS + q0 + warp * 16 + g;
    __nv_bfloat16* dst0 = ctxb + (size_t)rowg * DD + h * HDD;
    __nv_bfloat16* dst1 = dst0 + (size_t)8 * DD;
    #pragma unroll
    for (int j = 0; j < 8; j++) {
        *(__nv_bfloat162*)(dst0 + j * 8 + 2 * tg) = __floats2bfloat162_rn(o[j][0] * inv0, o[j][1] * inv0);
        *(__nv_bfloat162*)(dst1 + j * 8 + 2 * tg) = __floats2bfloat162_rn(o[j][2] * inv1, o[j][3] * inv1);
    }
}

// ---------------- classifier (bf16 activations) ----------------
__global__ __launch_bounds__(288)
void cls_kernel(const __nv_bfloat16* __restrict__ x, const float* __restrict__ W,
                const float* __restrict__ bias, float* __restrict__ logits) {
    int t = blockIdx.x;
    int w = threadIdx.x >> 5;
    int lane = threadIdx.x & 31;
    const __nv_bfloat16* xp = x + (size_t)t * DD;
    float s = 0.f;
    for (int d = lane; d < DD; d += 32) s += __bfloat162float(xp[d]) * W[(size_t)d * NK + w];
    #pragma unroll
    for (int o = 16; o > 0; o >>= 1) s += __shfl_down_sync(0xffffffffu, s, o);
    if (lane == 0) logits[(size_t)t * NK + w] = s + bias[w];
}

// ---------------- CRF gold-path score ----------------
__global__ __launch_bounds__(512)
void crf_score_kernel(const int* __restrict__ labels, const int* __restrict__ amask,
                      const float* __restrict__ logits, const float* __restrict__ start_t,
                      const float* __restrict__ end_t, const float* __restrict__ trans,
                      float* __restrict__ score) {
    __shared__ float sf[512];
    __shared__ int si[512];
    int b = blockIdx.x;
    int t = threadIdx.x;
    const int* lab = labels + b * SS;
    const int* m = amask + b * SS;
    const float* lg = logits + (size_t)b * SS * NK;
    float em = lg[t * NK + lab[t]];
    float contrib = (t == 0) ? em : (float)m[t] * (trans[lab[t - 1] * NK + lab[t]] + em);
    sf[t] = contrib; si[t] = m[t];
    __syncthreads();
    #pragma unroll
    for (int s = 256; s > 0; s >>= 1) {
        if (t < s) { sf[t] += sf[t + s]; si[t] += si[t + s]; }
        __syncthreads();
    }
    if (t == 0) {
        int last = si[0] - 1;
        score[b] = sf[0] + start_t[lab[0]] + end_t[lab[last]];
    }
}

// ---------------- CRF forward (logZ) ----------------
__global__ __launch_bounds__(32)
void crf_forward_kernel(const float* __restrict__ logits, const int* __restrict__ amask,
                        const float* __restrict__ start_t, const float* __restrict__ end_t,
                        const float* __restrict__ trans, float* __restrict__ logZ) {
    __shared__ float lg[SS * NK];
    __shared__ float tr[NK * NK];
    __shared__ float alpha[2][NK];
    int b = blockIdx.x;
    int tid = threadIdx.x;
    const float* src = logits + (size_t)b * SS * NK;
    for (int i = tid; i < SS * NK; i += 32) lg[i] = src[i];
    for (int i = tid; i < NK * NK; i += 32) tr[i] = trans[i];
    if (tid < NK) alpha[0][tid] = start_t[tid] + lg[tid];
    __syncwarp();
    int cur = 0;
    for (int t = 1; t < SS; t++) {
        if (tid < NK) {
            int j = tid;
            float mx = -INFINITY;
            #pragma unroll
            for (int i = 0; i < NK; i++) mx = fmaxf(mx, alpha[cur][i] + tr[i * NK + j]);
            float s = 0.f;
            #pragma unroll
            for (int i = 0; i < NK; i++) s += __expf(alpha[cur][i] + tr[i * NK + j] - mx);
            float cand = mx + __logf(s) + lg[t * NK + j];
            alpha[cur ^ 1][j] = (amask[b * SS + t] > 0) ? cand : alpha[cur][j];
        }
        __syncwarp();
        cur ^= 1;
    }
    if (tid == 0) {
        float mx = -INFINITY;
        #pragma unroll
        for (int i = 0; i < NK; i++) mx = fmaxf(mx, alpha[cur][i] + end_t[i]);
        float s = 0.f;
        #pragma unroll
        for (int i = 0; i < NK; i++) s += __expf(alpha[cur][i] + end_t[i] - mx);
        logZ[b] = mx + __logf(s);
    }
}

// ---------------- final reduction ----------------
__global__ __launch_bounds__(32)
void final_kernel(const float* __restrict__ logZ, const float* __restrict__ score,
                  float* __restrict__ out) {
    int tid = threadIdx.x;
    float v = (tid < BB) ? (logZ[tid] - score[tid]) : 0.f;
    #pragma unroll
    for (int o = 16; o > 0; o >>= 1) v += __shfl_down_sync(0xffffffffu, v, o);
    if (tid == 0) out[0] = v;
}

// ---------------- launch ----------------
extern "C" void kernel_launch(void* const* d_in, const int* in_sizes, int n_in,
                              void* d_out, int out_size) {
    const int*   ids     = (const int*)d_in[0];
    const int*   am      = (const int*)d_in[1];
    const int*   labels  = (const int*)d_in[2];
    const float* emb     = (const float*)d_in[3];
    const float* pos     = (const float*)d_in[4];
    const float* lng     = (const float*)d_in[5];
    const float* lnb     = (const float*)d_in[6];
    const float* Wqkv    = (const float*)d_in[7];
    const float* bqkv    = (const float*)d_in[8];
    const float* Wo      = (const float*)d_in[9];
    const float* bo      = (const float*)d_in[10];
    const float* ln1g    = (const float*)d_in[11];
    const float* ln1b    = (const float*)d_in[12];
    const float* W1      = (const float*)d_in[13];
    const float* b1      = (const float*)d_in[14];
    const float* W2      = (const float*)d_in[15];
    const float* b2      = (const float*)d_in[16];
    const float* ln2g    = (const float*)d_in[17];
    const float* ln2b    = (const float*)d_in[18];
    const float* Wcls    = (const float*)d_in[19];
    const float* bcls    = (const float*)d_in[20];
    const float* start_t = (const float*)d_in[21];
    const float* end_t   = (const float*)d_in[22];
    const float* trans   = (const float*)d_in[23];

    float *logitsp, *logZp, *scorep;
    __nv_bfloat16 *xbf, *tmpbf, *qkvbf, *ctxbf, *ffnbf, *wqkvt, *wot, *w1t, *w2t;
    cudaGetSymbolAddress((void**)&logitsp, g_logits);
    cudaGetSymbolAddress((void**)&logZp, g_logZ);
    cudaGetSymbolAddress((void**)&scorep, g_score);
    cudaGetSymbolAddress((void**)&xbf, g_x_bf);
    cudaGetSymbolAddress((void**)&tmpbf, g_tmp_bf);
    cudaGetSymbolAddress((void**)&qkvbf, g_qkv_bf);
    cudaGetSymbolAddress((void**)&ctxbf, g_ctx_bf);
    cudaGetSymbolAddress((void**)&ffnbf, g_ffn_bf);
    cudaGetSymbolAddress((void**)&wqkvt, g_Wqkv_t);
    cudaGetSymbolAddress((void**)&wot, g_Wo_t);
    cudaGetSymbolAddress((void**)&w1t, g_W1_t);
    cudaGetSymbolAddress((void**)&w2t, g_W2_t);

    cudaFuncSetAttribute(mma_gemm_bf16_kernel,
                         cudaFuncAttributeMaxDynamicSharedMemorySize, GEMMB_SMEM);
    cudaFuncSetAttribute(flash_attn_kernel,
                         cudaFuncAttributeMaxDynamicSharedMemorySize, FLASH_SMEM);

    // weight conversion + transpose, batched across layers via gridDim.z
    wconv_kernel<<<dim3(D3 / 128, DD / 32, LL), dim3(32, 8)>>>(Wqkv, wqkvt, DD, D3);
    wconv_kernel<<<dim3(DD / 128, DD / 32, LL), dim3(32, 8)>>>(Wo, wot, DD, DD);
    wconv_kernel<<<dim3(FF / 128, DD / 32, LL), dim3(32, 8)>>>(W1, w1t, DD, FF);
    wconv_kernel<<<dim3(DD / 128, FF / 32, LL), dim3(32, 8)>>>(W2, w2t, FF, DD);

    embed_ln_kernel<<<TT, 256>>>(ids, emb, pos, lng, lnb, xbf);

    for (int l = 0; l < LL; l++) {
        mma_gemm_bf16_kernel<<<dim3(D3 / 128, TT / 128), 256, GEMMB_SMEM>>>(
            xbf, wqkvt + (size_t)l * D3 * DD, bqkv + (size_t)l * D3,
            (float*)nullptr, qkvbf, TT, D3, DD, 0);
        flash_attn_kernel<<<dim3(SS / 128, BB * HH), 256, FLASH_SMEM>>>(qkvbf, am, ctxbf);
        mma_gemm_bf16_kernel<<<dim3(DD / 128, TT / 128), 256, GEMMB_SMEM>>>(
            ctxbf, wot + (size_t)l * DD * DD, bo + (size_t)l * DD,
            (float*)nullptr, tmpbf, TT, DD, DD, 0);
        ln_residual_kernel<<<TT, 256>>>(xbf, tmpbf, ln1g + (size_t)l * DD, ln1b + (size_t)l * DD, xbf);
        mma_gemm_bf16_kernel<<<dim3(FF / 128, TT / 128), 256, GEMMB_SMEM>>>(
            xbf, w1t + (size_t)l * FF * DD, b1 + (size_t)l * FF,
            (float*)nullptr, ffnbf, TT, FF, DD, 1);
        mma_gemm_bf16_kernel<<<dim3(DD / 128, TT / 128), 256, GEMMB_SMEM>>>(
            ffnbf, w2t + (size_t)l * DD * FF, b2 + (size_t)l * DD,
            (float*)nullptr, tmpbf, TT, DD, FF, 0);
        ln_residual_kernel<<<TT, 256>>>(xbf, tmpbf, ln2g + (size_t)l * DD, ln2b + (size_t)l * DD, xbf);
    }

    cls_kernel<<<TT, 288>>>(xbf, Wcls, bcls, logitsp);
    crf_score_kernel<<<BB, 512>>>(labels, am, logitsp, start_t, end_t, trans, scorep);
    crf_forward_kernel<<<BB, 32>>>(logitsp, am, start_t, end_t, trans, logZp);
    final_kernel<<<1, 32>>>(logZp, scorep, (float*)d_out);
}

// round 16
// speedup vs baseline: 6.2003x; 1.0202x over previous
#include <cuda_runtime.h>
#include <cuda_bf16.h>
#include <math.h>
#include <stdint.h>
#include <stddef.h>

// Problem constants
#define BB 16
#define SS 512
#define DD 768
#define HH 12
#define LL 4
#define FF 3072
#define HDD 64
#define NK 9
#define TT (BB*SS)          // 8192 tokens
#define D3 (3*DD)           // 2304

// ---------------- scratch (static device globals) ----------------
__device__ float g_logits[(size_t)TT*NK];
__device__ float g_logZ[BB];
__device__ float g_score[BB];

__device__ __nv_bfloat16 g_x_bf[(size_t)TT*DD];
__device__ __nv_bfloat16 g_tmp_bf[(size_t)TT*DD];
__device__ __nv_bfloat16 g_qkv_bf[(size_t)TT*D3];
__device__ __nv_bfloat16 g_ctx_bf[(size_t)TT*DD];
__device__ __nv_bfloat16 g_ffn_bf[(size_t)TT*FF];
__device__ __nv_bfloat16 g_Wqkv_t[(size_t)LL*D3*DD];   // [l][N=D3][K=DD]
__device__ __nv_bfloat16 g_Wo_t[(size_t)LL*DD*DD];
__device__ __nv_bfloat16 g_W1_t[(size_t)LL*FF*DD];
__device__ __nv_bfloat16 g_W2_t[(size_t)LL*DD*FF];

// ---------------- helpers ----------------
__device__ __forceinline__ float blk_reduce256(float v, float* sh) {
    int tid = threadIdx.x;
    sh[tid] = v; __syncthreads();
    #pragma unroll
    for (int s = 128; s > 0; s >>= 1) {
        if (tid < s) sh[tid] += sh[tid + s];
        __syncthreads();
    }
    float r = sh[0]; __syncthreads();
    return r;
}

__device__ __forceinline__ void cp_async16(void* smem, const void* gmem) {
    uint32_t s = (uint32_t)__cvta_generic_to_shared(smem);
    asm volatile("cp.async.cg.shared.global [%0], [%1], 16;\n" :: "r"(s), "l"(gmem));
}
#define CP_COMMIT() asm volatile("cp.async.commit_group;\n")
#define CP_WAIT(n)  asm volatile("cp.async.wait_group %0;\n" :: "n"(n))

#define MMA_BF16(acc, a0,a1,a2,a3, b0,b1) \
    asm volatile( \
        "mma.sync.aligned.m16n8k16.row.col.f32.bf16.bf16.f32 " \
        "{%0,%1,%2,%3}, {%4,%5,%6,%7}, {%8,%9}, {%0,%1,%2,%3};" \
        : "+f"(acc[0]), "+f"(acc[1]), "+f"(acc[2]), "+f"(acc[3]) \
        : "r"(a0), "r"(a1), "r"(a2), "r"(a3), "r"(b0), "r"(b1))

#define LDMX4(r0,r1,r2,r3, addr) \
    asm volatile("ldmatrix.sync.aligned.m8n8.x4.shared.b16 {%0,%1,%2,%3}, [%4];" \
        : "=r"(r0), "=r"(r1), "=r"(r2), "=r"(r3) : "r"(addr))

__device__ __forceinline__ float fast_tanh(float x) {
    float y;
    asm("tanh.approx.f32 %0, %1;" : "=f"(y) : "f"(x));
    return y;
}

// ---------------- weight convert + transpose: fp32 [K][N] -> bf16 [N][K] ----------------
__global__ void wconv_kernel(const float* __restrict__ W, __nv_bfloat16* __restrict__ Wt,
                             int K, int N) {
    W  += (size_t)blockIdx.z * K * N;
    Wt += (size_t)blockIdx.z * N * K;
    __shared__ float tile[32][133];
    int n0 = blockIdx.x * 128, k0 = blockIdx.y * 32;
    int tx = threadIdx.x, ty = threadIdx.y;
    #pragma unroll
    for (int j = ty; j < 32; j += 8) {
        const float* src = W + (size_t)(k0 + j) * N + n0;
        #pragma unroll
        for (int c = 0; c < 4; c++)
            tile[j][tx + 32 * c] = src[tx + 32 * c];
    }
    __syncthreads();
    #pragma unroll
    for (int jn = ty; jn < 128; jn += 8)
        Wt[(size_t)(n0 + jn) * K + k0 + tx] = __float2bfloat16(tile[tx][jn]);
}

// ---------------- embedding + LN (bf16 out) ----------------
__global__ void embed_ln_kernel(const int* __restrict__ ids, const float* __restrict__ emb,
                                const float* __restrict__ pos, const float* __restrict__ g,
                                const float* __restrict__ bta,
                                __nv_bfloat16* __restrict__ outb) {
    __shared__ float sh[256];
    int t = blockIdx.x, s = t % SS;
    int id = ids[t];
    const float* e = emb + (size_t)id * DD;
    const float* p = pos + (size_t)s * DD;
    float v[3]; float ls = 0.f, lq = 0.f;
    #pragma unroll
    for (int i = 0; i < 3; i++) {
        int d = threadIdx.x + i * 256;
        float w = e[d] + p[d];
        v[i] = w; ls += w; lq += w * w;
    }
    float sum = blk_reduce256(ls, sh);
    float sq  = blk_reduce256(lq, sh);
    float mean = sum * (1.0f / DD);
    float var  = sq * (1.0f / DD) - mean * mean;
    float rstd = rsqrtf(var + 1e-12f);
    __nv_bfloat16* ob = outb + (size_t)t * DD;
    #pragma unroll
    for (int i = 0; i < 3; i++) {
        int d = threadIdx.x + i * 256;
        float r = (v[i] - mean) * rstd * g[d] + bta[d];
        ob[d] = __float2bfloat16(r);
    }
}

// out = LN(a + r), all bf16 (fp32 internal math)
__global__ void ln_residual_kernel(const __nv_bfloat16* __restrict__ a,
                                   const __nv_bfloat16* __restrict__ r,
                                   const float* __restrict__ g, const float* __restrict__ bta,
                                   __nv_bfloat16* __restrict__ outb) {
    __shared__ float sh[256];
    int t = blockIdx.x;
    const __nv_bfloat16* ap = a + (size_t)t * DD;
    const __nv_bfloat16* rp = r + (size_t)t * DD;
    float v[3]; float ls = 0.f, lq = 0.f;
    #pragma unroll
    for (int i = 0; i < 3; i++) {
        int d = threadIdx.x + i * 256;
        float w = __bfloat162float(ap[d]) + __bfloat162float(rp[d]);
        v[i] = w; ls += w; lq += w * w;
    }
    float sum = blk_reduce256(ls, sh);
    float sq  = blk_reduce256(lq, sh);
    float mean = sum * (1.0f / DD);
    float var  = sq * (1.0f / DD) - mean * mean;
    float rstd = rsqrtf(var + 1e-12f);
    __nv_bfloat16* ob = outb + (size_t)t * DD;
    #pragma unroll
    for (int i = 0; i < 3; i++) {
        int d = threadIdx.x + i * 256;
        float rr = (v[i] - mean) * rstd * g[d] + bta[d];
        ob[d] = __float2bfloat16(rr);
    }
}

// ---------------- BF16 tensor-core GEMM: ldmatrix frags + 3-stage cp.async ----------------
// Single __syncthreads per k-tile: loads issued AFTER the barrier (all warps proven
// past compute kt-1, whose buffer (kt+2)%3 the loads overwrite). CP_WAIT(1) before the
// barrier leaves only buffer kt+1's group pending => buffer kt complete.
#define GEMM_STAGES 3
#define GEMMB_SMEM (GEMM_STAGES * 9216 * 4)
__global__ __launch_bounds__(256)
void mma_gemm_bf16_kernel(const __nv_bfloat16* __restrict__ A,
                          const __nv_bfloat16* __restrict__ Bt,
                          const float* __restrict__ bias,
                          float* __restrict__ Cf, __nv_bfloat16* __restrict__ Cb,
                          int M, int N, int Kd, int act) {
    extern __shared__ uint32_t dw[];

    const int tid  = threadIdx.x;
    const int warp = tid >> 5, lane = tid & 31;
    const int warpM = warp >> 2, warpN = warp & 3;
    const int g = lane >> 2, tg = lane & 3;
    const int rowBase = blockIdx.y * 128;
    const int colBase = blockIdx.x * 128;

    const int sub = lane >> 3, rr = lane & 7;
    const int rowA  = warpM * 64 + (sub & 1) * 8 + rr;
    const int koffA = (sub >> 1) * 8;
    const int rowB  = warpN * 32 + ((sub >> 1) & 1) * 8 + rr;
    const int koffB = (sub & 1) * 8;
    const uint32_t smem0 = (uint32_t)__cvta_generic_to_shared(dw);

    float acc[4][4][4];
    #pragma unroll
    for (int im = 0; im < 4; im++)
        #pragma unroll
        for (int in = 0; in < 4; in++)
            #pragma unroll
            for (int r = 0; r < 4; r++) acc[im][in][r] = 0.f;

    auto load_stage = [&](int k0, int s) {
        uint32_t* as = dw + s * 9216;
        uint32_t* bs = as + 4608;
        #pragma unroll
        for (int i = 0; i < 4; i++) {
            int idx = i * 256 + tid;
            int r = idx >> 3;
            int cw = (idx & 7) * 4;
            int ch = (idx & 7) * 8;
            cp_async16(as + r * 36 + cw, A  + (size_t)(rowBase + r) * Kd + k0 + ch);
            cp_async16(bs + r * 36 + cw, Bt + (size_t)(colBase + r) * Kd + k0 + ch);
        }
    };

    const int nK = Kd >> 6;
    load_stage(0, 0); CP_COMMIT();
    load_stage(64, 1); CP_COMMIT();
    int buf = 0;
    for (int kt = 0; kt < nK; kt++) {
        CP_WAIT(1);
        __syncthreads();
        if (kt + 2 < nK) load_stage((kt + 2) << 6, (buf + 2) % 3);
        CP_COMMIT();

        const uint32_t aBase = smem0 + (uint32_t)(buf * 9216) * 4;
        const uint32_t bBase = aBase + 4608 * 4;
        #pragma unroll
        for (int ks = 0; ks < 4; ks++) {
            uint32_t afr[4][4];
            #pragma unroll
            for (int im = 0; im < 4; im++) {
                uint32_t ad = aBase + (uint32_t)(((rowA + im * 16) * 72 + ks * 16 + koffA) * 2);
                LDMX4(afr[im][0], afr[im][1], afr[im][2], afr[im][3], ad);
            }
            uint32_t bq[2][4];
            #pragma unroll
            for (int inp = 0; inp < 2; inp++) {
                uint32_t bd = bBase + (uint32_t)(((rowB + inp * 16) * 72 + ks * 16 + koffB) * 2);
                LDMX4(bq[inp][0], bq[inp][1], bq[inp][2], bq[inp][3], bd);
            }
            #pragma unroll
            for (int im = 0; im < 4; im++)
                #pragma unroll
                for (int in = 0; in < 4; in++) {
                    if (in & 1)
                        MMA_BF16(acc[im][in], afr[im][0], afr[im][1], afr[im][2], afr[im][3],
                                 bq[in >> 1][2], bq[in >> 1][3]);
                    else
                        MMA_BF16(acc[im][in], afr[im][0], afr[im][1], afr[im][2], afr[im][3],
                                 bq[in >> 1][0], bq[in >> 1][1]);
                }
        }
        buf = (buf + 1) % 3;
    }

    #pragma unroll
    for (int im = 0; im < 4; im++) {
        int row0 = rowBase + warpM * 64 + im * 16 + g;
        #pragma unroll
        for (int in = 0; in < 4; in++) {
            int col0 = colBase + warpN * 32 + in * 8 + tg * 2;
            float b0 = bias[col0], b1 = bias[col0 + 1];
            float v0 = acc[im][in][0] + b0;
            float v1 = acc[im][in][1] + b1;
            float v2 = acc[im][in][2] + b0;
            float v3 = acc[im][in][3] + b1;
            if (act) {
                float u, cc;
                u = v0; cc = 0.7978845608028654f * (u + 0.044715f * u * u * u); v0 = 0.5f * u * (1.0f + fast_tanh(cc));
                u = v1; cc = 0.7978845608028654f * (u + 0.044715f * u * u * u); v1 = 0.5f * u * (1.0f + fast_tanh(cc));
                u = v2; cc = 0.7978845608028654f * (u + 0.044715f * u * u * u); v2 = 0.5f * u * (1.0f + fast_tanh(cc));
                u = v3; cc = 0.7978845608028654f * (u + 0.044715f * u * u * u); v3 = 0.5f * u * (1.0f + fast_tanh(cc));
            }
            if (Cf) {
                Cf[(size_t)row0 * N + col0]           = v0;
                Cf[(size_t)row0 * N + col0 + 1]       = v1;
                Cf[(size_t)(row0 + 8) * N + col0]     = v2;
                Cf[(size_t)(row0 + 8) * N + col0 + 1] = v3;
            }
            if (Cb) {
                *(__nv_bfloat162*)(Cb + (size_t)row0 * N + col0)       = __floats2bfloat162_rn(v0, v1);
                *(__nv_bfloat162*)(Cb + (size_t)(row0 + 8) * N + col0) = __floats2bfloat162_rn(v2, v3);
            }
        }
    }
}

// ---------------- fused flash attention: 128 q-rows per block, 8 warps ----------------
#define FLASH_SMEM (14336 * 4)
__global__ __launch_bounds__(256)
void flash_attn_kernel(const __nv_bfloat16* __restrict__ qkvb, const int* __restrict__ amask,
                       __nv_bfloat16* __restrict__ ctxb) {
    extern __shared__ uint32_t dyn[];
    uint32_t* Qs = dyn;
    float* bias_s = (float*)(dyn + 13824);

    const int bh = blockIdx.y;
    const int b = bh / HH, h = bh % HH;
    const int q0 = blockIdx.x * 128;
    const int tid = threadIdx.x;
    const int warp = tid >> 5, lane = tid & 31;
    const int g = lane >> 2, tg = lane & 3;
    const int sub = lane >> 3, rr8 = lane & 7;

    const __nv_bfloat16* Qg = qkvb + (size_t)(b * SS + q0) * D3 + h * HDD;
    const __nv_bfloat16* Kg = qkvb + (size_t)(b * SS) * D3 + DD + h * HDD;
    const __nv_bfloat16* Vg = qkvb + (size_t)(b * SS) * D3 + 2 * DD + h * HDD;

    const uint32_t dbase = (uint32_t)__cvta_generic_to_shared(dyn);
    const uint32_t qbase = dbase;
    const uint32_t kbase0 = dbase + 4608 * 4;
    const uint32_t vbase0 = dbase + 9216 * 4;

    const int rowQa  = warp * 16 + (sub & 1) * 8 + rr8;
    const int koffQa = (sub >> 1) * 8;
    const int rowKb  = ((sub >> 1) & 1) * 8 + rr8;
    const int koffKb = (sub & 1) * 8;

    #pragma unroll
    for (int i = 0; i < 2; i++) {
        int c = i * 256 + tid;
        bias_s[c] = (1.0f - (float)amask[b * SS + c]) * -1e9f;
    }
    #pragma unroll
    for (int i = 0; i < 4; i++) {
        int idx = i * 256 + tid;
        int row = idx >> 3, ch = idx & 7;
        cp_async16(Qs + row * 36 + ch * 4, Qg + (size_t)row * D3 + ch * 8);
    }
    #pragma unroll
    for (int i = 0; i < 2; i++) {
        int idx = i * 256 + tid;
        int row = idx >> 3, ch = idx & 7;
        cp_async16(dyn + 4608 + row * 36 + ch * 4, Kg + (size_t)row * D3 + ch * 8);
        cp_async16(dyn + 9216 + row * 36 + ch * 4, Vg + (size_t)row * D3 + ch * 8);
    }
    CP_COMMIT();

    float m0 = -INFINITY, m1 = -INFINITY, l0 = 0.f, l1 = 0.f;
    float o[8][4];
    #pragma unroll
    for (int j = 0; j < 8; j++)
        #pragma unroll
        for (int r = 0; r < 4; r++) o[j][r] = 0.f;

    const int mat = lane >> 3, r8 = lane & 7;
    int buf = 0;
    for (int kt = 0; kt < 8; kt++) {
        if (kt < 7) {
            #pragma unroll
            for (int i = 0; i < 2; i++) {
                int idx = i * 256 + tid;
                int row = idx >> 3, ch = idx & 7;
                int grow = (kt + 1) * 64 + row;
                cp_async16(dyn + 4608 + (buf ^ 1) * 2304 + row * 36 + ch * 4, Kg + (size_t)grow * D3 + ch * 8);
                cp_async16(dyn + 9216 + (buf ^ 1) * 2304 + row * 36 + ch * 4, Vg + (size_t)grow * D3 + ch * 8);
            }
            CP_COMMIT();
            CP_WAIT(1);
        } else {
            CP_WAIT(0);
        }
        __syncthreads();

        float s[8][4];
        #pragma unroll
        for (int j = 0; j < 8; j++)
            #pragma unroll
            for (int r = 0; r < 4; r++) s[j][r] = 0.f;
        const uint32_t kbase = kbase0 + (uint32_t)(buf * 2304 * 4);
        #pragma unroll
        for (int ks = 0; ks < 4; ks++) {
            uint32_t a0, a1, a2, a3;
            uint32_t qa = qbase + (uint32_t)((rowQa * 72 + ks * 16 + koffQa) * 2);
            LDMX4(a0, a1, a2, a3, qa);
            #pragma unroll
            for (int jp = 0; jp < 4; jp++) {
                uint32_t b0, b1, b2, b3;
                uint32_t kd = kbase + (uint32_t)(((rowKb + jp * 16) * 72 + ks * 16 + koffKb) * 2);
                LDMX4(b0, b1, b2, b3, kd);
                MMA_BF16(s[2 * jp],     a0, a1, a2, a3, b0, b1);
                MMA_BF16(s[2 * jp + 1], a0, a1, a2, a3, b2, b3);
            }
        }

        float mx0 = -INFINITY, mx1 = -INFINITY;
        #pragma unroll
        for (int j = 0; j < 8; j++) {
            float bi0 = bias_s[kt * 64 + j * 8 + 2 * tg];
            float bi1 = bias_s[kt * 64 + j * 8 + 2 * tg + 1];
            s[j][0] = s[j][0] * 0.125f + bi0;
            s[j][1] = s[j][1] * 0.125f + bi1;
            s[j][2] = s[j][2] * 0.125f + bi0;
            s[j][3] = s[j][3] * 0.125f + bi1;
            mx0 = fmaxf(mx0, fmaxf(s[j][0], s[j][1]));
            mx1 = fmaxf(mx1, fmaxf(s[j][2], s[j][3]));
        }
        mx0 = fmaxf(mx0, __shfl_xor_sync(0xffffffffu, mx0, 1));
        mx0 = fmaxf(mx0, __shfl_xor_sync(0xffffffffu, mx0, 2));
        mx1 = fmaxf(mx1, __shfl_xor_sync(0xffffffffu, mx1, 1));
        mx1 = fmaxf(mx1, __shfl_xor_sync(0xffffffffu, mx1, 2));

        float mn0 = fmaxf(m0, mx0), mn1 = fmaxf(m1, mx1);
        float al0 = __expf(m0 - mn0), al1 = __expf(m1 - mn1);
        float sum0 = 0.f, sum1 = 0.f;
        uint32_t pl[8], ph[8];
        #pragma unroll
        for (int j = 0; j < 8; j++) {
            float p0 = __expf(s[j][0] - mn0), p1 = __expf(s[j][1] - mn0);
            float p2 = __expf(s[j][2] - mn1), p3 = __expf(s[j][3] - mn1);
            sum0 += p0 + p1; sum1 += p2 + p3;
            __nv_bfloat162 t0 = __floats2bfloat162_rn(p0, p1);
            __nv_bfloat162 t1 = __floats2bfloat162_rn(p2, p3);
            pl[j] = *(uint32_t*)&t0;
            ph[j] = *(uint32_t*)&t1;
        }
        sum0 += __shfl_xor_sync(0xffffffffu, sum0, 1);
        sum0 += __shfl_xor_sync(0xffffffffu, sum0, 2);
        sum1 += __shfl_xor_sync(0xffffffffu, sum1, 1);
        sum1 += __shfl_xor_sync(0xffffffffu, sum1, 2);
        l0 = l0 * al0 + sum0; l1 = l1 * al1 + sum1;
        m0 = mn0; m1 = mn1;
        #pragma unroll
        for (int j = 0; j < 8; j++) {
            o[j][0] *= al0; o[j][1] *= al0; o[j][2] *= al1; o[j][3] *= al1;
        }

        uint32_t vbase = vbase0 + (uint32_t)(buf * 2304 * 4);
        #pragma unroll
        for (int ks = 0; ks < 4; ks++) {
            uint32_t a0 = pl[2 * ks], a1 = ph[2 * ks], a2 = pl[2 * ks + 1], a3 = ph[2 * ks + 1];
            #pragma unroll
            for (int jj = 0; jj < 4; jj++) {
                int rowv = ks * 16 + (mat & 1) * 8 + r8;
                int colh = jj * 16 + (mat >> 1) * 8;
                uint32_t addr = vbase + (uint32_t)(rowv * 144 + colh * 2);
                uint32_t r0, r1, r2, r3;
                asm volatile("ldmatrix.sync.aligned.m8n8.x4.trans.shared.b16 {%0,%1,%2,%3}, [%4];"
                             : "=r"(r0), "=r"(r1), "=r"(r2), "=r"(r3) : "r"(addr));
                MMA_BF16(o[2 * jj],     a0, a1, a2, a3, r0, r1);
                MMA_BF16(o[2 * jj + 1], a0, a1, a2, a3, r2, r3);
            }
        }
        __syncthreads();
        buf ^= 1;
    }

    float inv0 = 1.f / l0, inv1 = 1.f / l1;
    int rowg = b * SS + q0 + warp * 16 + g;
    __nv_bfloat16* dst0 = ctxb + (size_t)rowg * DD + h * HDD;
    __nv_bfloat16* dst1 = dst0 + (size_t)8 * DD;
    #pragma unroll
    for (int j = 0; j < 8; j++) {
        *(__nv_bfloat162*)(dst0 + j * 8 + 2 * tg) = __floats2bfloat162_rn(o[j][0] * inv0, o[j][1] * inv0);
        *(__nv_bfloat162*)(dst1 + j * 8 + 2 * tg) = __floats2bfloat162_rn(o[j][2] * inv1, o[j][3] * inv1);
    }
}

// ---------------- classifier (bf16 activations) ----------------
__global__ __launch_bounds__(288)
void cls_kernel(const __nv_bfloat16* __restrict__ x, const float* __restrict__ W,
                const float* __restrict__ bias, float* __restrict__ logits) {
    int t = blockIdx.x;
    int w = threadIdx.x >> 5;
    int lane = threadIdx.x & 31;
    const __nv_bfloat16* xp = x + (size_t)t * DD;
    float s = 0.f;
    for (int d = lane; d < DD; d += 32) s += __bfloat162float(xp[d]) * W[(size_t)d * NK + w];
    #pragma unroll
    for (int o = 16; o > 0; o >>= 1) s += __shfl_down_sync(0xffffffffu, s, o);
    if (lane == 0) logits[(size_t)t * NK + w] = s + bias[w];
}

// ---------------- CRF gold-path score ----------------
__global__ __launch_bounds__(512)
void crf_score_kernel(const int* __restrict__ labels, const int* __restrict__ amask,
                      const float* __restrict__ logits, const float* __restrict__ start_t,
                      const float* __restrict__ end_t, const float* __restrict__ trans,
                      float* __restrict__ score) {
    __shared__ float sf[512];
    __shared__ int si[512];
    int b = blockIdx.x;
    int t = threadIdx.x;
    const int* lab = labels + b * SS;
    const int* m = amask + b * SS;
    const float* lg = logits + (size_t)b * SS * NK;
    float em = lg[t * NK + lab[t]];
    float contrib = (t == 0) ? em : (float)m[t] * (trans[lab[t - 1] * NK + lab[t]] + em);
    sf[t] = contrib; si[t] = m[t];
    __syncthreads();
    #pragma unroll
    for (int s = 256; s > 0; s >>= 1) {
        if (t < s) { sf[t] += sf[t + s]; si[t] += si[t + s]; }
        __syncthreads();
    }
    if (t == 0) {
        int last = si[0] - 1;
        score[b] = sf[0] + start_t[lab[0]] + end_t[lab[last]];
    }
}

// ---------------- CRF forward (logZ): serial warp version (proven) ----------------
__global__ __launch_bounds__(32)
void crf_forward_kernel(const float* __restrict__ logits, const int* __restrict__ amask,
                        const float* __restrict__ start_t, const float* __restrict__ end_t,
                        const float* __restrict__ trans, float* __restrict__ logZ) {
    __shared__ float lg[SS * NK];
    __shared__ float tr[NK * NK];
    __shared__ float alpha[2][NK];
    int b = blockIdx.x;
    int tid = threadIdx.x;
    const float* src = logits + (size_t)b * SS * NK;
    for (int i = tid; i < SS * NK; i += 32) lg[i] = src[i];
    for (int i = tid; i < NK * NK; i += 32) tr[i] = trans[i];
    if (tid < NK) alpha[0][tid] = start_t[tid] + lg[tid];
    __syncwarp();
    int cur = 0;
    for (int t = 1; t < SS; t++) {
        if (tid < NK) {
            int j = tid;
            float mx = -INFINITY;
            #pragma unroll
            for (int i = 0; i < NK; i++) mx = fmaxf(mx, alpha[cur][i] + tr[i * NK + j]);
            float s = 0.f;
            #pragma unroll
            for (int i = 0; i < NK; i++) s += __expf(alpha[cur][i] + tr[i * NK + j] - mx);
            float cand = mx + __logf(s) + lg[t * NK + j];
            alpha[cur ^ 1][j] = (amask[b * SS + t] > 0) ? cand : alpha[cur][j];
        }
        __syncwarp();
        cur ^= 1;
    }
    if (tid == 0) {
        float mx = -INFINITY;
        #pragma unroll
        for (int i = 0; i < NK; i++) mx = fmaxf(mx, alpha[cur][i] + end_t[i]);
        float s = 0.f;
        #pragma unroll
        for (int i = 0; i < NK; i++) s += __expf(alpha[cur][i] + end_t[i] - mx);
        logZ[b] = mx + __logf(s);
    }
}

// ---------------- final reduction ----------------
__global__ __launch_bounds__(32)
void final_kernel(const float* __restrict__ logZ, const float* __restrict__ score,
                  float* __restrict__ out) {
    int tid = threadIdx.x;
    float v = (tid < BB) ? (logZ[tid] - score[tid]) : 0.f;
    #pragma unroll
    for (int o = 16; o > 0; o >>= 1) v += __shfl_down_sync(0xffffffffu, v, o);
    if (tid == 0) out[0] = v;
}

// ---------------- launch ----------------
extern "C" void kernel_launch(void* const* d_in, const int* in_sizes, int n_in,
                              void* d_out, int out_size) {
    const int*   ids     = (const int*)d_in[0];
    const int*   am      = (const int*)d_in[1];
    const int*   labels  = (const int*)d_in[2];
    const float* emb     = (const float*)d_in[3];
    const float* pos     = (const float*)d_in[4];
    const float* lng     = (const float*)d_in[5];
    const float* lnb     = (const float*)d_in[6];
    const float* Wqkv    = (const float*)d_in[7];
    const float* bqkv    = (const float*)d_in[8];
    const float* Wo      = (const float*)d_in[9];
    const float* bo      = (const float*)d_in[10];
    const float* ln1g    = (const float*)d_in[11];
    const float* ln1b    = (const float*)d_in[12];
    const float* W1      = (const float*)d_in[13];
    const float* b1      = (const float*)d_in[14];
    const float* W2      = (const float*)d_in[15];
    const float* b2      = (const float*)d_in[16];
    const float* ln2g    = (const float*)d_in[17];
    const float* ln2b    = (const float*)d_in[18];
    const float* Wcls    = (const float*)d_in[19];
    const float* bcls    = (const float*)d_in[20];
    const float* start_t = (const float*)d_in[21];
    const float* end_t   = (const float*)d_in[22];
    const float* trans   = (const float*)d_in[23];

    float *logitsp, *logZp, *scorep;
    __nv_bfloat16 *xbf, *tmpbf, *qkvbf, *ctxbf, *ffnbf, *wqkvt, *wot, *w1t, *w2t;
    cudaGetSymbolAddress((void**)&logitsp, g_logits);
    cudaGetSymbolAddress((void**)&logZp, g_logZ);
    cudaGetSymbolAddress((void**)&scorep, g_score);
    cudaGetSymbolAddress((void**)&xbf, g_x_bf);
    cudaGetSymbolAddress((void**)&tmpbf, g_tmp_bf);
    cudaGetSymbolAddress((void**)&qkvbf, g_qkv_bf);
    cudaGetSymbolAddress((void**)&ctxbf, g_ctx_bf);
    cudaGetSymbolAddress((void**)&ffnbf, g_ffn_bf);
    cudaGetSymbolAddress((void**)&wqkvt, g_Wqkv_t);
    cudaGetSymbolAddress((void**)&wot, g_Wo_t);
    cudaGetSymbolAddress((void**)&w1t, g_W1_t);
    cudaGetSymbolAddress((void**)&w2t, g_W2_t);

    cudaFuncSetAttribute(mma_gemm_bf16_kernel,
                         cudaFuncAttributeMaxDynamicSharedMemorySize, GEMMB_SMEM);
    cudaFuncSetAttribute(flash_attn_kernel,
                         cudaFuncAttributeMaxDynamicSharedMemorySize, FLASH_SMEM);

    // weight conversion + transpose, batched across layers via gridDim.z
    wconv_kernel<<<dim3(D3 / 128, DD / 32, LL), dim3(32, 8)>>>(Wqkv, wqkvt, DD, D3);
    wconv_kernel<<<dim3(DD / 128, DD / 32, LL), dim3(32, 8)>>>(Wo, wot, DD, DD);
    wconv_kernel<<<dim3(FF / 128, DD / 32, LL), dim3(32, 8)>>>(W1, w1t, DD, FF);
    wconv_kernel<<<dim3(DD / 128, FF / 32, LL), dim3(32, 8)>>>(W2, w2t, FF, DD);

    embed_ln_kernel<<<TT, 256>>>(ids, emb, pos, lng, lnb, xbf);

    for (int l = 0; l < LL; l++) {
        mma_gemm_bf16_kernel<<<dim3(D3 / 128, TT / 128), 256, GEMMB_SMEM>>>(
            xbf, wqkvt + (size_t)l * D3 * DD, bqkv + (size_t)l * D3,
            (float*)nullptr, qkvbf, TT, D3, DD, 0);
        flash_attn_kernel<<<dim3(SS / 128, BB * HH), 256, FLASH_SMEM>>>(qkvbf, am, ctxbf);
        mma_gemm_bf16_kernel<<<dim3(DD / 128, TT / 128), 256, GEMMB_SMEM>>>(
            ctxbf, wot + (size_t)l * DD * DD, bo + (size_t)l * DD,
            (float*)nullptr, tmpbf, TT, DD, DD, 0);
        ln_residual_kernel<<<TT, 256>>>(xbf, tmpbf, ln1g + (size_t)l * DD, ln1b + (size_t)l * DD, xbf);
        mma_gemm_bf16_kernel<<<dim3(FF / 128, TT / 128), 256, GEMMB_SMEM>>>(
            xbf, w1t + (size_t)l * FF * DD, b1 + (size_t)l * FF,
            (float*)nullptr, ffnbf, TT, FF, DD, 1);
        mma_gemm_bf16_kernel<<<dim3(DD / 128, TT / 128), 256, GEMMB_SMEM>>>(
            ffnbf, w2t + (size_t)l * DD * FF, b2 + (size_t)l * DD,
            (float*)nullptr, tmpbf, TT, DD, FF, 0);
        ln_residual_kernel<<<TT, 256>>>(xbf, tmpbf, ln2g + (size_t)l * DD, ln2b + (size_t)l * DD, xbf);
    }

    cls_kernel<<<TT, 288>>>(xbf, Wcls, bcls, logitsp);
    crf_score_kernel<<<BB, 512>>>(labels, am, logitsp, start_t, end_t, trans, scorep);
    crf_forward_kernel<<<BB, 32>>>(logitsp, am, start_t, end_t, trans, logZp);
    final_kernel<<<1, 32>>>(logZp, scorep, (float*)d_out);
}